// round 4
// baseline (speedup 1.0000x reference)
#include <cuda_runtime.h>
#include <math.h>

#define Bc 4
#define Sc 1024
#define Dc 768
#define Nc 12
#define Hc 64
#define Rc 2048
#define SCALE 0.125f
#define INFV 1000000.0f
#define EPSV 1e-9f

// ---------------- tf32 helpers ----------------
__device__ __forceinline__ unsigned f2tf(float x) {
    unsigned u; asm("cvt.rna.tf32.f32 %0, %1;" : "=r"(u) : "f"(x)); return u;
}
__device__ __forceinline__ float4 cvt4(float4 v) {
    v.x = __uint_as_float(f2tf(v.x)); v.y = __uint_as_float(f2tf(v.y));
    v.z = __uint_as_float(f2tf(v.z)); v.w = __uint_as_float(f2tf(v.w));
    return v;
}
// m16n8k8 tf32 mma: A row-major frag a0..a3, B col-frag b0,b1, C +=.
__device__ __forceinline__ void mma8(float4& c, unsigned a0, unsigned a1,
                                     unsigned a2, unsigned a3,
                                     unsigned b0, unsigned b1) {
    asm volatile(
        "mma.sync.aligned.m16n8k8.row.col.f32.tf32.tf32.f32 "
        "{%0,%1,%2,%3}, {%4,%5,%6,%7}, {%8,%9}, {%0,%1,%2,%3};"
        : "+f"(c.x), "+f"(c.y), "+f"(c.z), "+f"(c.w)
        : "r"(a0), "r"(a1), "r"(a2), "r"(a3), "r"(b0), "r"(b1));
}

// ---------------- scratch ----------------
__device__ float g_qh[Bc*Nc*Sc*Hc];   // tf32-rounded
__device__ float g_kh[Bc*Nc*Sc*Hc];   // tf32-rounded
__device__ float g_vh[Bc*Nc*Sc*Hc];   // tf32-rounded
__device__ float g_rh[Nc*Rc*Hc];      // tf32-rounded
__device__ float g_tt[Bc*Nc*Sc*2];
__device__ float g_av[Bc*Nc*Sc*Hc];   // tf32-rounded
__device__ float g_x [Bc*Sc*Dc];

// ============ projection GEMM: out = cvt_tf32(A@W * scale + bias), scattered ============
// Block: 256 thr, tile 128(M) x 64(N), KC=32. Warp tile 32x32.
__global__ __launch_bounds__(256)
void gemm_proj_t(const float* __restrict__ A, const float* __restrict__ W,
                 const float* __restrict__ bias, float scale, int sshift,
                 float* __restrict__ out) {
    __shared__ float As[128*36];
    __shared__ float Ws[32*72];
    int tid = threadIdx.x, w = tid >> 5, lane = tid & 31;
    int g = lane >> 2, t = lane & 3;
    int wm = w & 3, wn = w >> 2;
    int m0 = blockIdx.y * 128, n0 = blockIdx.x * 64;
    int Srows = 1 << sshift;

    float4 c[2][4];
    #pragma unroll
    for (int mt = 0; mt < 2; mt++)
        #pragma unroll
        for (int nt = 0; nt < 4; nt++) c[mt][nt] = make_float4(0.f,0.f,0.f,0.f);

    for (int k0 = 0; k0 < Dc; k0 += 32) {
        #pragma unroll
        for (int p = 0; p < 4; p++) {
            int idx = tid + p*256;
            int m = idx >> 3, kq = (idx & 7) * 4;
            float4 v = *(const float4*)(A + (size_t)(m0+m)*Dc + k0 + kq);
            *(float4*)(As + m*36 + kq) = cvt4(v);
        }
        #pragma unroll
        for (int p = 0; p < 2; p++) {
            int idx = tid + p*256;
            int k = idx >> 4, nq = (idx & 15) * 4;
            float4 v = *(const float4*)(W + (size_t)(k0+k)*Dc + n0 + nq);
            *(float4*)(Ws + k*72 + nq) = cvt4(v);
        }
        __syncthreads();
        #pragma unroll
        for (int ks = 0; ks < 4; ks++) {
            int kb = ks * 8;
            unsigned a[2][4];
            #pragma unroll
            for (int mt = 0; mt < 2; mt++) {
                int bm = wm*32 + mt*16;
                a[mt][0] = __float_as_uint(As[(bm+g  )*36 + kb+t  ]);
                a[mt][1] = __float_as_uint(As[(bm+g+8)*36 + kb+t  ]);
                a[mt][2] = __float_as_uint(As[(bm+g  )*36 + kb+t+4]);
                a[mt][3] = __float_as_uint(As[(bm+g+8)*36 + kb+t+4]);
            }
            unsigned bb[4][2];
            #pragma unroll
            for (int nt = 0; nt < 4; nt++) {
                int bn = wn*32 + nt*8 + g;
                bb[nt][0] = __float_as_uint(Ws[(kb+t  )*72 + bn]);
                bb[nt][1] = __float_as_uint(Ws[(kb+t+4)*72 + bn]);
            }
            #pragma unroll
            for (int mt = 0; mt < 2; mt++)
                #pragma unroll
                for (int nt = 0; nt < 4; nt++)
                    mma8(c[mt][nt], a[mt][0],a[mt][1],a[mt][2],a[mt][3],
                         bb[nt][0], bb[nt][1]);
        }
        __syncthreads();
    }
    #pragma unroll
    for (int mt = 0; mt < 2; mt++) {
        #pragma unroll
        for (int nt = 0; nt < 4; nt++) {
            int col = n0 + wn*32 + nt*8 + 2*t;
            float b0 = bias ? __ldg(bias + col) : 0.f;
            float b1 = bias ? __ldg(bias + col + 1) : 0.f;
            int nn = col >> 6, h = col & 63;
            #pragma unroll
            for (int r = 0; r < 2; r++) {
                int row = m0 + wm*32 + mt*16 + g + r*8;
                int bbx = row >> sshift, ss = row & (Srows - 1);
                float v0 = (r ? c[mt][nt].z : c[mt][nt].x) * scale + b0;
                float v1 = (r ? c[mt][nt].w : c[mt][nt].y) * scale + b1;
                float2 o = make_float2(__uint_as_float(f2tf(v0)),
                                       __uint_as_float(f2tf(v1)));
                *(float2*)(out + (((size_t)bbx*Nc + nn)*Srows + ss)*Hc + h) = o;
            }
        }
    }
}

// ============ output GEMM + residual: g_x = g_av@Wo + bo + query (fp32 out) ============
__global__ __launch_bounds__(256)
void gemm_out_t(const float* __restrict__ Wo, const float* __restrict__ bo,
                const float* __restrict__ query) {
    __shared__ float As[128*36];
    __shared__ float Ws[32*72];
    int tid = threadIdx.x, w = tid >> 5, lane = tid & 31;
    int g = lane >> 2, t = lane & 3;
    int wm = w & 3, wn = w >> 2;
    int m0 = blockIdx.y * 128, n0 = blockIdx.x * 64;

    float4 c[2][4];
    #pragma unroll
    for (int mt = 0; mt < 2; mt++)
        #pragma unroll
        for (int nt = 0; nt < 4; nt++) c[mt][nt] = make_float4(0.f,0.f,0.f,0.f);

    for (int k0 = 0; k0 < Dc; k0 += 32) {
        #pragma unroll
        for (int p = 0; p < 4; p++) {
            int idx = tid + p*256;
            int m = idx >> 3, kq = (idx & 7) * 4;
            int row = m0 + m, colk = k0 + kq;
            float4 v = *(const float4*)(g_av +
                (((size_t)(row >> 10)*Nc + (colk >> 6))*Sc + (row & 1023))*Hc + (colk & 63));
            *(float4*)(As + m*36 + kq) = v;   // already tf32-rounded
        }
        #pragma unroll
        for (int p = 0; p < 2; p++) {
            int idx = tid + p*256;
            int k = idx >> 4, nq = (idx & 15) * 4;
            float4 v = *(const float4*)(Wo + (size_t)(k0+k)*Dc + n0 + nq);
            *(float4*)(Ws + k*72 + nq) = cvt4(v);
        }
        __syncthreads();
        #pragma unroll
        for (int ks = 0; ks < 4; ks++) {
            int kb = ks * 8;
            unsigned a[2][4];
            #pragma unroll
            for (int mt = 0; mt < 2; mt++) {
                int bm = wm*32 + mt*16;
                a[mt][0] = __float_as_uint(As[(bm+g  )*36 + kb+t  ]);
                a[mt][1] = __float_as_uint(As[(bm+g+8)*36 + kb+t  ]);
                a[mt][2] = __float_as_uint(As[(bm+g  )*36 + kb+t+4]);
                a[mt][3] = __float_as_uint(As[(bm+g+8)*36 + kb+t+4]);
            }
            unsigned bb[4][2];
            #pragma unroll
            for (int nt = 0; nt < 4; nt++) {
                int bn = wn*32 + nt*8 + g;
                bb[nt][0] = __float_as_uint(Ws[(kb+t  )*72 + bn]);
                bb[nt][1] = __float_as_uint(Ws[(kb+t+4)*72 + bn]);
            }
            #pragma unroll
            for (int mt = 0; mt < 2; mt++)
                #pragma unroll
                for (int nt = 0; nt < 4; nt++)
                    mma8(c[mt][nt], a[mt][0],a[mt][1],a[mt][2],a[mt][3],
                         bb[nt][0], bb[nt][1]);
        }
        __syncthreads();
    }
    #pragma unroll
    for (int mt = 0; mt < 2; mt++) {
        #pragma unroll
        for (int nt = 0; nt < 4; nt++) {
            int col = n0 + wn*32 + nt*8 + 2*t;
            float b0 = __ldg(bo + col), b1 = __ldg(bo + col + 1);
            #pragma unroll
            for (int r = 0; r < 2; r++) {
                int row = m0 + wm*32 + mt*16 + g + r*8;
                float2 q = *(const float2*)(query + (size_t)row*Dc + col);
                float v0 = (r ? c[mt][nt].z : c[mt][nt].x) + b0 + q.x;
                float v1 = (r ? c[mt][nt].w : c[mt][nt].y) + b1 + q.y;
                *(float2*)(g_x + (size_t)row*Dc + col) = make_float2(v0, v1);
            }
        }
    }
}

// ---------------- token-type bias ----------------
__global__ __launch_bounds__(256)
void tt_kernel(const float* __restrict__ rsb, const float* __restrict__ seg) {
    int warp = threadIdx.x >> 5, lane = threadIdx.x & 31;
    int row = blockIdx.x * 8 + warp;
    int n = (row / Sc) % Nc;
    const float* q = &g_qh[(size_t)row * Hc];
    float d = 0.f, s = 0.f;
    #pragma unroll
    for (int p = 0; p < 2; p++) {
        int h = lane + p*32;
        float qv = q[h] + rsb[n*Hc + h] * SCALE;
        d += qv * seg[(0*Nc + n)*Hc + h];
        s += qv * seg[(1*Nc + n)*Hc + h];
    }
    #pragma unroll
    for (int off = 16; off; off >>= 1) {
        d += __shfl_xor_sync(~0u, d, off);
        s += __shfl_xor_sync(~0u, s, off);
    }
    if (lane == 0) { g_tt[(size_t)row*2 + 0] = d; g_tt[(size_t)row*2 + 1] = s; }
}

// ============ fused attention (tf32 mma) ============
#define LDQ 68
#define LDV 72
#define LDP 132
extern __shared__ float smdyn[];
__global__ __launch_bounds__(256, 2)
void attn_kernel(const float* __restrict__ rwb, const float* __restrict__ rrb,
                 const unsigned char* __restrict__ ttm,
                 const float* __restrict__ amask_g,
                 const float* __restrict__ clsm) {
    float* sq   = smdyn;            // 64*68 raw q (tf32-rounded, pre-bias)
    float* skv  = sq  + 64*LDQ;     // 64*72: K (stride 68) then V (stride 72)
    float* srs  = skv + 64*LDV;     // 128*68 r band (tf32)
    float* ps   = srs + 64*LDQ;     // overlay on srs rows 64..127
    float* posb = srs + 128*LDQ;    // 64*132
    float* rwbs = posb + 64*LDP;    // 64
    float* rrbs = rwbs + 64;        // 64
    float* samk = rrbs + 64;        // 64
    float* sttd = samk + 64;        // 128
    float* smM  = sttd + 128;       // 64
    float* smL  = smM + 64;         // 64
    float* sCor = smL + 64;         // 64
    float* mprt = sCor + 64;        // 128 [2][64]
    float* lprt = mprt + 128;       // 128

    int tid = threadIdx.x, w = tid >> 5, lane = tid & 31;
    int g = lane >> 2, t = lane & 3;
    int mt = w & 3, nh = w >> 2;
    int mtb = mt * 16;
    int i0 = blockIdx.x * 64, n = blockIdx.y, b = blockIdx.z;

    const float* qbase = &g_qh[(((size_t)b*Nc + n)*Sc + i0) * Hc];
    const float* kbase = &g_kh[(((size_t)b*Nc + n)*Sc) * Hc];
    const float* vbase = &g_vh[(((size_t)b*Nc + n)*Sc) * Hc];
    const float* rbase = &g_rh[(size_t)n * Rc * Hc];

    #pragma unroll
    for (int p = 0; p < 4; p++) {
        int idx = tid + p*256;
        int m = idx >> 4, h4 = (idx & 15) * 4;
        *(float4*)(sq + m*LDQ + h4) = *(const float4*)(qbase + m*Hc + h4);
    }
    if (tid < 64) {
        rwbs[tid] = rwb[n*Hc + tid] * SCALE;
        rrbs[tid] = rrb[n*Hc + tid] * SCALE;
        smM[tid] = -3.0e38f; smL[tid] = 0.f;
    }
    if (tid < 128) sttd[tid] = g_tt[(((size_t)b*Nc + n)*Sc + i0)*2 + tid];

    float4 of[4];
    #pragma unroll
    for (int nt = 0; nt < 4; nt++) of[nt] = make_float4(0.f,0.f,0.f,0.f);

    int u0 = mtb + g, u1 = u0 + 8;

    for (int j0 = 0; j0 < Sc; j0 += 64) {
        __syncthreads();
        // stage K (stride LDQ), band rs, amask
        #pragma unroll
        for (int p = 0; p < 4; p++) {
            int idx = tid + p*256;
            int j = idx >> 4, h4 = (idx & 15) * 4;
            *(float4*)(skv + j*LDQ + h4) =
                *(const float4*)(kbase + (size_t)(j0 + j)*Hc + h4);
        }
        int t_base = Sc - i0 - 63 + j0;
        #pragma unroll
        for (int p = 0; p < 8; p++) {
            int idx = tid + p*256;
            int r = idx >> 4, h4 = (idx & 15) * 4;
            int tt = t_base + r;
            float4 v = (tt >= 0 && tt < Rc)
                ? *(const float4*)(rbase + (size_t)tt*Hc + h4)
                : make_float4(0.f,0.f,0.f,0.f);
            *(float4*)(srs + r*LDQ + h4) = v;
        }
        if (tid < 64) samk[tid] = amask_g[b*Sc + j0 + tid];
        __syncthreads();

        // pos mma: pos_full[u][v] (64 x 128), two passes of 4 n-tiles
        #pragma unroll
        for (int half = 0; half < 2; half++) {
            float4 pf[4];
            #pragma unroll
            for (int nt = 0; nt < 4; nt++) pf[nt] = make_float4(0.f,0.f,0.f,0.f);
            #pragma unroll
            for (int ks = 0; ks < 8; ks++) {
                int kb = ks * 8;
                float bw0 = rrbs[kb+t], bw1 = rrbs[kb+t+4];
                unsigned a0 = f2tf(sq[u0*LDQ + kb+t  ] + bw0);
                unsigned a1 = f2tf(sq[u1*LDQ + kb+t  ] + bw0);
                unsigned a2 = f2tf(sq[u0*LDQ + kb+t+4] + bw1);
                unsigned a3 = f2tf(sq[u1*LDQ + kb+t+4] + bw1);
                #pragma unroll
                for (int nt = 0; nt < 4; nt++) {
                    int nb = nh*64 + half*32 + nt*8 + g;
                    unsigned b0 = __float_as_uint(srs[nb*LDQ + kb+t  ]);
                    unsigned b1 = __float_as_uint(srs[nb*LDQ + kb+t+4]);
                    mma8(pf[nt], a0,a1,a2,a3,b0,b1);
                }
            }
            #pragma unroll
            for (int nt = 0; nt < 4; nt++) {
                int v = nh*64 + half*32 + nt*8 + 2*t;
                *(float2*)(posb + u0*LDP + v) = make_float2(pf[nt].x, pf[nt].y);
                *(float2*)(posb + u1*LDP + v) = make_float2(pf[nt].z, pf[nt].w);
            }
        }
        // content mma: S (64 x 64)
        float4 sc[4];
        #pragma unroll
        for (int nt = 0; nt < 4; nt++) sc[nt] = make_float4(0.f,0.f,0.f,0.f);
        #pragma unroll
        for (int ks = 0; ks < 8; ks++) {
            int kb = ks * 8;
            float bw0 = rwbs[kb+t], bw1 = rwbs[kb+t+4];
            unsigned a0 = f2tf(sq[u0*LDQ + kb+t  ] + bw0);
            unsigned a1 = f2tf(sq[u1*LDQ + kb+t  ] + bw0);
            unsigned a2 = f2tf(sq[u0*LDQ + kb+t+4] + bw1);
            unsigned a3 = f2tf(sq[u1*LDQ + kb+t+4] + bw1);
            #pragma unroll
            for (int nt = 0; nt < 4; nt++) {
                int nb = nh*32 + nt*8 + g;
                unsigned b0 = __float_as_uint(skv[nb*LDQ + kb+t  ]);
                unsigned b1 = __float_as_uint(skv[nb*LDQ + kb+t+4]);
                mma8(sc[nt], a0,a1,a2,a3,b0,b1);
            }
        }
        __syncthreads();   // posb visible; skv(K) free

        // stage V (stride LDV)
        #pragma unroll
        for (int p = 0; p < 4; p++) {
            int idx = tid + p*256;
            int j = idx >> 4, h4 = (idx & 15) * 4;
            *(float4*)(skv + j*LDV + h4) =
                *(const float4*)(vbase + (size_t)(j0 + j)*Hc + h4);
        }
        // softmax part 1: full scores + partial row max
        int ii0 = i0 + u0, ii1 = i0 + u1;
        float td0 = sttd[2*u0], ts0 = sttd[2*u0+1];
        float td1 = sttd[2*u1], ts1 = sttd[2*u1+1];
        float mrow0 = -3.0e38f, mrow1 = -3.0e38f;
        #pragma unroll
        for (int nt = 0; nt < 4; nt++) {
            int j = nh*32 + nt*8 + 2*t, jj = j0 + j;
            float msk0 = INFV * (1.f - samk[j]);
            float msk1 = INFV * (1.f - samk[j+1]);
            float2 cls0 = *(const float2*)(clsm + (size_t)ii0*Sc + jj);
            float2 cls1 = *(const float2*)(clsm + (size_t)ii1*Sc + jj);
            unsigned short tz0 = *(const unsigned short*)(ttm + ((size_t)b*Sc+ii0)*Sc + jj);
            unsigned short tz1 = *(const unsigned short*)(ttm + ((size_t)b*Sc+ii1)*Sc + jj);
            float p00 = posb[u0*LDP + j   - u0 + 63];
            float p01 = posb[u0*LDP + j+1 - u0 + 63];
            float p10 = posb[u1*LDP + j   - u1 + 63];
            float p11 = posb[u1*LDP + j+1 - u1 + 63];
            sc[nt].x += cls0.x * (p00 + ((tz0 & 0xFF) ? ts0 : td0)); sc[nt].x -= msk0;
            sc[nt].y += cls0.y * (p01 + ((tz0 >> 8 ) ? ts0 : td0)); sc[nt].y -= msk1;
            sc[nt].z += cls1.x * (p10 + ((tz1 & 0xFF) ? ts1 : td1)); sc[nt].z -= msk0;
            sc[nt].w += cls1.y * (p11 + ((tz1 >> 8 ) ? ts1 : td1)); sc[nt].w -= msk1;
            mrow0 = fmaxf(mrow0, fmaxf(sc[nt].x, sc[nt].y));
            mrow1 = fmaxf(mrow1, fmaxf(sc[nt].z, sc[nt].w));
        }
        mrow0 = fmaxf(mrow0, __shfl_xor_sync(~0u, mrow0, 1));
        mrow0 = fmaxf(mrow0, __shfl_xor_sync(~0u, mrow0, 2));
        mrow1 = fmaxf(mrow1, __shfl_xor_sync(~0u, mrow1, 1));
        mrow1 = fmaxf(mrow1, __shfl_xor_sync(~0u, mrow1, 2));
        if (t == 0) { mprt[nh*64 + u0] = mrow0; mprt[nh*64 + u1] = mrow1; }
        __syncthreads();

        // softmax part 2: exp, P staging, partial sums
        float mn0 = fmaxf(smM[u0], fmaxf(mprt[u0], mprt[64 + u0]));
        float mn1 = fmaxf(smM[u1], fmaxf(mprt[u1], mprt[64 + u1]));
        float ls0 = 0.f, ls1 = 0.f;
        #pragma unroll
        for (int nt = 0; nt < 4; nt++) {
            int j = nh*32 + nt*8 + 2*t;
            float e00 = __expf(sc[nt].x - mn0), e01 = __expf(sc[nt].y - mn0);
            float e10 = __expf(sc[nt].z - mn1), e11 = __expf(sc[nt].w - mn1);
            ls0 += e00 + e01; ls1 += e10 + e11;
            *(float2*)(ps + u0*LDQ + j) =
                make_float2(__uint_as_float(f2tf(e00)), __uint_as_float(f2tf(e01)));
            *(float2*)(ps + u1*LDQ + j) =
                make_float2(__uint_as_float(f2tf(e10)), __uint_as_float(f2tf(e11)));
        }
        ls0 += __shfl_xor_sync(~0u, ls0, 1); ls0 += __shfl_xor_sync(~0u, ls0, 2);
        ls1 += __shfl_xor_sync(~0u, ls1, 1); ls1 += __shfl_xor_sync(~0u, ls1, 2);
        if (t == 0) { lprt[nh*64 + u0] = ls0; lprt[nh*64 + u1] = ls1; }
        __syncthreads();

        if (tid < 64) {
            int u = tid;
            float mn = fmaxf(smM[u], fmaxf(mprt[u], mprt[64 + u]));
            float corr = __expf(smM[u] - mn);
            smL[u] = smL[u] * corr + lprt[u] + lprt[64 + u];
            smM[u] = mn; sCor[u] = corr;
        }
        __syncthreads();

        // PV mma: O += P @ V  (warp tile 16 x 32 over (i, h))
        float cr0 = sCor[u0], cr1 = sCor[u1];
        #pragma unroll
        for (int nt = 0; nt < 4; nt++) {
            of[nt].x *= cr0; of[nt].y *= cr0;
            of[nt].z *= cr1; of[nt].w *= cr1;
        }
        #pragma unroll
        for (int ks = 0; ks < 8; ks++) {
            int kb = ks * 8;
            unsigned a0 = __float_as_uint(ps[u0*LDQ + kb+t  ]);
            unsigned a1 = __float_as_uint(ps[u1*LDQ + kb+t  ]);
            unsigned a2 = __float_as_uint(ps[u0*LDQ + kb+t+4]);
            unsigned a3 = __float_as_uint(ps[u1*LDQ + kb+t+4]);
            #pragma unroll
            for (int nt = 0; nt < 4; nt++) {
                int nb = nh*32 + nt*8 + g;
                unsigned b0 = __float_as_uint(skv[(kb+t  )*LDV + nb]);
                unsigned b1 = __float_as_uint(skv[(kb+t+4)*LDV + nb]);
                mma8(of[nt], a0,a1,a2,a3,b0,b1);
            }
        }
    }

    float inv0 = 1.f / smL[u0], inv1 = 1.f / smL[u1];
    float* outb = &g_av[(((size_t)b*Nc + n)*Sc + i0) * Hc];
    #pragma unroll
    for (int nt = 0; nt < 4; nt++) {
        int h = nh*32 + nt*8 + 2*t;
        *(float2*)(outb + (size_t)u0*Hc + h) =
            make_float2(__uint_as_float(f2tf(of[nt].x * inv0)),
                        __uint_as_float(f2tf(of[nt].y * inv0)));
        *(float2*)(outb + (size_t)u1*Hc + h) =
            make_float2(__uint_as_float(f2tf(of[nt].z * inv1)),
                        __uint_as_float(f2tf(of[nt].w * inv1)));
    }
}

// ---------------- LayerNorm ----------------
__global__ __launch_bounds__(256)
void ln_kernel(const float* __restrict__ lng, const float* __restrict__ lnb,
               float* __restrict__ out) {
    __shared__ float red[8];
    __shared__ float stat;
    int row = blockIdx.x;
    const float* x = &g_x[(size_t)row * Dc];
    int t = threadIdx.x;
    float v[3];
    float s = 0.f;
    #pragma unroll
    for (int p = 0; p < 3; p++) { v[p] = x[t + p*256]; s += v[p]; }
    #pragma unroll
    for (int off = 16; off; off >>= 1) s += __shfl_xor_sync(~0u, s, off);
    if ((t & 31) == 0) red[t >> 5] = s;
    __syncthreads();
    if (t < 32) {
        float r = (t < 8) ? red[t] : 0.f;
        #pragma unroll
        for (int off = 4; off; off >>= 1) r += __shfl_xor_sync(~0u, r, off);
        if (t == 0) stat = r * (1.f / Dc);
    }
    __syncthreads();
    float mu = stat;
    float s2 = 0.f;
    #pragma unroll
    for (int p = 0; p < 3; p++) { float d = v[p] - mu; s2 += d*d; }
    #pragma unroll
    for (int off = 16; off; off >>= 1) s2 += __shfl_xor_sync(~0u, s2, off);
    if ((t & 31) == 0) red[t >> 5] = s2;
    __syncthreads();
    if (t < 32) {
        float r = (t < 8) ? red[t] : 0.f;
        #pragma unroll
        for (int off = 4; off; off >>= 1) r += __shfl_xor_sync(~0u, r, off);
        if (t == 0) stat = rsqrtf(r * (1.f / Dc) + EPSV);
    }
    __syncthreads();
    float rstd = stat;
    #pragma unroll
    for (int p = 0; p < 3; p++) {
        int i = t + p*256;
        out[(size_t)row*Dc + i] = (v[p] - mu) * rstd * lng[i] + lnb[i];
    }
}

// ---------------- launch ----------------
extern "C" void kernel_launch(void* const* d_in, const int* in_sizes, int n_in,
                              void* d_out, int out_size) {
    const float* query = (const float*)d_in[0];
    const float* key   = (const float*)d_in[1];
    const float* value = (const float*)d_in[2];
    const float* pose  = (const float*)d_in[3];
    const unsigned char* ttm = (const unsigned char*)d_in[4];
    const float* amask = (const float*)d_in[5];
    const float* clsm  = (const float*)d_in[6];
    const float* Wq    = (const float*)d_in[7];
    const float* Wk    = (const float*)d_in[8];
    const float* bk    = (const float*)d_in[9];
    const float* Wv    = (const float*)d_in[10];
    const float* bv    = (const float*)d_in[11];
    const float* rwb   = (const float*)d_in[12];
    const float* rrb   = (const float*)d_in[13];
    const float* rker  = (const float*)d_in[14];
    const float* rsb   = (const float*)d_in[15];
    const float* seg   = (const float*)d_in[16];
    const float* Wo    = (const float*)d_in[17];
    const float* bo    = (const float*)d_in[18];
    const float* lng   = (const float*)d_in[19];
    const float* lnb   = (const float*)d_in[20];
    float* out = (float*)d_out;

    float *qh, *kh, *vh, *rh;
    cudaGetSymbolAddress((void**)&qh, g_qh);
    cudaGetSymbolAddress((void**)&kh, g_kh);
    cudaGetSymbolAddress((void**)&vh, g_vh);
    cudaGetSymbolAddress((void**)&rh, g_rh);

    dim3 blk(256);
    gemm_proj_t<<<dim3(12, 32), blk>>>(query, Wq, nullptr, SCALE, 10, qh);
    gemm_proj_t<<<dim3(12, 32), blk>>>(key,   Wk, bk,      1.0f, 10, kh);
    gemm_proj_t<<<dim3(12, 32), blk>>>(value, Wv, bv,      1.0f, 10, vh);
    gemm_proj_t<<<dim3(12, 16), blk>>>(pose,  rker, nullptr, 1.0f, 11, rh);

    tt_kernel<<<Bc*Nc*Sc/8, blk>>>(rsb, seg);

    size_t smem = (size_t)(64*LDQ + 64*LDV + 128*LDQ + 64*LDP + 768) * sizeof(float);
    cudaFuncSetAttribute(attn_kernel, cudaFuncAttributeMaxDynamicSharedMemorySize,
                         (int)smem);
    attn_kernel<<<dim3(Sc/64, Nc, Bc), blk, smem>>>(rwb, rrb, ttm, amask, clsm);

    gemm_out_t<<<dim3(12, 32), blk>>>(Wo, bo, query);

    ln_kernel<<<Bc*Sc, blk>>>(lng, lnb, out);
}

// round 5
// speedup vs baseline: 1.7731x; 1.7731x over previous
#include <cuda_runtime.h>
#include <cuda_bf16.h>
#include <math.h>

#define Bc 4
#define Sc 1024
#define Dc 768
#define Nc 12
#define Hc 64
#define Rc 2048
#define SCALE 0.125f
#define INFV 1000000.0f
#define EPSV 1e-9f

typedef unsigned int uint;
typedef __nv_bfloat16 bf;

__device__ __align__(16) bf    g_qh[Bc*Nc*Sc*Hc];
__device__ __align__(16) bf    g_kh[Bc*Nc*Sc*Hc];
__device__ __align__(16) bf    g_vh[Bc*Nc*Sc*Hc];
__device__ __align__(16) bf    g_rh[Nc*Rc*Hc];
__device__ float g_tt[Bc*Nc*Sc*2];
__device__ __align__(16) bf    g_av[Bc*Nc*Sc*Hc];
__device__ float g_x [Bc*Sc*Dc];

// ---------- helpers ----------
__device__ __forceinline__ uint smaddr(const void* p) {
    return (uint)__cvta_generic_to_shared(p);
}
__device__ __forceinline__ uint4 ldsm4(uint a) {
    uint4 r;
    asm volatile("ldmatrix.sync.aligned.m8n8.x4.shared.b16 {%0,%1,%2,%3},[%4];"
        : "=r"(r.x), "=r"(r.y), "=r"(r.z), "=r"(r.w) : "r"(a));
    return r;
}
__device__ __forceinline__ uint4 ldsm4t(uint a) {
    uint4 r;
    asm volatile("ldmatrix.sync.aligned.m8n8.x4.trans.shared.b16 {%0,%1,%2,%3},[%4];"
        : "=r"(r.x), "=r"(r.y), "=r"(r.z), "=r"(r.w) : "r"(a));
    return r;
}
// A (row-major [m][k]) 16x16 at (row0, kb)
__device__ __forceinline__ uint adrA(const bf* b, int ld, int row0, int kb) {
    int l = threadIdx.x & 31;
    return smaddr(b + (row0 + (l & 15)) * ld + kb + ((l >> 4) << 3));
}
// B from n-major [n][k]: 16n x 16k at (nb, kb)  (non-trans)
__device__ __forceinline__ uint adrB(const bf* b, int ld, int nb, int kb) {
    int l = threadIdx.x & 31;
    return smaddr(b + (nb + (l & 7) + ((l & 16) >> 1)) * ld + kb + (l & 8));
}
// B from k-major [k][n]: 16k x 16n at (kb, nb)  (trans)
__device__ __forceinline__ uint adrBT(const bf* b, int ld, int kb, int nb) {
    int l = threadIdx.x & 31;
    return smaddr(b + (kb + (l & 7) + (l & 8)) * ld + nb + ((l & 16) >> 1));
}
__device__ __forceinline__ void mmabf(float4& c, uint4 a, uint b0, uint b1) {
    asm volatile(
        "mma.sync.aligned.m16n8k16.row.col.f32.bf16.bf16.f32 "
        "{%0,%1,%2,%3},{%4,%5,%6,%7},{%8,%9},{%0,%1,%2,%3};"
        : "+f"(c.x), "+f"(c.y), "+f"(c.z), "+f"(c.w)
        : "r"(a.x), "r"(a.y), "r"(a.z), "r"(a.w), "r"(b0), "r"(b1));
}
__device__ __forceinline__ uint bfpair(float lo, float hi) {
    uint r; asm("cvt.rn.bf16x2.f32 %0,%1,%2;" : "=r"(r) : "f"(hi), "f"(lo));
    return r;
}
__device__ __forceinline__ uint addb2(uint a, uint b) {
    uint r; asm("add.rn.bf16x2 %0,%1,%2;" : "=r"(r) : "r"(a), "r"(b));
    return r;
}
__device__ __forceinline__ uint2 pack4(float4 v) {
    uint2 r; r.x = bfpair(v.x, v.y); r.y = bfpair(v.z, v.w); return r;
}

// ---------- input GEMM core: out = bf16((A@W)*scale + bias) scattered to [B,N,S,H] ----------
// 256 thr, tile 128M x 64N, KC=64, warps 4(wm) x 2(wn), warp tile 32x32
__device__ __forceinline__ void gemm_core(
    const float* __restrict__ A, const float* __restrict__ W,
    const float* __restrict__ bias, float scale, int sshift, bf* __restrict__ out) {
    __shared__ bf As[128 * 72];   // [m][k]
    __shared__ bf Ws[64 * 72];    // [k][n]
    int tid = threadIdx.x, l = tid & 31, g = l >> 2, t = l & 3, w = tid >> 5;
    int wm = w & 3, wn = w >> 2;
    int m0 = blockIdx.y * 128, n0 = blockIdx.x * 64;
    int Srows = 1 << sshift;

    float4 c[2][4];
    #pragma unroll
    for (int i = 0; i < 2; i++)
        #pragma unroll
        for (int j = 0; j < 4; j++) c[i][j] = make_float4(0.f, 0.f, 0.f, 0.f);

    for (int k0 = 0; k0 < Dc; k0 += 64) {
        #pragma unroll
        for (int p = 0; p < 8; p++) {
            int cid = tid + p * 256;
            int row = cid >> 4, kq = (cid & 15) << 2;
            float4 v = *(const float4*)(A + (size_t)(m0 + row) * Dc + k0 + kq);
            *(uint2*)(As + row * 72 + kq) = pack4(v);
        }
        #pragma unroll
        for (int p = 0; p < 4; p++) {
            int cid = tid + p * 256;
            int kk = cid >> 4, nq = (cid & 15) << 2;
            float4 v = *(const float4*)(W + (size_t)(k0 + kk) * Dc + n0 + nq);
            *(uint2*)(Ws + kk * 72 + nq) = pack4(v);
        }
        __syncthreads();
        #pragma unroll
        for (int ks = 0; ks < 4; ks++) {
            int kb = ks * 16;
            uint4 a0 = ldsm4(adrA(As, 72, wm * 32, kb));
            uint4 a1 = ldsm4(adrA(As, 72, wm * 32 + 16, kb));
            uint4 b0 = ldsm4t(adrBT(Ws, 72, kb, wn * 32));
            uint4 b1 = ldsm4t(adrBT(Ws, 72, kb, wn * 32 + 16));
            mmabf(c[0][0], a0, b0.x, b0.y); mmabf(c[0][1], a0, b0.z, b0.w);
            mmabf(c[0][2], a0, b1.x, b1.y); mmabf(c[0][3], a0, b1.z, b1.w);
            mmabf(c[1][0], a1, b0.x, b0.y); mmabf(c[1][1], a1, b0.z, b0.w);
            mmabf(c[1][2], a1, b1.x, b1.y); mmabf(c[1][3], a1, b1.z, b1.w);
        }
        __syncthreads();
    }
    #pragma unroll
    for (int mi = 0; mi < 2; mi++) {
        #pragma unroll
        for (int nt = 0; nt < 4; nt++) {
            int col = n0 + wn * 32 + nt * 8 + 2 * t;
            float b0f = bias ? __ldg(bias + col) : 0.f;
            float b1f = bias ? __ldg(bias + col + 1) : 0.f;
            int nn = col >> 6, hh = col & 63;
            #pragma unroll
            for (int r = 0; r < 2; r++) {
                int row = m0 + wm * 32 + mi * 16 + g + r * 8;
                int bb = row >> sshift, ss = row & (Srows - 1);
                float v0 = (r ? c[mi][nt].z : c[mi][nt].x) * scale + b0f;
                float v1 = (r ? c[mi][nt].w : c[mi][nt].y) * scale + b1f;
                *(uint*)(out + (((size_t)bb * Nc + nn) * Srows + ss) * Hc + hh) =
                    bfpair(v0, v1);
            }
        }
    }
}

__global__ __launch_bounds__(256)
void gemm_in(const float* q, const float* k, const float* v,
             const float* Wq, const float* Wk, const float* Wv,
             const float* bk, const float* bv) {
    int z = blockIdx.z;
    if (z == 0)      gemm_core(q, Wq, nullptr, SCALE, 10, g_qh);
    else if (z == 1) gemm_core(k, Wk, bk, 1.f, 10, g_kh);
    else             gemm_core(v, Wv, bv, 1.f, 10, g_vh);
}
__global__ __launch_bounds__(256)
void gemm_r(const float* pose, const float* rker) {
    gemm_core(pose, rker, nullptr, 1.f, 11, g_rh);
}

// ---------- output GEMM + residual ----------
__global__ __launch_bounds__(256)
void gemm_out_b(const float* __restrict__ Wo, const float* __restrict__ bo,
                const float* __restrict__ query) {
    __shared__ bf As[128 * 72];
    __shared__ bf Ws[64 * 72];
    int tid = threadIdx.x, l = tid & 31, g = l >> 2, t = l & 3, w = tid >> 5;
    int wm = w & 3, wn = w >> 2;
    int m0 = blockIdx.y * 128, n0 = blockIdx.x * 64;
    float4 c[2][4];
    #pragma unroll
    for (int i = 0; i < 2; i++)
        #pragma unroll
        for (int j = 0; j < 4; j++) c[i][j] = make_float4(0.f, 0.f, 0.f, 0.f);

    for (int k0 = 0; k0 < Dc; k0 += 64) {
        int nn = k0 >> 6;
        #pragma unroll
        for (int p = 0; p < 4; p++) {
            int cid = tid + p * 256;
            int row = cid >> 3, kq = (cid & 7) << 3;
            int rg = m0 + row;
            *(uint4*)(As + row * 72 + kq) = *(const uint4*)(g_av +
                (((size_t)(rg >> 10) * Nc + nn) * Sc + (rg & 1023)) * Hc + kq);
        }
        #pragma unroll
        for (int p = 0; p < 4; p++) {
            int cid = tid + p * 256;
            int kk = cid >> 4, nq = (cid & 15) << 2;
            float4 v = *(const float4*)(Wo + (size_t)(k0 + kk) * Dc + n0 + nq);
            *(uint2*)(Ws + kk * 72 + nq) = pack4(v);
        }
        __syncthreads();
        #pragma unroll
        for (int ks = 0; ks < 4; ks++) {
            int kb = ks * 16;
            uint4 a0 = ldsm4(adrA(As, 72, wm * 32, kb));
            uint4 a1 = ldsm4(adrA(As, 72, wm * 32 + 16, kb));
            uint4 b0 = ldsm4t(adrBT(Ws, 72, kb, wn * 32));
            uint4 b1 = ldsm4t(adrBT(Ws, 72, kb, wn * 32 + 16));
            mmabf(c[0][0], a0, b0.x, b0.y); mmabf(c[0][1], a0, b0.z, b0.w);
            mmabf(c[0][2], a0, b1.x, b1.y); mmabf(c[0][3], a0, b1.z, b1.w);
            mmabf(c[1][0], a1, b0.x, b0.y); mmabf(c[1][1], a1, b0.z, b0.w);
            mmabf(c[1][2], a1, b1.x, b1.y); mmabf(c[1][3], a1, b1.z, b1.w);
        }
        __syncthreads();
    }
    #pragma unroll
    for (int mi = 0; mi < 2; mi++) {
        #pragma unroll
        for (int nt = 0; nt < 4; nt++) {
            int col = n0 + wn * 32 + nt * 8 + 2 * t;
            float b0f = __ldg(bo + col), b1f = __ldg(bo + col + 1);
            #pragma unroll
            for (int r = 0; r < 2; r++) {
                int row = m0 + wm * 32 + mi * 16 + g + r * 8;
                float2 q = *(const float2*)(query + (size_t)row * Dc + col);
                float v0 = (r ? c[mi][nt].z : c[mi][nt].x) + b0f + q.x;
                float v1 = (r ? c[mi][nt].w : c[mi][nt].y) + b1f + q.y;
                *(float2*)(g_x + (size_t)row * Dc + col) = make_float2(v0, v1);
            }
        }
    }
}

// ---------- token-type bias ----------
__global__ __launch_bounds__(256)
void tt_kernel(const float* __restrict__ rsb, const float* __restrict__ seg) {
    int warp = threadIdx.x >> 5, lane = threadIdx.x & 31;
    int row = blockIdx.x * 8 + warp;
    int n = (row / Sc) % Nc;
    const bf* q = &g_qh[(size_t)row * Hc];
    float d = 0.f, s = 0.f;
    #pragma unroll
    for (int p = 0; p < 2; p++) {
        int h = lane + p * 32;
        float qv = __bfloat162float(q[h]) + rsb[n * Hc + h] * SCALE;
        d += qv * seg[(0 * Nc + n) * Hc + h];
        s += qv * seg[(1 * Nc + n) * Hc + h];
    }
    #pragma unroll
    for (int off = 16; off; off >>= 1) {
        d += __shfl_xor_sync(~0u, d, off);
        s += __shfl_xor_sync(~0u, s, off);
    }
    if (lane == 0) { g_tt[(size_t)row*2 + 0] = d; g_tt[(size_t)row*2 + 1] = s; }
}

// ---------- fused attention (bf16 mma) ----------
// bf16 region offsets (units of bf16)
#define OQ   0
#define OK_  4608
#define OV   9216
#define OP   13824
#define ORS  18432
#define ORW  27648
#define ORR  27712
#define FOFF 27776
#define SMEM_ATTN (FOFF*2 + (8*16*56 + 64 + 128 + 128 + 128)*4)

extern __shared__ bf smb[];
__global__ __launch_bounds__(256)
void attn_kernel(const float* __restrict__ rwb, const float* __restrict__ rrb,
                 const unsigned char* __restrict__ ttm,
                 const float* __restrict__ amask_g,
                 const float* __restrict__ clsm) {
    bf* sq  = smb + OQ;    // [64][72] q_head*scale
    bf* sk  = smb + OK_;   // [64][72] K
    bf* sv  = smb + OV;    // [64][72] V
    bf* sp  = smb + OP;    // [64][72] P
    bf* srs = smb + ORS;   // [128][72] r band
    bf* rwbs = smb + ORW;  // [64]
    bf* rrbs = smb + ORR;  // [64]
    float* fb   = (float*)(smb + FOFF);
    float* pww  = fb;            // [8][16][56] per-warp pos band (fp32)
    float* samk = fb + 8*16*56;  // 64
    float* sttd = samk + 64;     // 128
    float* mpart = sttd + 128;   // 128
    float* lpart = mpart + 128;  // 128

    int tid = threadIdx.x, l = tid & 31, g = l >> 2, t = l & 3, w = tid >> 5;
    int mt = w >> 1, nh = w & 1;
    int mtb = mt * 16;
    int i0 = blockIdx.x * 64, n = blockIdx.y, b = blockIdx.z;

    const bf* qbase = g_qh + (((size_t)b*Nc + n)*Sc + i0) * Hc;
    const bf* kbase = g_kh + (((size_t)b*Nc + n)*Sc) * Hc;
    const bf* vbase = g_vh + (((size_t)b*Nc + n)*Sc) * Hc;
    const bf* rbase = g_rh + (size_t)n * Rc * Hc;

    #pragma unroll
    for (int p = 0; p < 2; p++) {
        int cid = tid + p * 256;
        int row = cid >> 3, h8 = (cid & 7) << 3;
        *(uint4*)(sq + row * 72 + h8) = *(const uint4*)(qbase + row * Hc + h8);
    }
    if (tid < 64) {
        rwbs[tid] = __float2bfloat16(rwb[n * Hc + tid] * SCALE);
        rrbs[tid] = __float2bfloat16(rrb[n * Hc + tid] * SCALE);
    }
    if (tid < 128) sttd[tid] = g_tt[(((size_t)b*Nc + n)*Sc + i0)*2 + tid];

    float4 of[4];
    #pragma unroll
    for (int nt = 0; nt < 4; nt++) of[nt] = make_float4(0.f, 0.f, 0.f, 0.f);
    float m0r = -3.0e38f, m1r = -3.0e38f, l0r = 0.f, l1r = 0.f;

    int vmin = nh * 32 - mtb + 48;     // 48-wide pos window for this warp
    int u0 = mtb + g, u1 = u0 + 8;
    float* pw = pww + w * (16 * 56);

    for (int j0 = 0; j0 < Sc; j0 += 64) {
        __syncthreads();   // A: prev iter consumers done
        #pragma unroll
        for (int p = 0; p < 2; p++) {
            int cid = tid + p * 256;
            int row = cid >> 3, h8 = (cid & 7) << 3;
            *(uint4*)(sk + row * 72 + h8) =
                *(const uint4*)(kbase + (size_t)(j0 + row) * Hc + h8);
            *(uint4*)(sv + row * 72 + h8) =
                *(const uint4*)(vbase + (size_t)(j0 + row) * Hc + h8);
        }
        int t_base = Sc - i0 - 63 + j0;
        #pragma unroll
        for (int p = 0; p < 4; p++) {
            int cid = tid + p * 256;
            int row = cid >> 3, h8 = (cid & 7) << 3;
            int tt = t_base + row;
            uint4 vv = make_uint4(0u, 0u, 0u, 0u);
            if (tt >= 0 && tt < Rc)
                vv = *(const uint4*)(rbase + (size_t)tt * Hc + h8);
            *(uint4*)(srs + row * 72 + h8) = vv;
        }
        if (tid < 64) samk[tid] = amask_g[b * Sc + j0 + tid];
        __syncthreads();   // B: staging complete

        // content + pos mma
        float4 sc[4], pf[6];
        #pragma unroll
        for (int q_ = 0; q_ < 4; q_++) sc[q_] = make_float4(0.f, 0.f, 0.f, 0.f);
        #pragma unroll
        for (int q_ = 0; q_ < 6; q_++) pf[q_] = make_float4(0.f, 0.f, 0.f, 0.f);
        #pragma unroll
        for (int ks = 0; ks < 4; ks++) {
            int kb = ks * 16;
            uint4 qa = ldsm4(adrA(sq, 72, mtb, kb));
            uint rw0 = *(const uint*)(rwbs + kb + 2 * t);
            uint rw1 = *(const uint*)(rwbs + kb + 2 * t + 8);
            uint rr0 = *(const uint*)(rrbs + kb + 2 * t);
            uint rr1 = *(const uint*)(rrbs + kb + 2 * t + 8);
            uint4 aw, ar;
            aw.x = addb2(qa.x, rw0); aw.y = addb2(qa.y, rw0);
            aw.z = addb2(qa.z, rw1); aw.w = addb2(qa.w, rw1);
            ar.x = addb2(qa.x, rr0); ar.y = addb2(qa.y, rr0);
            ar.z = addb2(qa.z, rr1); ar.w = addb2(qa.w, rr1);
            uint4 bk0 = ldsm4(adrB(sk, 72, nh * 32, kb));
            uint4 bk1 = ldsm4(adrB(sk, 72, nh * 32 + 16, kb));
            mmabf(sc[0], aw, bk0.x, bk0.y); mmabf(sc[1], aw, bk0.z, bk0.w);
            mmabf(sc[2], aw, bk1.x, bk1.y); mmabf(sc[3], aw, bk1.z, bk1.w);
            uint4 br0 = ldsm4(adrB(srs, 72, vmin, kb));
            uint4 br1 = ldsm4(adrB(srs, 72, vmin + 16, kb));
            uint4 br2 = ldsm4(adrB(srs, 72, vmin + 32, kb));
            mmabf(pf[0], ar, br0.x, br0.y); mmabf(pf[1], ar, br0.z, br0.w);
            mmabf(pf[2], ar, br1.x, br1.y); mmabf(pf[3], ar, br1.z, br1.w);
            mmabf(pf[4], ar, br2.x, br2.y); mmabf(pf[5], ar, br2.z, br2.w);
        }
        #pragma unroll
        for (int q_ = 0; q_ < 6; q_++) {
            *(float2*)(pw + g * 56 + q_ * 8 + 2 * t)       = make_float2(pf[q_].x, pf[q_].y);
            *(float2*)(pw + (g + 8) * 56 + q_ * 8 + 2 * t) = make_float2(pf[q_].z, pf[q_].w);
        }
        __syncwarp();

        // combine scores; per-warp partial max/sum
        int ii0 = i0 + u0, ii1 = i0 + u1;
        float td0 = sttd[2*u0], ts0 = sttd[2*u0+1];
        float td1 = sttd[2*u1], ts1 = sttd[2*u1+1];
        float mr0 = -3.0e38f, mr1 = -3.0e38f;
        #pragma unroll
        for (int nt = 0; nt < 4; nt++) {
            int jl = nh * 32 + nt * 8 + 2 * t, jj = j0 + jl;
            float mk0 = INFV * (1.f - samk[jl]);
            float mk1 = INFV * (1.f - samk[jl + 1]);
            float2 c0 = *(const float2*)(clsm + (size_t)ii0 * Sc + jj);
            float2 c1 = *(const float2*)(clsm + (size_t)ii1 * Sc + jj);
            unsigned short z0 = *(const unsigned short*)(ttm + ((size_t)b*Sc + ii0)*Sc + jj);
            unsigned short z1 = *(const unsigned short*)(ttm + ((size_t)b*Sc + ii1)*Sc + jj);
            int vc0 = nt * 8 + 2 * t - g + 15;
            int vc1 = vc0 - 8;
            float p00 = pw[g * 56 + vc0],       p01 = pw[g * 56 + vc0 + 1];
            float p10 = pw[(g + 8) * 56 + vc1], p11 = pw[(g + 8) * 56 + vc1 + 1];
            sc[nt].x += c0.x * (p00 + ((z0 & 0xFF) ? ts0 : td0)); sc[nt].x -= mk0;
            sc[nt].y += c0.y * (p01 + ((z0 >> 8)   ? ts0 : td0)); sc[nt].y -= mk1;
            sc[nt].z += c1.x * (p10 + ((z1 & 0xFF) ? ts1 : td1)); sc[nt].z -= mk0;
            sc[nt].w += c1.y * (p11 + ((z1 >> 8)   ? ts1 : td1)); sc[nt].w -= mk1;
            mr0 = fmaxf(mr0, fmaxf(sc[nt].x, sc[nt].y));
            mr1 = fmaxf(mr1, fmaxf(sc[nt].z, sc[nt].w));
        }
        mr0 = fmaxf(mr0, __shfl_xor_sync(~0u, mr0, 1));
        mr0 = fmaxf(mr0, __shfl_xor_sync(~0u, mr0, 2));
        mr1 = fmaxf(mr1, __shfl_xor_sync(~0u, mr1, 1));
        mr1 = fmaxf(mr1, __shfl_xor_sync(~0u, mr1, 2));
        float ls0 = 0.f, ls1 = 0.f;
        #pragma unroll
        for (int nt = 0; nt < 4; nt++) {
            sc[nt].x = __expf(sc[nt].x - mr0); sc[nt].y = __expf(sc[nt].y - mr0);
            sc[nt].z = __expf(sc[nt].z - mr1); sc[nt].w = __expf(sc[nt].w - mr1);
            ls0 += sc[nt].x + sc[nt].y; ls1 += sc[nt].z + sc[nt].w;
        }
        ls0 += __shfl_xor_sync(~0u, ls0, 1); ls0 += __shfl_xor_sync(~0u, ls0, 2);
        ls1 += __shfl_xor_sync(~0u, ls1, 1); ls1 += __shfl_xor_sync(~0u, ls1, 2);
        if (t == 0) {
            mpart[nh * 64 + u0] = mr0; mpart[nh * 64 + u1] = mr1;
            lpart[nh * 64 + u0] = ls0; lpart[nh * 64 + u1] = ls1;
        }
        __syncthreads();   // C: partials visible

        // merge stats (redundantly in both nh warps of same mt — identical results)
        float a0m = mpart[u0], b0m = mpart[64 + u0];
        float a1m = mpart[u1], b1m = mpart[64 + u1];
        float mn0 = fmaxf(m0r, fmaxf(a0m, b0m));
        float mn1 = fmaxf(m1r, fmaxf(a1m, b1m));
        float co0 = __expf(m0r - mn0), co1 = __expf(m1r - mn1);
        l0r = l0r * co0 + lpart[u0] * __expf(a0m - mn0) + lpart[64 + u0] * __expf(b0m - mn0);
        l1r = l1r * co1 + lpart[u1] * __expf(a1m - mn1) + lpart[64 + u1] * __expf(b1m - mn1);
        m0r = mn0; m1r = mn1;
        // rescale this warp's P to the merged max and store to sp
        float f0 = __expf((nh ? b0m : a0m) - mn0);
        float f1 = __expf((nh ? b1m : a1m) - mn1);
        #pragma unroll
        for (int nt = 0; nt < 4; nt++) {
            int jl = nh * 32 + nt * 8 + 2 * t;
            *(uint*)(sp + u0 * 72 + jl) = bfpair(sc[nt].x * f0, sc[nt].y * f0);
            *(uint*)(sp + u1 * 72 + jl) = bfpair(sc[nt].z * f1, sc[nt].w * f1);
        }
        #pragma unroll
        for (int nt = 0; nt < 4; nt++) {
            of[nt].x *= co0; of[nt].y *= co0;
            of[nt].z *= co1; of[nt].w *= co1;
        }
        __syncthreads();   // D: sp complete

        // O += P @ V   (warp tile 16i x 32h)
        #pragma unroll
        for (int ks = 0; ks < 4; ks++) {
            int kb = ks * 16;
            uint4 ap = ldsm4(adrA(sp, 72, mtb, kb));
            uint4 v0 = ldsm4t(adrBT(sv, 72, kb, nh * 32));
            uint4 v1 = ldsm4t(adrBT(sv, 72, kb, nh * 32 + 16));
            mmabf(of[0], ap, v0.x, v0.y); mmabf(of[1], ap, v0.z, v0.w);
            mmabf(of[2], ap, v1.x, v1.y); mmabf(of[3], ap, v1.z, v1.w);
        }
    }

    float inv0 = 1.f / l0r, inv1 = 1.f / l1r;
    bf* outb = g_av + (((size_t)b*Nc + n)*Sc + i0) * Hc;
    #pragma unroll
    for (int nt = 0; nt < 4; nt++) {
        int h = nh * 32 + nt * 8 + 2 * t;
        *(uint*)(outb + (size_t)u0 * Hc + h) = bfpair(of[nt].x * inv0, of[nt].y * inv0);
        *(uint*)(outb + (size_t)u1 * Hc + h) = bfpair(of[nt].z * inv1, of[nt].w * inv1);
    }
}

// ---------- LayerNorm ----------
__global__ __launch_bounds__(256)
void ln_kernel(const float* __restrict__ lng, const float* __restrict__ lnb,
               float* __restrict__ out) {
    __shared__ float red[8];
    __shared__ float stat;
    int row = blockIdx.x;
    const float* x = &g_x[(size_t)row * Dc];
    int t = threadIdx.x;
    float v[3];
    float s = 0.f;
    #pragma unroll
    for (int p = 0; p < 3; p++) { v[p] = x[t + p*256]; s += v[p]; }
    #pragma unroll
    for (int off = 16; off; off >>= 1) s += __shfl_xor_sync(~0u, s, off);
    if ((t & 31) == 0) red[t >> 5] = s;
    __syncthreads();
    if (t < 32) {
        float r = (t < 8) ? red[t] : 0.f;
        #pragma unroll
        for (int off = 4; off; off >>= 1) r += __shfl_xor_sync(~0u, r, off);
        if (t == 0) stat = r * (1.f / Dc);
    }
    __syncthreads();
    float mu = stat;
    float s2 = 0.f;
    #pragma unroll
    for (int p = 0; p < 3; p++) { float d = v[p] - mu; s2 += d*d; }
    #pragma unroll
    for (int off = 16; off; off >>= 1) s2 += __shfl_xor_sync(~0u, s2, off);
    if ((t & 31) == 0) red[t >> 5] = s2;
    __syncthreads();
    if (t < 32) {
        float r = (t < 8) ? red[t] : 0.f;
        #pragma unroll
        for (int off = 4; off; off >>= 1) r += __shfl_xor_sync(~0u, r, off);
        if (t == 0) stat = rsqrtf(r * (1.f / Dc) + EPSV);
    }
    __syncthreads();
    float rstd = stat;
    #pragma unroll
    for (int p = 0; p < 3; p++) {
        int i = t + p*256;
        out[(size_t)row*Dc + i] = (v[p] - mu) * rstd * lng[i] + lnb[i];
    }
}

// ---------- launch ----------
extern "C" void kernel_launch(void* const* d_in, const int* in_sizes, int n_in,
                              void* d_out, int out_size) {
    const float* query = (const float*)d_in[0];
    const float* key   = (const float*)d_in[1];
    const float* value = (const float*)d_in[2];
    const float* pose  = (const float*)d_in[3];
    const unsigned char* ttm = (const unsigned char*)d_in[4];
    const float* amask = (const float*)d_in[5];
    const float* clsm  = (const float*)d_in[6];
    const float* Wq    = (const float*)d_in[7];
    const float* Wk    = (const float*)d_in[8];
    const float* bk    = (const float*)d_in[9];
    const float* Wv    = (const float*)d_in[10];
    const float* bv    = (const float*)d_in[11];
    const float* rwb   = (const float*)d_in[12];
    const float* rrb   = (const float*)d_in[13];
    const float* rker  = (const float*)d_in[14];
    const float* rsb   = (const float*)d_in[15];
    const float* seg   = (const float*)d_in[16];
    const float* Wo    = (const float*)d_in[17];
    const float* bo    = (const float*)d_in[18];
    const float* lng   = (const float*)d_in[19];
    const float* lnb   = (const float*)d_in[20];
    float* out = (float*)d_out;

    dim3 blk(256);
    gemm_in<<<dim3(12, 32, 3), blk>>>(query, key, value, Wq, Wk, Wv, bk, bv);
    gemm_r<<<dim3(12, 16), blk>>>(pose, rker);
    tt_kernel<<<Bc*Nc*Sc/8, blk>>>(rsb, seg);

    cudaFuncSetAttribute(attn_kernel, cudaFuncAttributeMaxDynamicSharedMemorySize,
                         SMEM_ATTN);
    attn_kernel<<<dim3(Sc/64, Nc, Bc), blk, SMEM_ATTN>>>(rwb, rrb, ttm, amask, clsm);

    gemm_out_b<<<dim3(12, 32), blk>>>(Wo, bo, query);
    ln_kernel<<<Bc*Sc, blk>>>(lng, lnb, out);
}

// round 6
// speedup vs baseline: 1.8481x; 1.0423x over previous
#include <cuda_runtime.h>
#include <cuda_bf16.h>
#include <math.h>

#define Bc 4
#define Sc 1024
#define Dc 768
#define Nc 12
#define Hc 64
#define Rc 2048
#define SCALE 0.125f
#define INFV 1000000.0f
#define EPSV 1e-9f

typedef unsigned int uint;
typedef __nv_bfloat16 bf;

__device__ __align__(16) bf    g_qh[Bc*Nc*Sc*Hc];
__device__ __align__(16) bf    g_kh[Bc*Nc*Sc*Hc];
__device__ __align__(16) bf    g_vh[Bc*Nc*Sc*Hc];
__device__ __align__(16) bf    g_rh[Nc*Rc*Hc];
__device__ float g_tt[Bc*Nc*Sc*2];
__device__ __align__(16) bf    g_av[Bc*Nc*Sc*Hc];
__device__ float g_x [Bc*Sc*Dc];
__device__ __align__(16) uint  g_cb[Bc*Sc*Sc];   // (e0,e1) bf16x2 per (b,i,j)

// ---------- helpers ----------
__device__ __forceinline__ uint smaddr(const void* p) {
    return (uint)__cvta_generic_to_shared(p);
}
__device__ __forceinline__ uint4 ldsm4(uint a) {
    uint4 r;
    asm volatile("ldmatrix.sync.aligned.m8n8.x4.shared.b16 {%0,%1,%2,%3},[%4];"
        : "=r"(r.x), "=r"(r.y), "=r"(r.z), "=r"(r.w) : "r"(a));
    return r;
}
__device__ __forceinline__ uint4 ldsm4t(uint a) {
    uint4 r;
    asm volatile("ldmatrix.sync.aligned.m8n8.x4.trans.shared.b16 {%0,%1,%2,%3},[%4];"
        : "=r"(r.x), "=r"(r.y), "=r"(r.z), "=r"(r.w) : "r"(a));
    return r;
}
__device__ __forceinline__ uint adrA(const bf* b, int ld, int row0, int kb) {
    int l = threadIdx.x & 31;
    return smaddr(b + (row0 + (l & 15)) * ld + kb + ((l >> 4) << 3));
}
__device__ __forceinline__ uint adrB(const bf* b, int ld, int nb, int kb) {
    int l = threadIdx.x & 31;
    return smaddr(b + (nb + (l & 7) + ((l & 16) >> 1)) * ld + kb + (l & 8));
}
__device__ __forceinline__ uint adrBT(const bf* b, int ld, int kb, int nb) {
    int l = threadIdx.x & 31;
    return smaddr(b + (kb + (l & 7) + (l & 8)) * ld + nb + ((l & 16) >> 1));
}
__device__ __forceinline__ void mmabf(float4& c, uint4 a, uint b0, uint b1) {
    asm volatile(
        "mma.sync.aligned.m16n8k16.row.col.f32.bf16.bf16.f32 "
        "{%0,%1,%2,%3},{%4,%5,%6,%7},{%8,%9},{%0,%1,%2,%3};"
        : "+f"(c.x), "+f"(c.y), "+f"(c.z), "+f"(c.w)
        : "r"(a.x), "r"(a.y), "r"(a.z), "r"(a.w), "r"(b0), "r"(b1));
}
__device__ __forceinline__ uint bfpair(float lo, float hi) {
    uint r; asm("cvt.rn.bf16x2.f32 %0,%1,%2;" : "=r"(r) : "f"(hi), "f"(lo));
    return r;
}
__device__ __forceinline__ uint addb2(uint a, uint b) {
    uint r; asm("add.rn.bf16x2 %0,%1,%2;" : "=r"(r) : "r"(a), "r"(b));
    return r;
}
__device__ __forceinline__ uint2 pack4(float4 v) {
    uint2 r; r.x = bfpair(v.x, v.y); r.y = bfpair(v.z, v.w); return r;
}

// ---------- combo precompute: g_cb[b,i,j] = (cls*(1-tt), cls*tt) ----------
__global__ __launch_bounds__(256)
void cb_kernel(const unsigned char* __restrict__ ttm, const float* __restrict__ clsm) {
    int r = blockIdx.x;                 // b*Sc + i
    int i = r & (Sc - 1);
    int j4 = threadIdx.x * 4;
    float4 cls = *(const float4*)(clsm + (size_t)i * Sc + j4);
    uchar4 tz = *(const uchar4*)(ttm + (size_t)r * Sc + j4);
    uint4 o;
    o.x = tz.x ? bfpair(0.f, cls.x) : bfpair(cls.x, 0.f);
    o.y = tz.y ? bfpair(0.f, cls.y) : bfpair(cls.y, 0.f);
    o.z = tz.z ? bfpair(0.f, cls.z) : bfpair(cls.z, 0.f);
    o.w = tz.w ? bfpair(0.f, cls.w) : bfpair(cls.w, 0.f);
    *(uint4*)(g_cb + (size_t)r * Sc + j4) = o;
}

// ---------- input GEMM core ----------
__device__ __forceinline__ void gemm_core(
    const float* __restrict__ A, const float* __restrict__ W,
    const float* __restrict__ bias, float scale, int sshift, bf* __restrict__ out) {
    __shared__ bf As[128 * 72];
    __shared__ bf Ws[64 * 72];
    int tid = threadIdx.x, l = tid & 31, g = l >> 2, t = l & 3, w = tid >> 5;
    int wm = w & 3, wn = w >> 2;
    int m0 = blockIdx.y * 128, n0 = blockIdx.x * 64;
    int Srows = 1 << sshift;

    float4 c[2][4];
    #pragma unroll
    for (int i = 0; i < 2; i++)
        #pragma unroll
        for (int j = 0; j < 4; j++) c[i][j] = make_float4(0.f, 0.f, 0.f, 0.f);

    for (int k0 = 0; k0 < Dc; k0 += 64) {
        #pragma unroll
        for (int p = 0; p < 8; p++) {
            int cid = tid + p * 256;
            int row = cid >> 4, kq = (cid & 15) << 2;
            float4 v = *(const float4*)(A + (size_t)(m0 + row) * Dc + k0 + kq);
            *(uint2*)(As + row * 72 + kq) = pack4(v);
        }
        #pragma unroll
        for (int p = 0; p < 4; p++) {
            int cid = tid + p * 256;
            int kk = cid >> 4, nq = (cid & 15) << 2;
            float4 v = *(const float4*)(W + (size_t)(k0 + kk) * Dc + n0 + nq);
            *(uint2*)(Ws + kk * 72 + nq) = pack4(v);
        }
        __syncthreads();
        #pragma unroll
        for (int ks = 0; ks < 4; ks++) {
            int kb = ks * 16;
            uint4 a0 = ldsm4(adrA(As, 72, wm * 32, kb));
            uint4 a1 = ldsm4(adrA(As, 72, wm * 32 + 16, kb));
            uint4 b0 = ldsm4t(adrBT(Ws, 72, kb, wn * 32));
            uint4 b1 = ldsm4t(adrBT(Ws, 72, kb, wn * 32 + 16));
            mmabf(c[0][0], a0, b0.x, b0.y); mmabf(c[0][1], a0, b0.z, b0.w);
            mmabf(c[0][2], a0, b1.x, b1.y); mmabf(c[0][3], a0, b1.z, b1.w);
            mmabf(c[1][0], a1, b0.x, b0.y); mmabf(c[1][1], a1, b0.z, b0.w);
            mmabf(c[1][2], a1, b1.x, b1.y); mmabf(c[1][3], a1, b1.z, b1.w);
        }
        __syncthreads();
    }
    #pragma unroll
    for (int mi = 0; mi < 2; mi++) {
        #pragma unroll
        for (int nt = 0; nt < 4; nt++) {
            int col = n0 + wn * 32 + nt * 8 + 2 * t;
            float b0f = bias ? __ldg(bias + col) : 0.f;
            float b1f = bias ? __ldg(bias + col + 1) : 0.f;
            int nn = col >> 6, hh = col & 63;
            #pragma unroll
            for (int r = 0; r < 2; r++) {
                int row = m0 + wm * 32 + mi * 16 + g + r * 8;
                int bb = row >> sshift, ss = row & (Srows - 1);
                float v0 = (r ? c[mi][nt].z : c[mi][nt].x) * scale + b0f;
                float v1 = (r ? c[mi][nt].w : c[mi][nt].y) * scale + b1f;
                *(uint*)(out + (((size_t)bb * Nc + nn) * Srows + ss) * Hc + hh) =
                    bfpair(v0, v1);
            }
        }
    }
}

__global__ __launch_bounds__(256)
void gemm_in(const float* q, const float* k, const float* v, const float* pose,
             const float* Wq, const float* Wk, const float* Wv, const float* rker,
             const float* bk, const float* bv) {
    int z = blockIdx.z;
    if (z == 0)      gemm_core(q, Wq, nullptr, SCALE, 10, g_qh);
    else if (z == 1) gemm_core(k, Wk, bk, 1.f, 10, g_kh);
    else if (z == 2) gemm_core(v, Wv, bv, 1.f, 10, g_vh);
    else if (blockIdx.y < 16) gemm_core(pose, rker, nullptr, 1.f, 11, g_rh);
}

// ---------- output GEMM + residual ----------
__global__ __launch_bounds__(256)
void gemm_out_b(const float* __restrict__ Wo, const float* __restrict__ bo,
                const float* __restrict__ query) {
    __shared__ bf As[128 * 72];
    __shared__ bf Ws[64 * 72];
    int tid = threadIdx.x, l = tid & 31, g = l >> 2, t = l & 3, w = tid >> 5;
    int wm = w & 3, wn = w >> 2;
    int m0 = blockIdx.y * 128, n0 = blockIdx.x * 64;
    float4 c[2][4];
    #pragma unroll
    for (int i = 0; i < 2; i++)
        #pragma unroll
        for (int j = 0; j < 4; j++) c[i][j] = make_float4(0.f, 0.f, 0.f, 0.f);

    for (int k0 = 0; k0 < Dc; k0 += 64) {
        int nn = k0 >> 6;
        #pragma unroll
        for (int p = 0; p < 4; p++) {
            int cid = tid + p * 256;
            int row = cid >> 3, kq = (cid & 7) << 3;
            int rg = m0 + row;
            *(uint4*)(As + row * 72 + kq) = *(const uint4*)(g_av +
                (((size_t)(rg >> 10) * Nc + nn) * Sc + (rg & 1023)) * Hc + kq);
        }
        #pragma unroll
        for (int p = 0; p < 4; p++) {
            int cid = tid + p * 256;
            int kk = cid >> 4, nq = (cid & 15) << 2;
            float4 v = *(const float4*)(Wo + (size_t)(k0 + kk) * Dc + n0 + nq);
            *(uint2*)(Ws + kk * 72 + nq) = pack4(v);
        }
        __syncthreads();
        #pragma unroll
        for (int ks = 0; ks < 4; ks++) {
            int kb = ks * 16;
            uint4 a0 = ldsm4(adrA(As, 72, wm * 32, kb));
            uint4 a1 = ldsm4(adrA(As, 72, wm * 32 + 16, kb));
            uint4 b0 = ldsm4t(adrBT(Ws, 72, kb, wn * 32));
            uint4 b1 = ldsm4t(adrBT(Ws, 72, kb, wn * 32 + 16));
            mmabf(c[0][0], a0, b0.x, b0.y); mmabf(c[0][1], a0, b0.z, b0.w);
            mmabf(c[0][2], a0, b1.x, b1.y); mmabf(c[0][3], a0, b1.z, b1.w);
            mmabf(c[1][0], a1, b0.x, b0.y); mmabf(c[1][1], a1, b0.z, b0.w);
            mmabf(c[1][2], a1, b1.x, b1.y); mmabf(c[1][3], a1, b1.z, b1.w);
        }
        __syncthreads();
    }
    #pragma unroll
    for (int mi = 0; mi < 2; mi++) {
        #pragma unroll
        for (int nt = 0; nt < 4; nt++) {
            int col = n0 + wn * 32 + nt * 8 + 2 * t;
            float b0f = __ldg(bo + col), b1f = __ldg(bo + col + 1);
            #pragma unroll
            for (int r = 0; r < 2; r++) {
                int row = m0 + wm * 32 + mi * 16 + g + r * 8;
                float2 q = *(const float2*)(query + (size_t)row * Dc + col);
                float v0 = (r ? c[mi][nt].z : c[mi][nt].x) + b0f + q.x;
                float v1 = (r ? c[mi][nt].w : c[mi][nt].y) + b1f + q.y;
                *(float2*)(g_x + (size_t)row * Dc + col) = make_float2(v0, v1);
            }
        }
    }
}

// ---------- token-type bias ----------
__global__ __launch_bounds__(256)
void tt_kernel(const float* __restrict__ rsb, const float* __restrict__ seg) {
    int warp = threadIdx.x >> 5, lane = threadIdx.x & 31;
    int row = blockIdx.x * 8 + warp;
    int n = (row / Sc) % Nc;
    const bf* q = &g_qh[(size_t)row * Hc];
    float d = 0.f, s = 0.f;
    #pragma unroll
    for (int p = 0; p < 2; p++) {
        int h = lane + p * 32;
        float qv = __bfloat162float(q[h]) + rsb[n * Hc + h] * SCALE;
        d += qv * seg[(0 * Nc + n) * Hc + h];
        s += qv * seg[(1 * Nc + n) * Hc + h];
    }
    #pragma unroll
    for (int off = 16; off; off >>= 1) {
        d += __shfl_xor_sync(~0u, d, off);
        s += __shfl_xor_sync(~0u, s, off);
    }
    if (lane == 0) { g_tt[(size_t)row*2 + 0] = d; g_tt[(size_t)row*2 + 1] = s; }
}

// ---------- fused attention ----------
#define OQ   0
#define OK_  4608
#define OV   9216
#define OP   13824
#define ORS  18432
#define ORW  27648
#define ORR  27712
#define FOFF 27776
// floats: pww 8*16*56=7168, samk 64, sttd 128, mpart 128, lpart 128 = 7616
// then scb uint[64*68]
#define SMEM_ATTN (27776*2 + 7616*4 + 64*68*4)

extern __shared__ bf smb[];
__global__ __launch_bounds__(256)
void attn_kernel(const float* __restrict__ rwb, const float* __restrict__ rrb,
                 const float* __restrict__ amask_g) {
    bf* sq  = smb + OQ;
    bf* sk  = smb + OK_;
    bf* sv  = smb + OV;
    bf* sp  = smb + OP;
    bf* srs = smb + ORS;
    bf* rwbs = smb + ORW;
    bf* rrbs = smb + ORR;
    float* fb   = (float*)(smb + FOFF);
    float* pww  = fb;
    float* samk = fb + 8*16*56;
    float* sttd = samk + 64;
    float* mpart = sttd + 128;
    float* lpart = mpart + 128;
    uint* scb = (uint*)(lpart + 128);   // [64][68]

    int tid = threadIdx.x, l = tid & 31, g = l >> 2, t = l & 3, w = tid >> 5;
    int mt = w >> 1, nh = w & 1;
    int mtb = mt * 16;
    int i0 = blockIdx.x * 64, n = blockIdx.y, b = blockIdx.z;

    const bf* qbase = g_qh + (((size_t)b*Nc + n)*Sc + i0) * Hc;
    const bf* kbase = g_kh + (((size_t)b*Nc + n)*Sc) * Hc;
    const bf* vbase = g_vh + (((size_t)b*Nc + n)*Sc) * Hc;
    const bf* rbase = g_rh + (size_t)n * Rc * Hc;
    const uint* cbase = g_cb + ((size_t)b * Sc + i0) * Sc;

    #pragma unroll
    for (int p = 0; p < 2; p++) {
        int cid = tid + p * 256;
        int row = cid >> 3, h8 = (cid & 7) << 3;
        *(uint4*)(sq + row * 72 + h8) = *(const uint4*)(qbase + row * Hc + h8);
    }
    if (tid < 64) {
        rwbs[tid] = __float2bfloat16(rwb[n * Hc + tid] * SCALE);
        rrbs[tid] = __float2bfloat16(rrb[n * Hc + tid] * SCALE);
    }
    if (tid < 128) sttd[tid] = g_tt[(((size_t)b*Nc + n)*Sc + i0)*2 + tid];

    float4 of[4];
    #pragma unroll
    for (int nt = 0; nt < 4; nt++) of[nt] = make_float4(0.f, 0.f, 0.f, 0.f);
    float m0r = -3.0e38f, m1r = -3.0e38f, l0r = 0.f, l1r = 0.f;

    int vmin = nh * 32 - mtb + 48;
    int u0 = mtb + g, u1 = u0 + 8;
    float* pw = pww + w * (16 * 56);

    for (int j0 = 0; j0 < Sc; j0 += 64) {
        __syncthreads();   // A
        #pragma unroll
        for (int p = 0; p < 2; p++) {
            int cid = tid + p * 256;
            int row = cid >> 3, h8 = (cid & 7) << 3;
            *(uint4*)(sk + row * 72 + h8) =
                *(const uint4*)(kbase + (size_t)(j0 + row) * Hc + h8);
            *(uint4*)(sv + row * 72 + h8) =
                *(const uint4*)(vbase + (size_t)(j0 + row) * Hc + h8);
        }
        int t_base = Sc - i0 - 63 + j0;
        #pragma unroll
        for (int p = 0; p < 4; p++) {
            int cid = tid + p * 256;
            int row = cid >> 3, h8 = (cid & 7) << 3;
            int tt = t_base + row;
            uint4 vv = make_uint4(0u, 0u, 0u, 0u);
            if (tt >= 0 && tt < Rc)
                vv = *(const uint4*)(rbase + (size_t)tt * Hc + h8);
            *(uint4*)(srs + row * 72 + h8) = vv;
        }
        // combo tile: 64 rows x 64 uints, coalesced
        #pragma unroll
        for (int p = 0; p < 4; p++) {
            int cid = tid + p * 256;
            int row = cid >> 4, c4 = (cid & 15) << 2;
            *(uint4*)(scb + row * 68 + c4) =
                *(const uint4*)(cbase + (size_t)row * Sc + j0 + c4);
        }
        if (tid < 64) samk[tid] = amask_g[b * Sc + j0 + tid];
        __syncthreads();   // B

        float4 sc[4], pf[6];
        #pragma unroll
        for (int q_ = 0; q_ < 4; q_++) sc[q_] = make_float4(0.f, 0.f, 0.f, 0.f);
        #pragma unroll
        for (int q_ = 0; q_ < 6; q_++) pf[q_] = make_float4(0.f, 0.f, 0.f, 0.f);
        #pragma unroll
        for (int ks = 0; ks < 4; ks++) {
            int kb = ks * 16;
            uint4 qa = ldsm4(adrA(sq, 72, mtb, kb));
            uint rw0 = *(const uint*)(rwbs + kb + 2 * t);
            uint rw1 = *(const uint*)(rwbs + kb + 2 * t + 8);
            uint rr0 = *(const uint*)(rrbs + kb + 2 * t);
            uint rr1 = *(const uint*)(rrbs + kb + 2 * t + 8);
            uint4 aw, ar;
            aw.x = addb2(qa.x, rw0); aw.y = addb2(qa.y, rw0);
            aw.z = addb2(qa.z, rw1); aw.w = addb2(qa.w, rw1);
            ar.x = addb2(qa.x, rr0); ar.y = addb2(qa.y, rr0);
            ar.z = addb2(qa.z, rr1); ar.w = addb2(qa.w, rr1);
            uint4 bk0 = ldsm4(adrB(sk, 72, nh * 32, kb));
            uint4 bk1 = ldsm4(adrB(sk, 72, nh * 32 + 16, kb));
            mmabf(sc[0], aw, bk0.x, bk0.y); mmabf(sc[1], aw, bk0.z, bk0.w);
            mmabf(sc[2], aw, bk1.x, bk1.y); mmabf(sc[3], aw, bk1.z, bk1.w);
            uint4 br0 = ldsm4(adrB(srs, 72, vmin, kb));
            uint4 br1 = ldsm4(adrB(srs, 72, vmin + 16, kb));
            uint4 br2 = ldsm4(adrB(srs, 72, vmin + 32, kb));
            mmabf(pf[0], ar, br0.x, br0.y); mmabf(pf[1], ar, br0.z, br0.w);
            mmabf(pf[2], ar, br1.x, br1.y); mmabf(pf[3], ar, br1.z, br1.w);
            mmabf(pf[4], ar, br2.x, br2.y); mmabf(pf[5], ar, br2.z, br2.w);
        }
        #pragma unroll
        for (int q_ = 0; q_ < 6; q_++) {
            *(float2*)(pw + g * 56 + q_ * 8 + 2 * t)       = make_float2(pf[q_].x, pf[q_].y);
            *(float2*)(pw + (g + 8) * 56 + q_ * 8 + 2 * t) = make_float2(pf[q_].z, pf[q_].w);
        }
        __syncwarp();

        float td0 = sttd[2*u0], ts0 = sttd[2*u0+1];
        float td1 = sttd[2*u1], ts1 = sttd[2*u1+1];
        float mr0 = -3.0e38f, mr1 = -3.0e38f;
        #pragma unroll
        for (int nt = 0; nt < 4; nt++) {
            int jl = nh * 32 + nt * 8 + 2 * t;
            float mk0 = INFV * (1.f - samk[jl]);
            float mk1 = INFV * (1.f - samk[jl + 1]);
            uint2 cb0 = *(const uint2*)(scb + u0 * 68 + jl);
            uint2 cb1 = *(const uint2*)(scb + u1 * 68 + jl);
            float2 eA = __bfloat1622float2(*(__nv_bfloat162*)&cb0.x);
            float2 eB = __bfloat1622float2(*(__nv_bfloat162*)&cb0.y);
            float2 eC = __bfloat1622float2(*(__nv_bfloat162*)&cb1.x);
            float2 eD = __bfloat1622float2(*(__nv_bfloat162*)&cb1.y);
            int vc0 = nt * 8 + 2 * t - g + 15;
            int vc1 = vc0 - 8;
            float p00 = pw[g * 56 + vc0],       p01 = pw[g * 56 + vc0 + 1];
            float p10 = pw[(g + 8) * 56 + vc1], p11 = pw[(g + 8) * 56 + vc1 + 1];
            sc[nt].x += (eA.x + eA.y) * p00 + eA.x * td0 + eA.y * ts0 - mk0;
            sc[nt].y += (eB.x + eB.y) * p01 + eB.x * td0 + eB.y * ts0 - mk1;
            sc[nt].z += (eC.x + eC.y) * p10 + eC.x * td1 + eC.y * ts1 - mk0;
            sc[nt].w += (eD.x + eD.y) * p11 + eD.x * td1 + eD.y * ts1 - mk1;
            mr0 = fmaxf(mr0, fmaxf(sc[nt].x, sc[nt].y));
            mr1 = fmaxf(mr1, fmaxf(sc[nt].z, sc[nt].w));
        }
        mr0 = fmaxf(mr0, __shfl_xor_sync(~0u, mr0, 1));
        mr0 = fmaxf(mr0, __shfl_xor_sync(~0u, mr0, 2));
        mr1 = fmaxf(mr1, __shfl_xor_sync(~0u, mr1, 1));
        mr1 = fmaxf(mr1, __shfl_xor_sync(~0u, mr1, 2));
        float ls0 = 0.f, ls1 = 0.f;
        #pragma unroll
        for (int nt = 0; nt < 4; nt++) {
            sc[nt].x = __expf(sc[nt].x - mr0); sc[nt].y = __expf(sc[nt].y - mr0);
            sc[nt].z = __expf(sc[nt].z - mr1); sc[nt].w = __expf(sc[nt].w - mr1);
            ls0 += sc[nt].x + sc[nt].y; ls1 += sc[nt].z + sc[nt].w;
        }
        ls0 += __shfl_xor_sync(~0u, ls0, 1); ls0 += __shfl_xor_sync(~0u, ls0, 2);
        ls1 += __shfl_xor_sync(~0u, ls1, 1); ls1 += __shfl_xor_sync(~0u, ls1, 2);
        if (t == 0) {
            mpart[nh * 64 + u0] = mr0; mpart[nh * 64 + u1] = mr1;
            lpart[nh * 64 + u0] = ls0; lpart[nh * 64 + u1] = ls1;
        }
        __syncthreads();   // C

        float a0m = mpart[u0], b0m = mpart[64 + u0];
        float a1m = mpart[u1], b1m = mpart[64 + u1];
        float mn0 = fmaxf(m0r, fmaxf(a0m, b0m));
        float mn1 = fmaxf(m1r, fmaxf(a1m, b1m));
        float co0 = __expf(m0r - mn0), co1 = __expf(m1r - mn1);
        l0r = l0r * co0 + lpart[u0] * __expf(a0m - mn0) + lpart[64 + u0] * __expf(b0m - mn0);
        l1r = l1r * co1 + lpart[u1] * __expf(a1m - mn1) + lpart[64 + u1] * __expf(b1m - mn1);
        m0r = mn0; m1r = mn1;
        float f0 = __expf((nh ? b0m : a0m) - mn0);
        float f1 = __expf((nh ? b1m : a1m) - mn1);
        #pragma unroll
        for (int nt = 0; nt < 4; nt++) {
            int jl = nh * 32 + nt * 8 + 2 * t;
            *(uint*)(sp + u0 * 72 + jl) = bfpair(sc[nt].x * f0, sc[nt].y * f0);
            *(uint*)(sp + u1 * 72 + jl) = bfpair(sc[nt].z * f1, sc[nt].w * f1);
        }
        #pragma unroll
        for (int nt = 0; nt < 4; nt++) {
            of[nt].x *= co0; of[nt].y *= co0;
            of[nt].z *= co1; of[nt].w *= co1;
        }
        __syncthreads();   // D

        #pragma unroll
        for (int ks = 0; ks < 4; ks++) {
            int kb = ks * 16;
            uint4 ap = ldsm4(adrA(sp, 72, mtb, kb));
            uint4 v0 = ldsm4t(adrBT(sv, 72, kb, nh * 32));
            uint4 v1 = ldsm4t(adrBT(sv, 72, kb, nh * 32 + 16));
            mmabf(of[0], ap, v0.x, v0.y); mmabf(of[1], ap, v0.z, v0.w);
            mmabf(of[2], ap, v1.x, v1.y); mmabf(of[3], ap, v1.z, v1.w);
        }
    }

    float inv0 = 1.f / l0r, inv1 = 1.f / l1r;
    bf* outb = g_av + (((size_t)b*Nc + n)*Sc + i0) * Hc;
    #pragma unroll
    for (int nt = 0; nt < 4; nt++) {
        int h = nh * 32 + nt * 8 + 2 * t;
        *(uint*)(outb + (size_t)u0 * Hc + h) = bfpair(of[nt].x * inv0, of[nt].y * inv0);
        *(uint*)(outb + (size_t)u1 * Hc + h) = bfpair(of[nt].z * inv1, of[nt].w * inv1);
    }
}

// ---------- LayerNorm ----------
__global__ __launch_bounds__(256)
void ln_kernel(const float* __restrict__ lng, const float* __restrict__ lnb,
               float* __restrict__ out) {
    __shared__ float red[8];
    __shared__ float stat;
    int row = blockIdx.x;
    const float* x = &g_x[(size_t)row * Dc];
    int t = threadIdx.x;
    float v[3];
    float s = 0.f;
    #pragma unroll
    for (int p = 0; p < 3; p++) { v[p] = x[t + p*256]; s += v[p]; }
    #pragma unroll
    for (int off = 16; off; off >>= 1) s += __shfl_xor_sync(~0u, s, off);
    if ((t & 31) == 0) red[t >> 5] = s;
    __syncthreads();
    if (t < 32) {
        float r = (t < 8) ? red[t] : 0.f;
        #pragma unroll
        for (int off = 4; off; off >>= 1) r += __shfl_xor_sync(~0u, r, off);
        if (t == 0) stat = r * (1.f / Dc);
    }
    __syncthreads();
    float mu = stat;
    float s2 = 0.f;
    #pragma unroll
    for (int p = 0; p < 3; p++) { float d = v[p] - mu; s2 += d*d; }
    #pragma unroll
    for (int off = 16; off; off >>= 1) s2 += __shfl_xor_sync(~0u, s2, off);
    if ((t & 31) == 0) red[t >> 5] = s2;
    __syncthreads();
    if (t < 32) {
        float r = (t < 8) ? red[t] : 0.f;
        #pragma unroll
        for (int off = 4; off; off >>= 1) r += __shfl_xor_sync(~0u, r, off);
        if (t == 0) stat = rsqrtf(r * (1.f / Dc) + EPSV);
    }
    __syncthreads();
    float rstd = stat;
    #pragma unroll
    for (int p = 0; p < 3; p++) {
        int i = t + p*256;
        out[(size_t)row*Dc + i] = (v[p] - mu) * rstd * lng[i] + lnb[i];
    }
}

// ---------- launch ----------
extern "C" void kernel_launch(void* const* d_in, const int* in_sizes, int n_in,
                              void* d_out, int out_size) {
    const float* query = (const float*)d_in[0];
    const float* key   = (const float*)d_in[1];
    const float* value = (const float*)d_in[2];
    const float* pose  = (const float*)d_in[3];
    const unsigned char* ttm = (const unsigned char*)d_in[4];
    const float* amask = (const float*)d_in[5];
    const float* clsm  = (const float*)d_in[6];
    const float* Wq    = (const float*)d_in[7];
    const float* Wk    = (const float*)d_in[8];
    const float* bk    = (const float*)d_in[9];
    const float* Wv    = (const float*)d_in[10];
    const float* bv    = (const float*)d_in[11];
    const float* rwb   = (const float*)d_in[12];
    const float* rrb   = (const float*)d_in[13];
    const float* rker  = (const float*)d_in[14];
    const float* rsb   = (const float*)d_in[15];
    const float* seg   = (const float*)d_in[16];
    const float* Wo    = (const float*)d_in[17];
    const float* bo    = (const float*)d_in[18];
    const float* lng   = (const float*)d_in[19];
    const float* lnb   = (const float*)d_in[20];
    float* out = (float*)d_out;

    dim3 blk(256);
    cb_kernel<<<Bc*Sc, blk>>>(ttm, clsm);
    gemm_in<<<dim3(12, 32, 4), blk>>>(query, key, value, pose,
                                      Wq, Wk, Wv, rker, bk, bv);
    tt_kernel<<<Bc*Nc*Sc/8, blk>>>(rsb, seg);

    cudaFuncSetAttribute(attn_kernel, cudaFuncAttributeMaxDynamicSharedMemorySize,
                         SMEM_ATTN);
    attn_kernel<<<dim3(Sc/64, Nc, Bc), blk, SMEM_ATTN>>>(rwb, rrb, amask);

    gemm_out_b<<<dim3(12, 32), blk>>>(Wo, bo, query);
    ln_kernel<<<Bc*Sc, blk>>>(lng, lnb, out);
}

// round 7
// speedup vs baseline: 2.0599x; 1.1146x over previous
#include <cuda_runtime.h>
#include <cuda_bf16.h>
#include <math.h>

#define Bc 4
#define Sc 1024
#define Dc 768
#define Nc 12
#define Hc 64
#define Rc 2048
#define SCALE 0.125f
#define INFV 1000000.0f
#define EPSV 1e-9f

typedef unsigned int uint;
typedef __nv_bfloat16 bf;

__device__ __align__(16) bf    g_qh[Bc*Nc*Sc*Hc];
__device__ __align__(16) bf    g_kh[Bc*Nc*Sc*Hc];
__device__ __align__(16) bf    g_vh[Bc*Nc*Sc*Hc];
__device__ __align__(16) bf    g_rh[Nc*Rc*Hc];
__device__ float g_tt[Bc*Nc*Sc*2];
__device__ __align__(16) bf    g_av[Bc*Nc*Sc*Hc];
__device__ float g_x [Bc*Sc*Dc];
__device__ __align__(16) bf    g_cls[Sc*Sc];       // cls_mask bf16 [i][j]
__device__ __align__(16) uint  g_ttb[Bc*Sc*32];    // tt bits, 32 uints per (b,i)
__device__ __align__(16) float g_mk [Bc*Sc];       // INFV*(1-amask)

// ---------- helpers ----------
__device__ __forceinline__ uint smaddr(const void* p) {
    return (uint)__cvta_generic_to_shared(p);
}
__device__ __forceinline__ void cpa16(uint sa, const void* g) {
    asm volatile("cp.async.cg.shared.global [%0], [%1], 16;"
        :: "r"(sa), "l"(__cvta_generic_to_global(g)));
}
__device__ __forceinline__ void cpa16z(uint sa, const void* g, int sz) {
    asm volatile("cp.async.cg.shared.global [%0], [%1], 16, %2;"
        :: "r"(sa), "l"(__cvta_generic_to_global(g)), "r"(sz));
}
__device__ __forceinline__ void cpa8(uint sa, const void* g) {
    asm volatile("cp.async.ca.shared.global [%0], [%1], 8;"
        :: "r"(sa), "l"(__cvta_generic_to_global(g)));
}
__device__ __forceinline__ void cpcommit() {
    asm volatile("cp.async.commit_group;" ::: "memory");
}
__device__ __forceinline__ void cpwait1() {
    asm volatile("cp.async.wait_group 1;" ::: "memory");
}
__device__ __forceinline__ uint4 ldsm4(uint a) {
    uint4 r;
    asm volatile("ldmatrix.sync.aligned.m8n8.x4.shared.b16 {%0,%1,%2,%3},[%4];"
        : "=r"(r.x), "=r"(r.y), "=r"(r.z), "=r"(r.w) : "r"(a));
    return r;
}
__device__ __forceinline__ uint4 ldsm4t(uint a) {
    uint4 r;
    asm volatile("ldmatrix.sync.aligned.m8n8.x4.trans.shared.b16 {%0,%1,%2,%3},[%4];"
        : "=r"(r.x), "=r"(r.y), "=r"(r.z), "=r"(r.w) : "r"(a));
    return r;
}
__device__ __forceinline__ uint adrA(const bf* b, int ld, int row0, int kb) {
    int l = threadIdx.x & 31;
    return smaddr(b + (row0 + (l & 15)) * ld + kb + ((l >> 4) << 3));
}
__device__ __forceinline__ uint adrB(const bf* b, int ld, int nb, int kb) {
    int l = threadIdx.x & 31;
    return smaddr(b + (nb + (l & 7) + ((l & 16) >> 1)) * ld + kb + (l & 8));
}
__device__ __forceinline__ uint adrBT(const bf* b, int ld, int kb, int nb) {
    int l = threadIdx.x & 31;
    return smaddr(b + (kb + (l & 7) + (l & 8)) * ld + nb + ((l & 16) >> 1));
}
__device__ __forceinline__ void mmabf(float4& c, uint4 a, uint b0, uint b1) {
    asm volatile(
        "mma.sync.aligned.m16n8k16.row.col.f32.bf16.bf16.f32 "
        "{%0,%1,%2,%3},{%4,%5,%6,%7},{%8,%9},{%0,%1,%2,%3};"
        : "+f"(c.x), "+f"(c.y), "+f"(c.z), "+f"(c.w)
        : "r"(a.x), "r"(a.y), "r"(a.z), "r"(a.w), "r"(b0), "r"(b1));
}
__device__ __forceinline__ uint bfpair(float lo, float hi) {
    uint r; asm("cvt.rn.bf16x2.f32 %0,%1,%2;" : "=r"(r) : "f"(hi), "f"(lo));
    return r;
}
__device__ __forceinline__ uint addb2(uint a, uint b) {
    uint r; asm("add.rn.bf16x2 %0,%1,%2;" : "=r"(r) : "r"(a), "r"(b));
    return r;
}
__device__ __forceinline__ uint2 pack4(float4 v) {
    uint2 r; r.x = bfpair(v.x, v.y); r.y = bfpair(v.z, v.w); return r;
}

// ---------- precompute: cls bf16, tt bit-pack, mask ----------
__global__ __launch_bounds__(256)
void cb_kernel(const unsigned char* __restrict__ ttm,
               const float* __restrict__ clsm,
               const float* __restrict__ amask) {
    int r = blockIdx.x;                  // b*Sc + i
    int tid = threadIdx.x, w = tid >> 5, lane = tid & 31;
    #pragma unroll
    for (int c = 0; c < 4; c++) {
        int j = w * 128 + c * 32 + lane;
        uint m = __ballot_sync(~0u, ttm[(size_t)r * Sc + j] != 0);
        if (lane == 0) g_ttb[r * 32 + w * 4 + c] = m;
    }
    if (r < Sc) {
        int j4 = tid * 4;
        float4 c4 = *(const float4*)(clsm + (size_t)r * Sc + j4);
        *(uint2*)(g_cls + (size_t)r * Sc + j4) = pack4(c4);
    }
    if (r < 16) {
        int idx = r * 256 + tid;
        g_mk[idx] = INFV * (1.f - amask[idx]);
    }
}

// ---------- input GEMM core ----------
__device__ __forceinline__ void gemm_core(
    const float* __restrict__ A, const float* __restrict__ W,
    const float* __restrict__ bias, float scale, int sshift, bf* __restrict__ out) {
    __shared__ bf As[128 * 72];
    __shared__ bf Ws[64 * 72];
    int tid = threadIdx.x, l = tid & 31, g = l >> 2, t = l & 3, w = tid >> 5;
    int wm = w & 3, wn = w >> 2;
    int m0 = blockIdx.y * 128, n0 = blockIdx.x * 64;
    int Srows = 1 << sshift;
    float4 c[2][4];
    #pragma unroll
    for (int i = 0; i < 2; i++)
        #pragma unroll
        for (int j = 0; j < 4; j++) c[i][j] = make_float4(0.f, 0.f, 0.f, 0.f);

    for (int k0 = 0; k0 < Dc; k0 += 64) {
        #pragma unroll
        for (int p = 0; p < 8; p++) {
            int cid = tid + p * 256;
            int row = cid >> 4, kq = (cid & 15) << 2;
            float4 v = *(const float4*)(A + (size_t)(m0 + row) * Dc + k0 + kq);
            *(uint2*)(As + row * 72 + kq) = pack4(v);
        }
        #pragma unroll
        for (int p = 0; p < 4; p++) {
            int cid = tid + p * 256;
            int kk = cid >> 4, nq = (cid & 15) << 2;
            float4 v = *(const float4*)(W + (size_t)(k0 + kk) * Dc + n0 + nq);
            *(uint2*)(Ws + kk * 72 + nq) = pack4(v);
        }
        __syncthreads();
        #pragma unroll
        for (int ks = 0; ks < 4; ks++) {
            int kb = ks * 16;
            uint4 a0 = ldsm4(adrA(As, 72, wm * 32, kb));
            uint4 a1 = ldsm4(adrA(As, 72, wm * 32 + 16, kb));
            uint4 b0 = ldsm4t(adrBT(Ws, 72, kb, wn * 32));
            uint4 b1 = ldsm4t(adrBT(Ws, 72, kb, wn * 32 + 16));
            mmabf(c[0][0], a0, b0.x, b0.y); mmabf(c[0][1], a0, b0.z, b0.w);
            mmabf(c[0][2], a0, b1.x, b1.y); mmabf(c[0][3], a0, b1.z, b1.w);
            mmabf(c[1][0], a1, b0.x, b0.y); mmabf(c[1][1], a1, b0.z, b0.w);
            mmabf(c[1][2], a1, b1.x, b1.y); mmabf(c[1][3], a1, b1.z, b1.w);
        }
        __syncthreads();
    }
    #pragma unroll
    for (int mi = 0; mi < 2; mi++) {
        #pragma unroll
        for (int nt = 0; nt < 4; nt++) {
            int col = n0 + wn * 32 + nt * 8 + 2 * t;
            float b0f = bias ? __ldg(bias + col) : 0.f;
            float b1f = bias ? __ldg(bias + col + 1) : 0.f;
            int nn = col >> 6, hh = col & 63;
            #pragma unroll
            for (int r = 0; r < 2; r++) {
                int row = m0 + wm * 32 + mi * 16 + g + r * 8;
                int bb = row >> sshift, ss = row & (Srows - 1);
                float v0 = (r ? c[mi][nt].z : c[mi][nt].x) * scale + b0f;
                float v1 = (r ? c[mi][nt].w : c[mi][nt].y) * scale + b1f;
                *(uint*)(out + (((size_t)bb * Nc + nn) * Srows + ss) * Hc + hh) =
                    bfpair(v0, v1);
            }
        }
    }
}

__global__ __launch_bounds__(256)
void gemm_in(const float* q, const float* k, const float* v, const float* pose,
             const float* Wq, const float* Wk, const float* Wv, const float* rker,
             const float* bk, const float* bv) {
    int z = blockIdx.z;
    if (z == 0)      gemm_core(q, Wq, nullptr, SCALE, 10, g_qh);
    else if (z == 1) gemm_core(k, Wk, bk, 1.f, 10, g_kh);
    else if (z == 2) gemm_core(v, Wv, bv, 1.f, 10, g_vh);
    else if (blockIdx.y < 16) gemm_core(pose, rker, nullptr, 1.f, 11, g_rh);
}

// ---------- output GEMM + residual ----------
__global__ __launch_bounds__(256)
void gemm_out_b(const float* __restrict__ Wo, const float* __restrict__ bo,
                const float* __restrict__ query) {
    __shared__ bf As[128 * 72];
    __shared__ bf Ws[64 * 72];
    int tid = threadIdx.x, l = tid & 31, g = l >> 2, t = l & 3, w = tid >> 5;
    int wm = w & 3, wn = w >> 2;
    int m0 = blockIdx.y * 128, n0 = blockIdx.x * 64;
    float4 c[2][4];
    #pragma unroll
    for (int i = 0; i < 2; i++)
        #pragma unroll
        for (int j = 0; j < 4; j++) c[i][j] = make_float4(0.f, 0.f, 0.f, 0.f);

    for (int k0 = 0; k0 < Dc; k0 += 64) {
        int nn = k0 >> 6;
        #pragma unroll
        for (int p = 0; p < 4; p++) {
            int cid = tid + p * 256;
            int row = cid >> 3, kq = (cid & 7) << 3;
            int rg = m0 + row;
            *(uint4*)(As + row * 72 + kq) = *(const uint4*)(g_av +
                (((size_t)(rg >> 10) * Nc + nn) * Sc + (rg & 1023)) * Hc + kq);
        }
        #pragma unroll
        for (int p = 0; p < 4; p++) {
            int cid = tid + p * 256;
            int kk = cid >> 4, nq = (cid & 15) << 2;
            float4 v = *(const float4*)(Wo + (size_t)(k0 + kk) * Dc + n0 + nq);
            *(uint2*)(Ws + kk * 72 + nq) = pack4(v);
        }
        __syncthreads();
        #pragma unroll
        for (int ks = 0; ks < 4; ks++) {
            int kb = ks * 16;
            uint4 a0 = ldsm4(adrA(As, 72, wm * 32, kb));
            uint4 a1 = ldsm4(adrA(As, 72, wm * 32 + 16, kb));
            uint4 b0 = ldsm4t(adrBT(Ws, 72, kb, wn * 32));
            uint4 b1 = ldsm4t(adrBT(Ws, 72, kb, wn * 32 + 16));
            mmabf(c[0][0], a0, b0.x, b0.y); mmabf(c[0][1], a0, b0.z, b0.w);
            mmabf(c[0][2], a0, b1.x, b1.y); mmabf(c[0][3], a0, b1.z, b1.w);
            mmabf(c[1][0], a1, b0.x, b0.y); mmabf(c[1][1], a1, b0.z, b0.w);
            mmabf(c[1][2], a1, b1.x, b1.y); mmabf(c[1][3], a1, b1.z, b1.w);
        }
        __syncthreads();
    }
    #pragma unroll
    for (int mi = 0; mi < 2; mi++) {
        #pragma unroll
        for (int nt = 0; nt < 4; nt++) {
            int col = n0 + wn * 32 + nt * 8 + 2 * t;
            float b0f = __ldg(bo + col), b1f = __ldg(bo + col + 1);
            #pragma unroll
            for (int r = 0; r < 2; r++) {
                int row = m0 + wm * 32 + mi * 16 + g + r * 8;
                float2 q = *(const float2*)(query + (size_t)row * Dc + col);
                float v0 = (r ? c[mi][nt].z : c[mi][nt].x) + b0f + q.x;
                float v1 = (r ? c[mi][nt].w : c[mi][nt].y) + b1f + q.y;
                *(float2*)(g_x + (size_t)row * Dc + col) = make_float2(v0, v1);
            }
        }
    }
}

// ---------- token-type bias ----------
__global__ __launch_bounds__(256)
void tt_kernel(const float* __restrict__ rsb, const float* __restrict__ seg) {
    int warp = threadIdx.x >> 5, lane = threadIdx.x & 31;
    int row = blockIdx.x * 8 + warp;
    int n = (row / Sc) % Nc;
    const bf* q = &g_qh[(size_t)row * Hc];
    float d = 0.f, s = 0.f;
    #pragma unroll
    for (int p = 0; p < 2; p++) {
        int h = lane + p * 32;
        float qv = __bfloat162float(q[h]) + rsb[n * Hc + h] * SCALE;
        d += qv * seg[(0 * Nc + n) * Hc + h];
        s += qv * seg[(1 * Nc + n) * Hc + h];
    }
    #pragma unroll
    for (int off = 16; off; off >>= 1) {
        d += __shfl_xor_sync(~0u, d, off);
        s += __shfl_xor_sync(~0u, s, off);
    }
    if (lane == 0) { g_tt[(size_t)row*2 + 0] = d; g_tt[(size_t)row*2 + 1] = s; }
}

// ---------- fused attention: cp.async pipelined ----------
#define OQ    0
#define OK0   4608
#define OK1   9216
#define OV    13824
#define OP    18432
#define ORS0  23040
#define ORS1  32256
#define OCLS  41472
#define OPW   46080
#define ORW   53248
#define ORR   53312
#define FOFF  53376
#define SMEM_ATTN (53376*2 + (128 + 64 + 128 + 128 + 128)*4)   // 109056

extern __shared__ bf smb[];
__global__ __launch_bounds__(256)
void attn_kernel(const float* __restrict__ rwb, const float* __restrict__ rrb) {
    bf* sq   = smb + OQ;
    bf* sv   = smb + OV;
    bf* sp   = smb + OP;
    bf* scls = smb + OCLS;
    bf* rwbs = smb + ORW;
    bf* rrbs = smb + ORR;
    uint*  sttb = (uint*)(smb + FOFF);       // 128 uints
    float* samk = (float*)(sttb + 128);      // 64
    float* sttd = samk + 64;                 // 128
    float* mpart = sttd + 128;               // 128
    float* lpart = mpart + 128;              // 128

    int tid = threadIdx.x, l = tid & 31, g = l >> 2, t = l & 3, w = tid >> 5;
    int mt = w >> 1, nh = w & 1;
    int mtb = mt * 16;
    int i0 = blockIdx.x * 64, n = blockIdx.y, b = blockIdx.z;

    const bf* qbase = g_qh + (((size_t)b*Nc + n)*Sc + i0) * Hc;
    const bf* kbase = g_kh + (((size_t)b*Nc + n)*Sc) * Hc;
    const bf* vbase = g_vh + (((size_t)b*Nc + n)*Sc) * Hc;
    const bf* rbase = g_rh + (size_t)n * Rc * Hc;

    // prologue: q + first K/rs tile (group A_0)
    #pragma unroll
    for (int p = 0; p < 2; p++) {
        int cid = tid + p * 256;
        int row = cid >> 3, c16 = cid & 7;
        cpa16(smaddr(sq + row * 72) + c16 * 16, qbase + (size_t)row * Hc + c16 * 8);
        cpa16(smaddr(smb + OK0 + row * 72) + c16 * 16,
              kbase + (size_t)row * Hc + c16 * 8);
    }
    {
        int tb_ = Sc - i0 - 63;
        #pragma unroll
        for (int p = 0; p < 4; p++) {
            int cid = tid + p * 256;
            int row = cid >> 3, c16 = cid & 7;
            int tt2 = tb_ + row;
            int sz = ((unsigned)tt2 < Rc) ? 16 : 0;
            cpa16z(smaddr(smb + ORS0 + row * 72) + c16 * 16,
                   rbase + (size_t)(tt2 & 2047) * Hc + c16 * 8, sz);
        }
    }
    cpcommit();
    if (tid < 64) {
        rwbs[tid] = __float2bfloat16(rwb[n * Hc + tid] * SCALE);
        rrbs[tid] = __float2bfloat16(rrb[n * Hc + tid] * SCALE);
    }
    if (tid < 128) sttd[tid] = g_tt[(((size_t)b*Nc + n)*Sc + i0)*2 + tid];

    float4 of[4];
    #pragma unroll
    for (int nt = 0; nt < 4; nt++) of[nt] = make_float4(0.f, 0.f, 0.f, 0.f);
    float m0r = -3.0e38f, m1r = -3.0e38f, l0r = 0.f, l1r = 0.f;

    int vmin = nh * 32 - mtb + 48;
    int u0 = mtb + g, u1 = u0 + 8;
    bf* pwb = smb + OPW + w * (16 * 56);

    for (int t16 = 0; t16 < 16; t16++) {
        int j0 = t16 * 64;
        int p = t16 & 1;
        bf* skp  = smb + (p ? OK1 : OK0);
        bf* srsp = smb + (p ? ORS1 : ORS0);

        __syncthreads();   // (1) single-buffer consumers of prev iter done
        // group B_t: V, cls, ttb, mask
        #pragma unroll
        for (int q_ = 0; q_ < 2; q_++) {
            int cid = tid + q_ * 256;
            int row = cid >> 3, c16 = cid & 7;
            cpa16(smaddr(sv + row * 72) + c16 * 16,
                  vbase + (size_t)(j0 + row) * Hc + c16 * 8);
            cpa16(smaddr(scls + row * 72) + c16 * 16,
                  g_cls + (size_t)(i0 + row) * Sc + j0 + c16 * 8);
        }
        if (tid < 64)
            cpa8(smaddr(sttb) + tid * 8,
                 g_ttb + ((size_t)(b * Sc + i0 + tid) * 32 + (j0 >> 5)));
        if (tid < 16)
            cpa16(smaddr(samk) + tid * 16, g_mk + b * Sc + j0 + tid * 4);
        cpcommit();

        cpwait1();          // A_t done
        __syncthreads();    // (3)

        // prefetch A_{t+1}
        {
            int j0n = j0 + 64;
            if (j0n < Sc) {
                bf* dK = smb + (p ? OK0 : OK1);
                bf* dR = smb + (p ? ORS0 : ORS1);
                #pragma unroll
                for (int q_ = 0; q_ < 2; q_++) {
                    int cid = tid + q_ * 256;
                    int row = cid >> 3, c16 = cid & 7;
                    cpa16(smaddr(dK + row * 72) + c16 * 16,
                          kbase + (size_t)(j0n + row) * Hc + c16 * 8);
                }
                int tb_ = Sc - i0 - 63 + j0n;
                #pragma unroll
                for (int q_ = 0; q_ < 4; q_++) {
                    int cid = tid + q_ * 256;
                    int row = cid >> 3, c16 = cid & 7;
                    int tt2 = tb_ + row;
                    int sz = ((unsigned)tt2 < Rc) ? 16 : 0;
                    cpa16z(smaddr(dR + row * 72) + c16 * 16,
                           rbase + (size_t)(tt2 & 2047) * Hc + c16 * 8, sz);
                }
            }
            cpcommit();
        }

        // ---- content + pos mma ----
        float4 sc[4], pf[6];
        #pragma unroll
        for (int q_ = 0; q_ < 4; q_++) sc[q_] = make_float4(0.f, 0.f, 0.f, 0.f);
        #pragma unroll
        for (int q_ = 0; q_ < 6; q_++) pf[q_] = make_float4(0.f, 0.f, 0.f, 0.f);
        #pragma unroll
        for (int ks = 0; ks < 4; ks++) {
            int kb = ks * 16;
            uint4 qa = ldsm4(adrA(sq, 72, mtb, kb));
            uint rw0 = *(const uint*)(rwbs + kb + 2 * t);
            uint rw1 = *(const uint*)(rwbs + kb + 2 * t + 8);
            uint rr0 = *(const uint*)(rrbs + kb + 2 * t);
            uint rr1 = *(const uint*)(rrbs + kb + 2 * t + 8);
            uint4 aw, ar;
            aw.x = addb2(qa.x, rw0); aw.y = addb2(qa.y, rw0);
            aw.z = addb2(qa.z, rw1); aw.w = addb2(qa.w, rw1);
            ar.x = addb2(qa.x, rr0); ar.y = addb2(qa.y, rr0);
            ar.z = addb2(qa.z, rr1); ar.w = addb2(qa.w, rr1);
            uint4 bk0 = ldsm4(adrB(skp, 72, nh * 32, kb));
            uint4 bk1 = ldsm4(adrB(skp, 72, nh * 32 + 16, kb));
            mmabf(sc[0], aw, bk0.x, bk0.y); mmabf(sc[1], aw, bk0.z, bk0.w);
            mmabf(sc[2], aw, bk1.x, bk1.y); mmabf(sc[3], aw, bk1.z, bk1.w);
            uint4 br0 = ldsm4(adrB(srsp, 72, vmin, kb));
            uint4 br1 = ldsm4(adrB(srsp, 72, vmin + 16, kb));
            uint4 br2 = ldsm4(adrB(srsp, 72, vmin + 32, kb));
            mmabf(pf[0], ar, br0.x, br0.y); mmabf(pf[1], ar, br0.z, br0.w);
            mmabf(pf[2], ar, br1.x, br1.y); mmabf(pf[3], ar, br1.z, br1.w);
            mmabf(pf[4], ar, br2.x, br2.y); mmabf(pf[5], ar, br2.z, br2.w);
        }
        #pragma unroll
        for (int q_ = 0; q_ < 6; q_++) {
            *(uint*)(pwb + g * 56 + q_ * 8 + 2 * t)       = bfpair(pf[q_].x, pf[q_].y);
            *(uint*)(pwb + (g + 8) * 56 + q_ * 8 + 2 * t) = bfpair(pf[q_].z, pf[q_].w);
        }
        __syncwarp();

        cpwait1();          // B_t done
        __syncthreads();    // (6)

        // ---- combine + per-warp softmax partials ----
        float td0 = sttd[2*u0], ts0 = sttd[2*u0+1];
        float td1 = sttd[2*u1], ts1 = sttd[2*u1+1];
        uint tb0 = sttb[u0 * 2 + nh];
        uint tb1 = sttb[u1 * 2 + nh];
        float mr0 = -3.0e38f, mr1 = -3.0e38f;
        #pragma unroll
        for (int nt = 0; nt < 4; nt++) {
            int jl = nh * 32 + nt * 8 + 2 * t;
            int sh = nt * 8 + 2 * t;
            float mk0 = samk[jl], mk1 = samk[jl + 1];
            uint cu0 = *(const uint*)(scls + u0 * 72 + jl);
            uint cu1 = *(const uint*)(scls + u1 * 72 + jl);
            float2 cl0 = __bfloat1622float2(*(__nv_bfloat162*)&cu0);
            float2 cl1 = __bfloat1622float2(*(__nv_bfloat162*)&cu1);
            int vc0 = nt * 8 + 2 * t - g + 15;
            int vc1 = vc0 - 8;
            float p00 = __bfloat162float(pwb[g * 56 + vc0]);
            float p01 = __bfloat162float(pwb[g * 56 + vc0 + 1]);
            float p10 = __bfloat162float(pwb[(g + 8) * 56 + vc1]);
            float p11 = __bfloat162float(pwb[(g + 8) * 56 + vc1 + 1]);
            float tv00 = ((tb0 >> sh) & 1)       ? ts0 : td0;
            float tv01 = ((tb0 >> (sh + 1)) & 1) ? ts0 : td0;
            float tv10 = ((tb1 >> sh) & 1)       ? ts1 : td1;
            float tv11 = ((tb1 >> (sh + 1)) & 1) ? ts1 : td1;
            sc[nt].x += cl0.x * (p00 + tv00) - mk0;
            sc[nt].y += cl0.y * (p01 + tv01) - mk1;
            sc[nt].z += cl1.x * (p10 + tv10) - mk0;
            sc[nt].w += cl1.y * (p11 + tv11) - mk1;
            mr0 = fmaxf(mr0, fmaxf(sc[nt].x, sc[nt].y));
            mr1 = fmaxf(mr1, fmaxf(sc[nt].z, sc[nt].w));
        }
        mr0 = fmaxf(mr0, __shfl_xor_sync(~0u, mr0, 1));
        mr0 = fmaxf(mr0, __shfl_xor_sync(~0u, mr0, 2));
        mr1 = fmaxf(mr1, __shfl_xor_sync(~0u, mr1, 1));
        mr1 = fmaxf(mr1, __shfl_xor_sync(~0u, mr1, 2));
        float ls0 = 0.f, ls1 = 0.f;
        #pragma unroll
        for (int nt = 0; nt < 4; nt++) {
            sc[nt].x = __expf(sc[nt].x - mr0); sc[nt].y = __expf(sc[nt].y - mr0);
            sc[nt].z = __expf(sc[nt].z - mr1); sc[nt].w = __expf(sc[nt].w - mr1);
            ls0 += sc[nt].x + sc[nt].y; ls1 += sc[nt].z + sc[nt].w;
        }
        ls0 += __shfl_xor_sync(~0u, ls0, 1); ls0 += __shfl_xor_sync(~0u, ls0, 2);
        ls1 += __shfl_xor_sync(~0u, ls1, 1); ls1 += __shfl_xor_sync(~0u, ls1, 2);
        if (t == 0) {
            mpart[nh * 64 + u0] = mr0; mpart[nh * 64 + u1] = mr1;
            lpart[nh * 64 + u0] = ls0; lpart[nh * 64 + u1] = ls1;
        }
        __syncthreads();   // C

        float a0m = mpart[u0], b0m = mpart[64 + u0];
        float a1m = mpart[u1], b1m = mpart[64 + u1];
        float mn0 = fmaxf(m0r, fmaxf(a0m, b0m));
        float mn1 = fmaxf(m1r, fmaxf(a1m, b1m));
        float co0 = __expf(m0r - mn0), co1 = __expf(m1r - mn1);
        l0r = l0r * co0 + lpart[u0] * __expf(a0m - mn0) + lpart[64 + u0] * __expf(b0m - mn0);
        l1r = l1r * co1 + lpart[u1] * __expf(a1m - mn1) + lpart[64 + u1] * __expf(b1m - mn1);
        m0r = mn0; m1r = mn1;
        float f0 = __expf((nh ? b0m : a0m) - mn0);
        float f1 = __expf((nh ? b1m : a1m) - mn1);
        #pragma unroll
        for (int nt = 0; nt < 4; nt++) {
            int jl = nh * 32 + nt * 8 + 2 * t;
            *(uint*)(sp + u0 * 72 + jl) = bfpair(sc[nt].x * f0, sc[nt].y * f0);
            *(uint*)(sp + u1 * 72 + jl) = bfpair(sc[nt].z * f1, sc[nt].w * f1);
        }
        #pragma unroll
        for (int nt = 0; nt < 4; nt++) {
            of[nt].x *= co0; of[nt].y *= co0;
            of[nt].z *= co1; of[nt].w *= co1;
        }
        __syncthreads();   // D

        #pragma unroll
        for (int ks = 0; ks < 4; ks++) {
            int kb = ks * 16;
            uint4 ap = ldsm4(adrA(sp, 72, mtb, kb));
            uint4 v0 = ldsm4t(adrBT(sv, 72, kb, nh * 32));
            uint4 v1 = ldsm4t(adrBT(sv, 72, kb, nh * 32 + 16));
            mmabf(of[0], ap, v0.x, v0.y); mmabf(of[1], ap, v0.z, v0.w);
            mmabf(of[2], ap, v1.x, v1.y); mmabf(of[3], ap, v1.z, v1.w);
        }
    }

    float inv0 = 1.f / l0r, inv1 = 1.f / l1r;
    bf* outb = g_av + (((size_t)b*Nc + n)*Sc + i0) * Hc;
    #pragma unroll
    for (int nt = 0; nt < 4; nt++) {
        int h = nh * 32 + nt * 8 + 2 * t;
        *(uint*)(outb + (size_t)u0 * Hc + h) = bfpair(of[nt].x * inv0, of[nt].y * inv0);
        *(uint*)(outb + (size_t)u1 * Hc + h) = bfpair(of[nt].z * inv1, of[nt].w * inv1);
    }
}

// ---------- LayerNorm ----------
__global__ __launch_bounds__(256)
void ln_kernel(const float* __restrict__ lng, const float* __restrict__ lnb,
               float* __restrict__ out) {
    __shared__ float red[8];
    __shared__ float stat;
    int row = blockIdx.x;
    const float* x = &g_x[(size_t)row * Dc];
    int t = threadIdx.x;
    float v[3];
    float s = 0.f;
    #pragma unroll
    for (int p = 0; p < 3; p++) { v[p] = x[t + p*256]; s += v[p]; }
    #pragma unroll
    for (int off = 16; off; off >>= 1) s += __shfl_xor_sync(~0u, s, off);
    if ((t & 31) == 0) red[t >> 5] = s;
    __syncthreads();
    if (t < 32) {
        float r = (t < 8) ? red[t] : 0.f;
        #pragma unroll
        for (int off = 4; off; off >>= 1) r += __shfl_xor_sync(~0u, r, off);
        if (t == 0) stat = r * (1.f / Dc);
    }
    __syncthreads();
    float mu = stat;
    float s2 = 0.f;
    #pragma unroll
    for (int p = 0; p < 3; p++) { float d = v[p] - mu; s2 += d*d; }
    #pragma unroll
    for (int off = 16; off; off >>= 1) s2 += __shfl_xor_sync(~0u, s2, off);
    if ((t & 31) == 0) red[t >> 5] = s2;
    __syncthreads();
    if (t < 32) {
        float r = (t < 8) ? red[t] : 0.f;
        #pragma unroll
        for (int off = 4; off; off >>= 1) r += __shfl_xor_sync(~0u, r, off);
        if (t == 0) stat = rsqrtf(r * (1.f / Dc) + EPSV);
    }
    __syncthreads();
    float rstd = stat;
    #pragma unroll
    for (int p = 0; p < 3; p++) {
        int i = t + p*256;
        out[(size_t)row*Dc + i] = (v[p] - mu) * rstd * lng[i] + lnb[i];
    }
}

// ---------- launch ----------
extern "C" void kernel_launch(void* const* d_in, const int* in_sizes, int n_in,
                              void* d_out, int out_size) {
    const float* query = (const float*)d_in[0];
    const float* key   = (const float*)d_in[1];
    const float* value = (const float*)d_in[2];
    const float* pose  = (const float*)d_in[3];
    const unsigned char* ttm = (const unsigned char*)d_in[4];
    const float* amask = (const float*)d_in[5];
    const float* clsm  = (const float*)d_in[6];
    const float* Wq    = (const float*)d_in[7];
    const float* Wk    = (const float*)d_in[8];
    const float* bk    = (const float*)d_in[9];
    const float* Wv    = (const float*)d_in[10];
    const float* bv    = (const float*)d_in[11];
    const float* rwb   = (const float*)d_in[12];
    const float* rrb   = (const float*)d_in[13];
    const float* rker  = (const float*)d_in[14];
    const float* rsb   = (const float*)d_in[15];
    const float* seg   = (const float*)d_in[16];
    const float* Wo    = (const float*)d_in[17];
    const float* bo    = (const float*)d_in[18];
    const float* lng   = (const float*)d_in[19];
    const float* lnb   = (const float*)d_in[20];
    float* out = (float*)d_out;

    dim3 blk(256);
    cb_kernel<<<Bc*Sc, blk>>>(ttm, clsm, amask);
    gemm_in<<<dim3(12, 32, 4), blk>>>(query, key, value, pose,
                                      Wq, Wk, Wv, rker, bk, bv);
    tt_kernel<<<Bc*Nc*Sc/8, blk>>>(rsb, seg);

    cudaFuncSetAttribute(attn_kernel, cudaFuncAttributeMaxDynamicSharedMemorySize,
                         SMEM_ATTN);
    attn_kernel<<<dim3(Sc/64, Nc, Bc), blk, SMEM_ATTN>>>(rwb, rrb);

    gemm_out_b<<<dim3(12, 32), blk>>>(Wo, bo, query);
    ln_kernel<<<Bc*Sc, blk>>>(lng, lnb, out);
}

// round 9
// speedup vs baseline: 2.2784x; 1.1061x over previous
#include <cuda_runtime.h>
#include <cuda_bf16.h>
#include <math.h>

#define Bc 4
#define Sc 1024
#define Dc 768
#define Nc 12
#define Hc 64
#define Rc 2048
#define SCALE 0.125f
#define INFV 1000000.0f
#define EPSV 1e-9f

typedef unsigned int uint;
typedef __nv_bfloat16 bf;

__device__ __align__(16) bf    g_qh[Bc*Nc*Sc*Hc];
__device__ __align__(16) bf    g_kh[Bc*Nc*Sc*Hc];
__device__ __align__(16) bf    g_vh[Bc*Nc*Sc*Hc];
__device__ __align__(16) bf    g_rh[Nc*Rc*Hc];
__device__ float g_tt[Bc*Nc*Sc*2];
__device__ __align__(16) bf    g_av[Bc*Nc*Sc*Hc];
__device__ float g_x [Bc*Sc*Dc];
__device__ __align__(16) bf    g_cls[Sc*Sc];
__device__ __align__(16) uint  g_ttb[Bc*Sc*32];
__device__ __align__(16) float g_mk [Bc*Sc];
// bf16 copies of inputs (prep kernel)
__device__ __align__(16) bf c_q [Bc*Sc*Dc];
__device__ __align__(16) bf c_k [Bc*Sc*Dc];
__device__ __align__(16) bf c_v [Bc*Sc*Dc];
__device__ __align__(16) bf c_p [Rc*Dc];
__device__ __align__(16) bf c_wq[Dc*Dc];
__device__ __align__(16) bf c_wk[Dc*Dc];
__device__ __align__(16) bf c_wv[Dc*Dc];
__device__ __align__(16) bf c_wr[Dc*Dc];
__device__ __align__(16) bf c_wo[Dc*Dc];

// ---------- helpers ----------
__device__ __forceinline__ uint smaddr(const void* p) {
    return (uint)__cvta_generic_to_shared(p);
}
__device__ __forceinline__ void cpa16(uint sa, const void* g) {
    asm volatile("cp.async.cg.shared.global [%0], [%1], 16;"
        :: "r"(sa), "l"(__cvta_generic_to_global(g)));
}
__device__ __forceinline__ void cpa16z(uint sa, const void* g, int sz) {
    asm volatile("cp.async.cg.shared.global [%0], [%1], 16, %2;"
        :: "r"(sa), "l"(__cvta_generic_to_global(g)), "r"(sz));
}
__device__ __forceinline__ void cpa8(uint sa, const void* g) {
    asm volatile("cp.async.ca.shared.global [%0], [%1], 8;"
        :: "r"(sa), "l"(__cvta_generic_to_global(g)));
}
__device__ __forceinline__ void cpcommit() {
    asm volatile("cp.async.commit_group;" ::: "memory");
}
__device__ __forceinline__ void cpwait1() {
    asm volatile("cp.async.wait_group 1;" ::: "memory");
}
__device__ __forceinline__ void cpwait0() {
    asm volatile("cp.async.wait_group 0;" ::: "memory");
}
__device__ __forceinline__ uint4 ldsm4(uint a) {
    uint4 r;
    asm volatile("ldmatrix.sync.aligned.m8n8.x4.shared.b16 {%0,%1,%2,%3},[%4];"
        : "=r"(r.x), "=r"(r.y), "=r"(r.z), "=r"(r.w) : "r"(a));
    return r;
}
__device__ __forceinline__ uint4 ldsm4t(uint a) {
    uint4 r;
    asm volatile("ldmatrix.sync.aligned.m8n8.x4.trans.shared.b16 {%0,%1,%2,%3},[%4];"
        : "=r"(r.x), "=r"(r.y), "=r"(r.z), "=r"(r.w) : "r"(a));
    return r;
}
__device__ __forceinline__ uint adrA(const bf* b, int ld, int row0, int kb) {
    int l = threadIdx.x & 31;
    return smaddr(b + (row0 + (l & 15)) * ld + kb + ((l >> 4) << 3));
}
__device__ __forceinline__ uint adrB(const bf* b, int ld, int nb, int kb) {
    int l = threadIdx.x & 31;
    return smaddr(b + (nb + (l & 7) + ((l & 16) >> 1)) * ld + kb + (l & 8));
}
__device__ __forceinline__ uint adrBT(const bf* b, int ld, int kb, int nb) {
    int l = threadIdx.x & 31;
    return smaddr(b + (kb + (l & 7) + (l & 8)) * ld + nb + ((l & 16) >> 1));
}
__device__ __forceinline__ void mmabf(float4& c, uint4 a, uint b0, uint b1) {
    asm volatile(
        "mma.sync.aligned.m16n8k16.row.col.f32.bf16.bf16.f32 "
        "{%0,%1,%2,%3},{%4,%5,%6,%7},{%8,%9},{%0,%1,%2,%3};"
        : "+f"(c.x), "+f"(c.y), "+f"(c.z), "+f"(c.w)
        : "r"(a.x), "r"(a.y), "r"(a.z), "r"(a.w), "r"(b0), "r"(b1));
}
__device__ __forceinline__ uint bfpair(float lo, float hi) {
    uint r; asm("cvt.rn.bf16x2.f32 %0,%1,%2;" : "=r"(r) : "f"(hi), "f"(lo));
    return r;
}
__device__ __forceinline__ uint addb2(uint a, uint b) {
    uint r; asm("add.rn.bf16x2 %0,%1,%2;" : "=r"(r) : "r"(a), "r"(b));
    return r;
}
__device__ __forceinline__ uint2 pack4(float4 v) {
    uint2 r; r.x = bfpair(v.x, v.y); r.y = bfpair(v.z, v.w); return r;
}

// ---------- prep: fp32 -> bf16 copies ----------
__global__ __launch_bounds__(256)
void prep(const float* q, const float* k, const float* v, const float* pose,
          const float* Wq, const float* Wk, const float* Wv,
          const float* rk, const float* Wo) {
    const int NQ4 = Bc*Sc*Dc/4, NP4 = Rc*Dc/4, NW4 = Dc*Dc/4;
    int total = 3*NQ4 + NP4 + 5*NW4;
    for (int i = blockIdx.x * blockDim.x + threadIdx.x; i < total;
         i += gridDim.x * blockDim.x) {
        const float* s; bf* d; int o = i;
        if (o < NQ4)               { s = q;    d = c_q;  }
        else if ((o -= NQ4) < NQ4) { s = k;    d = c_k;  }
        else if ((o -= NQ4) < NQ4) { s = v;    d = c_v;  }
        else if ((o -= NQ4) < NP4) { s = pose; d = c_p;  }
        else if ((o -= NP4) < NW4) { s = Wq;   d = c_wq; }
        else if ((o -= NW4) < NW4) { s = Wk;   d = c_wk; }
        else if ((o -= NW4) < NW4) { s = Wv;   d = c_wv; }
        else if ((o -= NW4) < NW4) { s = rk;   d = c_wr; }
        else { o -= NW4;             s = Wo;   d = c_wo; }
        float4 vv = *((const float4*)s + o);
        *(uint2*)(d + (size_t)o * 4) = pack4(vv);
    }
}

// ---------- precompute: cls bf16, tt bit-pack, mask ----------
__global__ __launch_bounds__(256)
void cb_kernel(const unsigned char* __restrict__ ttm,
               const float* __restrict__ clsm,
               const float* __restrict__ amask) {
    int r = blockIdx.x;
    int tid = threadIdx.x, w = tid >> 5, lane = tid & 31;
    #pragma unroll
    for (int c = 0; c < 4; c++) {
        int j = w * 128 + c * 32 + lane;
        uint m = __ballot_sync(~0u, ttm[(size_t)r * Sc + j] != 0);
        if (lane == 0) g_ttb[r * 32 + w * 4 + c] = m;
    }
    if (r < Sc) {
        int j4 = tid * 4;
        float4 c4 = *(const float4*)(clsm + (size_t)r * Sc + j4);
        *(uint2*)(g_cls + (size_t)r * Sc + j4) = pack4(c4);
    }
    if (r < 16) {
        int idx = r * 256 + tid;
        g_mk[idx] = INFV * (1.f - amask[idx]);
    }
}

// ---------- pipelined bf16 GEMMs: 128x128 tile, KC=64, cp.async dbuf ----------
#define GA0 0
#define GA1 9216
#define GB0 18432
#define GB1 27136
#define GSM_BYTES (35840*2)

extern __shared__ bf gsm[];

__device__ __forceinline__ void gstage(const bf* __restrict__ A,
                                       const bf* __restrict__ W,
                                       int m0, int n0, int ks, int b) {
    int tid = threadIdx.x;
    bf* As = gsm + (b ? GA1 : GA0);
    bf* Bs = gsm + (b ? GB1 : GB0);
    #pragma unroll
    for (int p = 0; p < 4; p++) {
        int cid = tid + p * 256;
        int row = cid >> 3, cc = cid & 7;
        cpa16(smaddr(As + row * 72 + cc * 8),
              A + (size_t)(m0 + row) * Dc + ks * 64 + cc * 8);
    }
    #pragma unroll
    for (int p = 0; p < 4; p++) {
        int cid = tid + p * 256;
        int kk = cid >> 4, cc = cid & 15;
        cpa16(smaddr(Bs + kk * 136 + cc * 8),
              W + (size_t)(ks * 64 + kk) * Dc + n0 + cc * 8);
    }
    cpcommit();
}

__device__ __forceinline__ void gcompute(float4 (&c)[4][4], int wm, int wn, int b) {
    bf* As = gsm + (b ? GA1 : GA0);
    bf* Bs = gsm + (b ? GB1 : GB0);
    #pragma unroll
    for (int ks16 = 0; ks16 < 4; ks16++) {
        int kb = ks16 * 16;
        uint4 a0 = ldsm4(adrA(As, 72, wm * 64, kb));
        uint4 a1 = ldsm4(adrA(As, 72, wm * 64 + 16, kb));
        uint4 a2 = ldsm4(adrA(As, 72, wm * 64 + 32, kb));
        uint4 a3 = ldsm4(adrA(As, 72, wm * 64 + 48, kb));
        uint4 b0 = ldsm4t(adrBT(Bs, 136, kb, wn * 32));
        uint4 b1 = ldsm4t(adrBT(Bs, 136, kb, wn * 32 + 16));
        mmabf(c[0][0], a0, b0.x, b0.y); mmabf(c[0][1], a0, b0.z, b0.w);
        mmabf(c[0][2], a0, b1.x, b1.y); mmabf(c[0][3], a0, b1.z, b1.w);
        mmabf(c[1][0], a1, b0.x, b0.y); mmabf(c[1][1], a1, b0.z, b0.w);
        mmabf(c[1][2], a1, b1.x, b1.y); mmabf(c[1][3], a1, b1.z, b1.w);
        mmabf(c[2][0], a2, b0.x, b0.y); mmabf(c[2][1], a2, b0.z, b0.w);
        mmabf(c[2][2], a2, b1.x, b1.y); mmabf(c[2][3], a2, b1.z, b1.w);
        mmabf(c[3][0], a3, b0.x, b0.y); mmabf(c[3][1], a3, b0.z, b0.w);
        mmabf(c[3][2], a3, b1.x, b1.y); mmabf(c[3][3], a3, b1.z, b1.w);
    }
}

__device__ __forceinline__ void gemm_core_b(
    const bf* __restrict__ A, const bf* __restrict__ W,
    const float* __restrict__ bias, float scale, int sshift, bf* __restrict__ out) {
    int tid = threadIdx.x, l = tid & 31, g = l >> 2, t = l & 3, w = tid >> 5;
    int wm = w & 1, wn = w >> 1;
    int m0 = blockIdx.y * 128, n0 = blockIdx.x * 128;
    int Srows = 1 << sshift;

    float4 c[4][4];
    #pragma unroll
    for (int i = 0; i < 4; i++)
        #pragma unroll
        for (int j = 0; j < 4; j++) c[i][j] = make_float4(0.f, 0.f, 0.f, 0.f);

    gstage(A, W, m0, n0, 0, 0);
    for (int ks = 0; ks < 12; ks++) {
        int b = ks & 1;
        if (ks < 11) { gstage(A, W, m0, n0, ks + 1, b ^ 1); cpwait1(); }
        else cpwait0();
        __syncthreads();
        gcompute(c, wm, wn, b);
        __syncthreads();
    }
    #pragma unroll
    for (int mi = 0; mi < 4; mi++) {
        #pragma unroll
        for (int nt = 0; nt < 4; nt++) {
            int col = n0 + wn * 32 + nt * 8 + 2 * t;
            float b0f = bias ? __ldg(bias + col) : 0.f;
            float b1f = bias ? __ldg(bias + col + 1) : 0.f;
            int nn = col >> 6, hh = col & 63;
            #pragma unroll
            for (int r = 0; r < 2; r++) {
                int row = m0 + wm * 64 + mi * 16 + g + r * 8;
                int bb = row >> sshift, ss = row & (Srows - 1);
                float v0 = (r ? c[mi][nt].z : c[mi][nt].x) * scale + b0f;
                float v1 = (r ? c[mi][nt].w : c[mi][nt].y) * scale + b1f;
                *(uint*)(out + (((size_t)bb * Nc + nn) * Srows + ss) * Hc + hh) =
                    bfpair(v0, v1);
            }
        }
    }
}

__global__ __launch_bounds__(256)
void gemm_in(const float* bk, const float* bv) {
    int z = blockIdx.z;
    if (z == 0)      gemm_core_b(c_q, c_wq, nullptr, SCALE, 10, g_qh);
    else if (z == 1) gemm_core_b(c_k, c_wk, bk, 1.f, 10, g_kh);
    else if (z == 2) gemm_core_b(c_v, c_wv, bv, 1.f, 10, g_vh);
    else if (blockIdx.y < 16) gemm_core_b(c_p, c_wr, nullptr, 1.f, 11, g_rh);
}

// ---------- output GEMM + residual (pipelined) ----------
__global__ __launch_bounds__(256)
void gemm_out_b(const float* __restrict__ bo, const float* __restrict__ query) {
    int tid = threadIdx.x, l = tid & 31, g = l >> 2, t = l & 3, w = tid >> 5;
    int wm = w & 1, wn = w >> 1;
    int m0 = blockIdx.y * 128, n0 = blockIdx.x * 128;

    float4 c[4][4];
    #pragma unroll
    for (int i = 0; i < 4; i++)
        #pragma unroll
        for (int j = 0; j < 4; j++) c[i][j] = make_float4(0.f, 0.f, 0.f, 0.f);

    auto stage = [&](int ks, int b) {
        bf* As = gsm + (b ? GA1 : GA0);
        bf* Bs = gsm + (b ? GB1 : GB0);
        #pragma unroll
        for (int p = 0; p < 4; p++) {
            int cid = tid + p * 256;
            int row = cid >> 3, cc = cid & 7;
            int rg = m0 + row;
            cpa16(smaddr(As + row * 72 + cc * 8),
                  g_av + (((size_t)(rg >> 10) * Nc + ks) * Sc + (rg & 1023)) * Hc + cc * 8);
        }
        #pragma unroll
        for (int p = 0; p < 4; p++) {
            int cid = tid + p * 256;
            int kk = cid >> 4, cc = cid & 15;
            cpa16(smaddr(Bs + kk * 136 + cc * 8),
                  c_wo + (size_t)(ks * 64 + kk) * Dc + n0 + cc * 8);
        }
        cpcommit();
    };

    stage(0, 0);
    for (int ks = 0; ks < 12; ks++) {
        int b = ks & 1;
        if (ks < 11) { stage(ks + 1, b ^ 1); cpwait1(); }
        else cpwait0();
        __syncthreads();
        gcompute(c, wm, wn, b);
        __syncthreads();
    }
    #pragma unroll
    for (int mi = 0; mi < 4; mi++) {
        #pragma unroll
        for (int nt = 0; nt < 4; nt++) {
            int col = n0 + wn * 32 + nt * 8 + 2 * t;
            float b0f = __ldg(bo + col), b1f = __ldg(bo + col + 1);
            #pragma unroll
            for (int r = 0; r < 2; r++) {
                int row = m0 + wm * 64 + mi * 16 + g + r * 8;
                float2 q = *(const float2*)(query + (size_t)row * Dc + col);
                float v0 = (r ? c[mi][nt].z : c[mi][nt].x) + b0f + q.x;
                float v1 = (r ? c[mi][nt].w : c[mi][nt].y) + b1f + q.y;
                *(float2*)(g_x + (size_t)row * Dc + col) = make_float2(v0, v1);
            }
        }
    }
}

// ---------- token-type bias ----------
__global__ __launch_bounds__(256)
void tt_kernel(const float* __restrict__ rsb, const float* __restrict__ seg) {
    int warp = threadIdx.x >> 5, lane = threadIdx.x & 31;
    int row = blockIdx.x * 8 + warp;
    int n = (row / Sc) % Nc;
    const bf* q = &g_qh[(size_t)row * Hc];
    float d = 0.f, s = 0.f;
    #pragma unroll
    for (int p = 0; p < 2; p++) {
        int h = lane + p * 32;
        float qv = __bfloat162float(q[h]) + rsb[n * Hc + h] * SCALE;
        d += qv * seg[(0 * Nc + n) * Hc + h];
        s += qv * seg[(1 * Nc + n) * Hc + h];
    }
    #pragma unroll
    for (int off = 16; off; off >>= 1) {
        d += __shfl_xor_sync(~0u, d, off);
        s += __shfl_xor_sync(~0u, s, off);
    }
    if (lane == 0) { g_tt[(size_t)row*2 + 0] = d; g_tt[(size_t)row*2 + 1] = s; }
}

// ---------- fused attention: cp.async pipelined (unchanged from R7) ----------
#define OQ    0
#define OK0   4608
#define OK1   9216
#define OV    13824
#define OP    18432
#define ORS0  23040
#define ORS1  32256
#define OCLS  41472
#define OPW   46080
#define ORW   53248
#define ORR   53312
#define FOFF  53376
#define SMEM_ATTN (53376*2 + (128 + 64 + 128 + 128 + 128)*4)

extern __shared__ bf smb[];
__global__ __launch_bounds__(256)
void attn_kernel(const float* __restrict__ rwb, const float* __restrict__ rrb) {
    bf* sq   = smb + OQ;
    bf* sv   = smb + OV;
    bf* sp   = smb + OP;
    bf* scls = smb + OCLS;
    bf* rwbs = smb + ORW;
    bf* rrbs = smb + ORR;
    uint*  sttb = (uint*)(smb + FOFF);
    float* samk = (float*)(sttb + 128);
    float* sttd = samk + 64;
    float* mpart = sttd + 128;
    float* lpart = mpart + 128;

    int tid = threadIdx.x, l = tid & 31, g = l >> 2, t = l & 3, w = tid >> 5;
    int mt = w >> 1, nh = w & 1;
    int mtb = mt * 16;
    int i0 = blockIdx.x * 64, n = blockIdx.y, b = blockIdx.z;

    const bf* qbase = g_qh + (((size_t)b*Nc + n)*Sc + i0) * Hc;
    const bf* kbase = g_kh + (((size_t)b*Nc + n)*Sc) * Hc;
    const bf* vbase = g_vh + (((size_t)b*Nc + n)*Sc) * Hc;
    const bf* rbase = g_rh + (size_t)n * Rc * Hc;

    #pragma unroll
    for (int p = 0; p < 2; p++) {
        int cid = tid + p * 256;
        int row = cid >> 3, c16 = cid & 7;
        cpa16(smaddr(sq + row * 72) + c16 * 16, qbase + (size_t)row * Hc + c16 * 8);
        cpa16(smaddr(smb + OK0 + row * 72) + c16 * 16,
              kbase + (size_t)row * Hc + c16 * 8);
    }
    {
        int tb_ = Sc - i0 - 63;
        #pragma unroll
        for (int p = 0; p < 4; p++) {
            int cid = tid + p * 256;
            int row = cid >> 3, c16 = cid & 7;
            int tt2 = tb_ + row;
            int sz = ((unsigned)tt2 < Rc) ? 16 : 0;
            cpa16z(smaddr(smb + ORS0 + row * 72) + c16 * 16,
                   rbase + (size_t)(tt2 & 2047) * Hc + c16 * 8, sz);
        }
    }
    cpcommit();
    if (tid < 64) {
        rwbs[tid] = __float2bfloat16(rwb[n * Hc + tid] * SCALE);
        rrbs[tid] = __float2bfloat16(rrb[n * Hc + tid] * SCALE);
    }
    if (tid < 128) sttd[tid] = g_tt[(((size_t)b*Nc + n)*Sc + i0)*2 + tid];

    float4 of[4];
    #pragma unroll
    for (int nt = 0; nt < 4; nt++) of[nt] = make_float4(0.f, 0.f, 0.f, 0.f);
    float m0r = -3.0e38f, m1r = -3.0e38f, l0r = 0.f, l1r = 0.f;

    int vmin = nh * 32 - mtb + 48;
    int u0 = mtb + g, u1 = u0 + 8;
    bf* pwb = smb + OPW + w * (16 * 56);

    for (int t16 = 0; t16 < 16; t16++) {
        int j0 = t16 * 64;
        int p = t16 & 1;
        bf* skp  = smb + (p ? OK1 : OK0);
        bf* srsp = smb + (p ? ORS1 : ORS0);

        __syncthreads();
        #pragma unroll
        for (int q_ = 0; q_ < 2; q_++) {
            int cid = tid + q_ * 256;
            int row = cid >> 3, c16 = cid & 7;
            cpa16(smaddr(sv + row * 72) + c16 * 16,
                  vbase + (size_t)(j0 + row) * Hc + c16 * 8);
            cpa16(smaddr(scls + row * 72) + c16 * 16,
                  g_cls + (size_t)(i0 + row) * Sc + j0 + c16 * 8);
        }
        if (tid < 64)
            cpa8(smaddr(sttb) + tid * 8,
                 g_ttb + ((size_t)(b * Sc + i0 + tid) * 32 + (j0 >> 5)));
        if (tid < 16)
            cpa16(smaddr(samk) + tid * 16, g_mk + b * Sc + j0 + tid * 4);
        cpcommit();

        cpwait1();
        __syncthreads();

        {
            int j0n = j0 + 64;
            if (j0n < Sc) {
                bf* dK = smb + (p ? OK0 : OK1);
                bf* dR = smb + (p ? ORS0 : ORS1);
                #pragma unroll
                for (int q_ = 0; q_ < 2; q_++) {
                    int cid = tid + q_ * 256;
                    int row = cid >> 3, c16 = cid & 7;
                    cpa16(smaddr(dK + row * 72) + c16 * 16,
                          kbase + (size_t)(j0n + row) * Hc + c16 * 8);
                }
                int tb_ = Sc - i0 - 63 + j0n;
                #pragma unroll
                for (int q_ = 0; q_ < 4; q_++) {
                    int cid = tid + q_ * 256;
                    int row = cid >> 3, c16 = cid & 7;
                    int tt2 = tb_ + row;
                    int sz = ((unsigned)tt2 < Rc) ? 16 : 0;
                    cpa16z(smaddr(dR + row * 72) + c16 * 16,
                           rbase + (size_t)(tt2 & 2047) * Hc + c16 * 8, sz);
                }
            }
            cpcommit();
        }

        float4 sc[4], pf[6];
        #pragma unroll
        for (int q_ = 0; q_ < 4; q_++) sc[q_] = make_float4(0.f, 0.f, 0.f, 0.f);
        #pragma unroll
        for (int q_ = 0; q_ < 6; q_++) pf[q_] = make_float4(0.f, 0.f, 0.f, 0.f);
        #pragma unroll
        for (int ks = 0; ks < 4; ks++) {
            int kb = ks * 16;
            uint4 qa = ldsm4(adrA(sq, 72, mtb, kb));
            uint rw0 = *(const uint*)(rwbs + kb + 2 * t);
            uint rw1 = *(const uint*)(rwbs + kb + 2 * t + 8);
            uint rr0 = *(const uint*)(rrbs + kb + 2 * t);
            uint rr1 = *(const uint*)(rrbs + kb + 2 * t + 8);
            uint4 aw, ar;
            aw.x = addb2(qa.x, rw0); aw.y = addb2(qa.y, rw0);
            aw.z = addb2(qa.z, rw1); aw.w = addb2(qa.w, rw1);
            ar.x = addb2(qa.x, rr0); ar.y = addb2(qa.y, rr0);
            ar.z = addb2(qa.z, rr1); ar.w = addb2(qa.w, rr1);
            uint4 bk0 = ldsm4(adrB(skp, 72, nh * 32, kb));
            uint4 bk1 = ldsm4(adrB(skp, 72, nh * 32 + 16, kb));
            mmabf(sc[0], aw, bk0.x, bk0.y); mmabf(sc[1], aw, bk0.z, bk0.w);
            mmabf(sc[2], aw, bk1.x, bk1.y); mmabf(sc[3], aw, bk1.z, bk1.w);
            uint4 br0 = ldsm4(adrB(srsp, 72, vmin, kb));
            uint4 br1 = ldsm4(adrB(srsp, 72, vmin + 16, kb));
            uint4 br2 = ldsm4(adrB(srsp, 72, vmin + 32, kb));
            mmabf(pf[0], ar, br0.x, br0.y); mmabf(pf[1], ar, br0.z, br0.w);
            mmabf(pf[2], ar, br1.x, br1.y); mmabf(pf[3], ar, br1.z, br1.w);
            mmabf(pf[4], ar, br2.x, br2.y); mmabf(pf[5], ar, br2.z, br2.w);
        }
        #pragma unroll
        for (int q_ = 0; q_ < 6; q_++) {
            *(uint*)(pwb + g * 56 + q_ * 8 + 2 * t)       = bfpair(pf[q_].x, pf[q_].y);
            *(uint*)(pwb + (g + 8) * 56 + q_ * 8 + 2 * t) = bfpair(pf[q_].z, pf[q_].w);
        }
        __syncwarp();

        cpwait1();
        __syncthreads();

        float td0 = sttd[2*u0], ts0 = sttd[2*u0+1];
        float td1 = sttd[2*u1], ts1 = sttd[2*u1+1];
        uint tb0 = sttb[u0 * 2 + nh];
        uint tb1 = sttb[u1 * 2 + nh];
        float mr0 = -3.0e38f, mr1 = -3.0e38f;
        #pragma unroll
        for (int nt = 0; nt < 4; nt++) {
            int jl = nh * 32 + nt * 8 + 2 * t;
            int sh = nt * 8 + 2 * t;
            float mk0 = samk[jl], mk1 = samk[jl + 1];
            uint cu0 = *(const uint*)(scls + u0 * 72 + jl);
            uint cu1 = *(const uint*)(scls + u1 * 72 + jl);
            float2 cl0 = __bfloat1622float2(*(__nv_bfloat162*)&cu0);
            float2 cl1 = __bfloat1622float2(*(__nv_bfloat162*)&cu1);
            int vc0 = nt * 8 + 2 * t - g + 15;
            int vc1 = vc0 - 8;
            float p00 = __bfloat162float(pwb[g * 56 + vc0]);
            float p01 = __bfloat162float(pwb[g * 56 + vc0 + 1]);
            float p10 = __bfloat162float(pwb[(g + 8) * 56 + vc1]);
            float p11 = __bfloat162float(pwb[(g + 8) * 56 + vc1 + 1]);
            float tv00 = ((tb0 >> sh) & 1)       ? ts0 : td0;
            float tv01 = ((tb0 >> (sh + 1)) & 1) ? ts0 : td0;
            float tv10 = ((tb1 >> sh) & 1)       ? ts1 : td1;
            float tv11 = ((tb1 >> (sh + 1)) & 1) ? ts1 : td1;
            sc[nt].x += cl0.x * (p00 + tv00) - mk0;
            sc[nt].y += cl0.y * (p01 + tv01) - mk1;
            sc[nt].z += cl1.x * (p10 + tv10) - mk0;
            sc[nt].w += cl1.y * (p11 + tv11) - mk1;
            mr0 = fmaxf(mr0, fmaxf(sc[nt].x, sc[nt].y));
            mr1 = fmaxf(mr1, fmaxf(sc[nt].z, sc[nt].w));
        }
        mr0 = fmaxf(mr0, __shfl_xor_sync(~0u, mr0, 1));
        mr0 = fmaxf(mr0, __shfl_xor_sync(~0u, mr0, 2));
        mr1 = fmaxf(mr1, __shfl_xor_sync(~0u, mr1, 1));
        mr1 = fmaxf(mr1, __shfl_xor_sync(~0u, mr1, 2));
        float ls0 = 0.f, ls1 = 0.f;
        #pragma unroll
        for (int nt = 0; nt < 4; nt++) {
            sc[nt].x = __expf(sc[nt].x - mr0); sc[nt].y = __expf(sc[nt].y - mr0);
            sc[nt].z = __expf(sc[nt].z - mr1); sc[nt].w = __expf(sc[nt].w - mr1);
            ls0 += sc[nt].x + sc[nt].y; ls1 += sc[nt].z + sc[nt].w;
        }
        ls0 += __shfl_xor_sync(~0u, ls0, 1); ls0 += __shfl_xor_sync(~0u, ls0, 2);
        ls1 += __shfl_xor_sync(~0u, ls1, 1); ls1 += __shfl_xor_sync(~0u, ls1, 2);
        if (t == 0) {
            mpart[nh * 64 + u0] = mr0; mpart[nh * 64 + u1] = mr1;
            lpart[nh * 64 + u0] = ls0; lpart[nh * 64 + u1] = ls1;
        }
        __syncthreads();

        float a0m = mpart[u0], b0m = mpart[64 + u0];
        float a1m = mpart[u1], b1m = mpart[64 + u1];
        float mn0 = fmaxf(m0r, fmaxf(a0m, b0m));
        float mn1 = fmaxf(m1r, fmaxf(a1m, b1m));
        float co0 = __expf(m0r - mn0), co1 = __expf(m1r - mn1);
        l0r = l0r * co0 + lpart[u0] * __expf(a0m - mn0) + lpart[64 + u0] * __expf(b0m - mn0);
        l1r = l1r * co1 + lpart[u1] * __expf(a1m - mn1) + lpart[64 + u1] * __expf(b1m - mn1);
        m0r = mn0; m1r = mn1;
        float f0 = __expf((nh ? b0m : a0m) - mn0);
        float f1 = __expf((nh ? b1m : a1m) - mn1);
        #pragma unroll
        for (int nt = 0; nt < 4; nt++) {
            int jl = nh * 32 + nt * 8 + 2 * t;
            *(uint*)(sp + u0 * 72 + jl) = bfpair(sc[nt].x * f0, sc[nt].y * f0);
            *(uint*)(sp + u1 * 72 + jl) = bfpair(sc[nt].z * f1, sc[nt].w * f1);
        }
        #pragma unroll
        for (int nt = 0; nt < 4; nt++) {
            of[nt].x *= co0; of[nt].y *= co0;
            of[nt].z *= co1; of[nt].w *= co1;
        }
        __syncthreads();

        #pragma unroll
        for (int ks = 0; ks < 4; ks++) {
            int kb = ks * 16;
            uint4 ap = ldsm4(adrA(sp, 72, mtb, kb));
            uint4 v0 = ldsm4t(adrBT(sv, 72, kb, nh * 32));
            uint4 v1 = ldsm4t(adrBT(sv, 72, kb, nh * 32 + 16));
            mmabf(of[0], ap, v0.x, v0.y); mmabf(of[1], ap, v0.z, v0.w);
            mmabf(of[2], ap, v1.x, v1.y); mmabf(of[3], ap, v1.z, v1.w);
        }
    }

    float inv0 = 1.f / l0r, inv1 = 1.f / l1r;
    bf* outb = g_av + (((size_t)b*Nc + n)*Sc + i0) * Hc;
    #pragma unroll
    for (int nt = 0; nt < 4; nt++) {
        int h = nh * 32 + nt * 8 + 2 * t;
        *(uint*)(outb + (size_t)u0 * Hc + h) = bfpair(of[nt].x * inv0, of[nt].y * inv0);
        *(uint*)(outb + (size_t)u1 * Hc + h) = bfpair(of[nt].z * inv1, of[nt].w * inv1);
    }
}

// ---------- LayerNorm ----------
__global__ __launch_bounds__(256)
void ln_kernel(const float* __restrict__ lng, const float* __restrict__ lnb,
               float* __restrict__ out) {
    __shared__ float red[8];
    __shared__ float stat;
    int row = blockIdx.x;
    const float* x = &g_x[(size_t)row * Dc];
    int t = threadIdx.x;
    float v[3];
    float s = 0.f;
    #pragma unroll
    for (int p = 0; p < 3; p++) { v[p] = x[t + p*256]; s += v[p]; }
    #pragma unroll
    for (int off = 16; off; off >>= 1) s += __shfl_xor_sync(~0u, s, off);
    if ((t & 31) == 0) red[t >> 5] = s;
    __syncthreads();
    if (t < 32) {
        float r = (t < 8) ? red[t] : 0.f;
        #pragma unroll
        for (int off = 4; off; off >>= 1) r += __shfl_xor_sync(~0u, r, off);
        if (t == 0) stat = r * (1.f / Dc);
    }
    __syncthreads();
    float mu = stat;
    float s2 = 0.f;
    #pragma unroll
    for (int p = 0; p < 3; p++) { float d = v[p] - mu; s2 += d*d; }
    #pragma unroll
    for (int off = 16; off; off >>= 1) s2 += __shfl_xor_sync(~0u, s2, off);
    if ((t & 31) == 0) red[t >> 5] = s2;
    __syncthreads();
    if (t < 32) {
        float r = (t < 8) ? red[t] : 0.f;
        #pragma unroll
        for (int off = 4; off; off >>= 1) r += __shfl_xor_sync(~0u, r, off);
        if (t == 0) stat = rsqrtf(r * (1.f / Dc) + EPSV);
    }
    __syncthreads();
    float rstd = stat;
    #pragma unroll
    for (int p = 0; p < 3; p++) {
        int i = t + p*256;
        out[(size_t)row*Dc + i] = (v[p] - mu) * rstd * lng[i] + lnb[i];
    }
}

// ---------- launch ----------
extern "C" void kernel_launch(void* const* d_in, const int* in_sizes, int n_in,
                              void* d_out, int out_size) {
    const float* query = (const float*)d_in[0];
    const float* key   = (const float*)d_in[1];
    const float* value = (const float*)d_in[2];
    const float* pose  = (const float*)d_in[3];
    const unsigned char* ttm = (const unsigned char*)d_in[4];
    const float* amask = (const float*)d_in[5];
    const float* clsm  = (const float*)d_in[6];
    const float* Wq    = (const float*)d_in[7];
    const float* Wk    = (const float*)d_in[8];
    const float* bk    = (const float*)d_in[9];
    const float* Wv    = (const float*)d_in[10];
    const float* bv    = (const float*)d_in[11];
    const float* rwb   = (const float*)d_in[12];
    const float* rrb   = (const float*)d_in[13];
    const float* rker  = (const float*)d_in[14];
    const float* rsb   = (const float*)d_in[15];
    const float* seg   = (const float*)d_in[16];
    const float* Wo    = (const float*)d_in[17];
    const float* bo    = (const float*)d_in[18];
    const float* lng   = (const float*)d_in[19];
    const float* lnb   = (const float*)d_in[20];
    float* out = (float*)d_out;

    dim3 blk(256);
    prep<<<4096, blk>>>(query, key, value, pose, Wq, Wk, Wv, rker, Wo);
    cb_kernel<<<Bc*Sc, blk>>>(ttm, clsm, amask);

    cudaFuncSetAttribute(gemm_in, cudaFuncAttributeMaxDynamicSharedMemorySize,
                         GSM_BYTES);
    gemm_in<<<dim3(6, 32, 4), blk, GSM_BYTES>>>(bk, bv);

    tt_kernel<<<Bc*Nc*Sc/8, blk>>>(rsb, seg);

    cudaFuncSetAttribute(attn_kernel, cudaFuncAttributeMaxDynamicSharedMemorySize,
                         SMEM_ATTN);
    attn_kernel<<<dim3(Sc/64, Nc, Bc), blk, SMEM_ATTN>>>(rwb, rrb);

    cudaFuncSetAttribute(gemm_out_b, cudaFuncAttributeMaxDynamicSharedMemorySize,
                         GSM_BYTES);
    gemm_out_b<<<dim3(6, 32), blk, GSM_BYTES>>>(bo, query);

    ln_kernel<<<Bc*Sc, blk>>>(lng, lnb, out);
}

// round 12
// speedup vs baseline: 2.3243x; 1.0202x over previous
#include <cuda_runtime.h>
#include <cuda_bf16.h>
#include <math.h>

#define Bc 4
#define Sc 1024
#define Dc 768
#define Nc 12
#define Hc 64
#define Rc 2048
#define SCALE 0.125f
#define INFV 1000000.0f
#define EPSV 1e-9f

typedef unsigned int uint;
typedef __nv_bfloat16 bf;

__device__ __align__(16) bf    g_qh[Bc*Nc*Sc*Hc];
__device__ __align__(16) bf    g_kh[Bc*Nc*Sc*Hc];
__device__ __align__(16) bf    g_vh[Bc*Nc*Sc*Hc];
__device__ __align__(16) bf    g_rh[Nc*Rc*Hc];
__device__ __align__(16) bf    g_av[Bc*Nc*Sc*Hc];
__device__ float g_x [Bc*Sc*Dc];
__device__ __align__(16) bf    g_cls[Sc*Sc];
__device__ __align__(16) uint  g_ttb[Bc*Sc*32];
__device__ __align__(16) float g_mk [Bc*Sc];
// bf16 copies of inputs
__device__ __align__(16) bf c_q [Bc*Sc*Dc];
__device__ __align__(16) bf c_k [Bc*Sc*Dc];
__device__ __align__(16) bf c_v [Bc*Sc*Dc];
__device__ __align__(16) bf c_p [Rc*Dc];
__device__ __align__(16) bf c_wq[Dc*Dc];
__device__ __align__(16) bf c_wk[Dc*Dc];
__device__ __align__(16) bf c_wv[Dc*Dc];
__device__ __align__(16) bf c_wr[Dc*Dc];
__device__ __align__(16) bf c_wo[Dc*Dc];

// ---------- helpers ----------
__device__ __forceinline__ uint smaddr(const void* p) {
    return (uint)__cvta_generic_to_shared(p);
}
__device__ __forceinline__ void cpa16(uint sa, const void* g) {
    asm volatile("cp.async.cg.shared.global [%0], [%1], 16;"
        :: "r"(sa), "l"(__cvta_generic_to_global(g)));
}
__device__ __forceinline__ void cpa16z(uint sa, const void* g, int sz) {
    asm volatile("cp.async.cg.shared.global [%0], [%1], 16, %2;"
        :: "r"(sa), "l"(__cvta_generic_to_global(g)), "r"(sz));
}
__device__ __forceinline__ void cpa8(uint sa, const void* g) {
    asm volatile("cp.async.ca.shared.global [%0], [%1], 8;"
        :: "r"(sa), "l"(__cvta_generic_to_global(g)));
}
__device__ __forceinline__ void cpcommit() {
    asm volatile("cp.async.commit_group;" ::: "memory");
}
__device__ __forceinline__ void cpwait1() {
    asm volatile("cp.async.wait_group 1;" ::: "memory");
}
__device__ __forceinline__ void cpwait0() {
    asm volatile("cp.async.wait_group 0;" ::: "memory");
}
__device__ __forceinline__ uint4 ldsm4(uint a) {
    uint4 r;
    asm volatile("ldmatrix.sync.aligned.m8n8.x4.shared.b16 {%0,%1,%2,%3},[%4];"
        : "=r"(r.x), "=r"(r.y), "=r"(r.z), "=r"(r.w) : "r"(a));
    return r;
}
__device__ __forceinline__ uint4 ldsm4t(uint a) {
    uint4 r;
    asm volatile("ldmatrix.sync.aligned.m8n8.x4.trans.shared.b16 {%0,%1,%2,%3},[%4];"
        : "=r"(r.x), "=r"(r.y), "=r"(r.z), "=r"(r.w) : "r"(a));
    return r;
}
__device__ __forceinline__ uint adrA(const bf* b, int ld, int row0, int kb) {
    int l = threadIdx.x & 31;
    return smaddr(b + (row0 + (l & 15)) * ld + kb + ((l >> 4) << 3));
}
__device__ __forceinline__ uint adrB(const bf* b, int ld, int nb, int kb) {
    int l = threadIdx.x & 31;
    return smaddr(b + (nb + (l & 7) + ((l & 16) >> 1)) * ld + kb + (l & 8));
}
__device__ __forceinline__ uint adrBT(const bf* b, int ld, int kb, int nb) {
    int l = threadIdx.x & 31;
    return smaddr(b + (kb + (l & 7) + (l & 8)) * ld + nb + ((l & 16) >> 1));
}
__device__ __forceinline__ void mmabf(float4& c, uint4 a, uint b0, uint b1) {
    asm volatile(
        "mma.sync.aligned.m16n8k16.row.col.f32.bf16.bf16.f32 "
        "{%0,%1,%2,%3},{%4,%5,%6,%7},{%8,%9},{%0,%1,%2,%3};"
        : "+f"(c.x), "+f"(c.y), "+f"(c.z), "+f"(c.w)
        : "r"(a.x), "r"(a.y), "r"(a.z), "r"(a.w), "r"(b0), "r"(b1));
}
__device__ __forceinline__ uint bfpair(float lo, float hi) {
    uint r; asm("cvt.rn.bf16x2.f32 %0,%1,%2;" : "=r"(r) : "f"(hi), "f"(lo));
    return r;
}
__device__ __forceinline__ uint addb2(uint a, uint b) {
    uint r; asm("add.rn.bf16x2 %0,%1,%2;" : "=r"(r) : "r"(a), "r"(b));
    return r;
}
__device__ __forceinline__ uint2 pack4(float4 v) {
    uint2 r; r.x = bfpair(v.x, v.y); r.y = bfpair(v.z, v.w); return r;
}

// ---------- setup: cb (blocks < 4096) + prep (blocks >= 4096) ----------
__global__ __launch_bounds__(256)
void setup(const unsigned char* __restrict__ ttm,
           const float* __restrict__ clsm,
           const float* __restrict__ amask,
           const float* q, const float* k, const float* v, const float* pose,
           const float* Wq, const float* Wk, const float* Wv,
           const float* rk, const float* Wo) {
    int tid = threadIdx.x;
    if (blockIdx.x < Bc*Sc) {
        int r = blockIdx.x;
        int w = tid >> 5, lane = tid & 31;
        #pragma unroll
        for (int c = 0; c < 4; c++) {
            int j = w * 128 + c * 32 + lane;
            uint m = __ballot_sync(~0u, ttm[(size_t)r * Sc + j] != 0);
            if (lane == 0) g_ttb[r * 32 + w * 4 + c] = m;
        }
        if (r < Sc) {
            int j4 = tid * 4;
            float4 c4 = *(const float4*)(clsm + (size_t)r * Sc + j4);
            *(uint2*)(g_cls + (size_t)r * Sc + j4) = pack4(c4);
        }
        if (r < 16) {
            int idx = r * 256 + tid;
            g_mk[idx] = INFV * (1.f - amask[idx]);
        }
    } else {
        const int NQ4 = Bc*Sc*Dc/4, NP4 = Rc*Dc/4, NW4 = Dc*Dc/4;
        int total = 3*NQ4 + NP4 + 5*NW4;
        int nb = gridDim.x - Bc*Sc;
        for (int i = (blockIdx.x - Bc*Sc) * 256 + tid; i < total; i += nb * 256) {
            const float* s; bf* d; int o = i;
            if (o < NQ4)               { s = q;    d = c_q;  }
            else if ((o -= NQ4) < NQ4) { s = k;    d = c_k;  }
            else if ((o -= NQ4) < NQ4) { s = v;    d = c_v;  }
            else if ((o -= NQ4) < NP4) { s = pose; d = c_p;  }
            else if ((o -= NP4) < NW4) { s = Wq;   d = c_wq; }
            else if ((o -= NW4) < NW4) { s = Wk;   d = c_wk; }
            else if ((o -= NW4) < NW4) { s = Wv;   d = c_wv; }
            else if ((o -= NW4) < NW4) { s = rk;   d = c_wr; }
            else { o -= NW4;             s = Wo;   d = c_wo; }
            float4 vv = *((const float4*)s + o);
            *(uint2*)(d + (size_t)o * 4) = pack4(vv);
        }
    }
}

// ---------- pipelined bf16 GEMMs ----------
#define GA0 0
#define GA1 9216
#define GB0 18432
#define GB1 27136
#define GSM_BYTES (35840*2)

extern __shared__ bf gsm[];

__device__ __forceinline__ void gstage(const bf* __restrict__ A,
                                       const bf* __restrict__ W,
                                       int m0, int n0, int ks, int b) {
    int tid = threadIdx.x;
    bf* As = gsm + (b ? GA1 : GA0);
    bf* Bs = gsm + (b ? GB1 : GB0);
    #pragma unroll
    for (int p = 0; p < 4; p++) {
        int cid = tid + p * 256;
        int row = cid >> 3, cc = cid & 7;
        cpa16(smaddr(As + row * 72 + cc * 8),
              A + (size_t)(m0 + row) * Dc + ks * 64 + cc * 8);
    }
    #pragma unroll
    for (int p = 0; p < 4; p++) {
        int cid = tid + p * 256;
        int kk = cid >> 4, cc = cid & 15;
        cpa16(smaddr(Bs + kk * 136 + cc * 8),
              W + (size_t)(ks * 64 + kk) * Dc + n0 + cc * 8);
    }
    cpcommit();
}

__device__ __forceinline__ void gcompute(float4 (&c)[4][4], int wm, int wn, int b) {
    bf* As = gsm + (b ? GA1 : GA0);
    bf* Bs = gsm + (b ? GB1 : GB0);
    #pragma unroll
    for (int ks16 = 0; ks16 < 4; ks16++) {
        int kb = ks16 * 16;
        uint4 a0 = ldsm4(adrA(As, 72, wm * 64, kb));
        uint4 a1 = ldsm4(adrA(As, 72, wm * 64 + 16, kb));
        uint4 a2 = ldsm4(adrA(As, 72, wm * 64 + 32, kb));
        uint4 a3 = ldsm4(adrA(As, 72, wm * 64 + 48, kb));
        uint4 b0 = ldsm4t(adrBT(Bs, 136, kb, wn * 32));
        uint4 b1 = ldsm4t(adrBT(Bs, 136, kb, wn * 32 + 16));
        mmabf(c[0][0], a0, b0.x, b0.y); mmabf(c[0][1], a0, b0.z, b0.w);
        mmabf(c[0][2], a0, b1.x, b1.y); mmabf(c[0][3], a0, b1.z, b1.w);
        mmabf(c[1][0], a1, b0.x, b0.y); mmabf(c[1][1], a1, b0.z, b0.w);
        mmabf(c[1][2], a1, b1.x, b1.y); mmabf(c[1][3], a1, b1.z, b1.w);
        mmabf(c[2][0], a2, b0.x, b0.y); mmabf(c[2][1], a2, b0.z, b0.w);
        mmabf(c[2][2], a2, b1.x, b1.y); mmabf(c[2][3], a2, b1.z, b1.w);
        mmabf(c[3][0], a3, b0.x, b0.y); mmabf(c[3][1], a3, b0.z, b0.w);
        mmabf(c[3][2], a3, b1.x, b1.y); mmabf(c[3][3], a3, b1.z, b1.w);
    }
}

__device__ __forceinline__ void gemm_core_b(
    const bf* __restrict__ A, const bf* __restrict__ W,
    const float* __restrict__ bias, float scale, int sshift, bf* __restrict__ out) {
    int tid = threadIdx.x, l = tid & 31, g = l >> 2, t = l & 3, w = tid >> 5;
    int wm = w & 1, wn = w >> 1;
    int m0 = blockIdx.y * 128, n0 = blockIdx.x * 128;
    int Srows = 1 << sshift;

    float4 c[4][4];
    #pragma unroll
    for (int i = 0; i < 4; i++)
        #pragma unroll
        for (int j = 0; j < 4; j++) c[i][j] = make_float4(0.f, 0.f, 0.f, 0.f);

    gstage(A, W, m0, n0, 0, 0);
    for (int ks = 0; ks < 12; ks++) {
        int b = ks & 1;
        if (ks < 11) { gstage(A, W, m0, n0, ks + 1, b ^ 1); cpwait1(); }
        else cpwait0();
        __syncthreads();
        gcompute(c, wm, wn, b);
        __syncthreads();
    }
    #pragma unroll
    for (int mi = 0; mi < 4; mi++) {
        #pragma unroll
        for (int nt = 0; nt < 4; nt++) {
            int col = n0 + wn * 32 + nt * 8 + 2 * t;
            float b0f = bias ? __ldg(bias + col) : 0.f;
            float b1f = bias ? __ldg(bias + col + 1) : 0.f;
            int nn = col >> 6, hh = col & 63;
            #pragma unroll
            for (int r = 0; r < 2; r++) {
                int row = m0 + wm * 64 + mi * 16 + g + r * 8;
                int bb = row >> sshift, ss = row & (Srows - 1);
                float v0 = (r ? c[mi][nt].z : c[mi][nt].x) * scale + b0f;
                float v1 = (r ? c[mi][nt].w : c[mi][nt].y) * scale + b1f;
                *(uint*)(out + (((size_t)bb * Nc + nn) * Srows + ss) * Hc + hh) =
                    bfpair(v0, v1);
            }
        }
    }
}

__global__ __launch_bounds__(256)
void gemm_in(const float* bk, const float* bv) {
    int z = blockIdx.z;
    if (z == 0)      gemm_core_b(c_q, c_wq, nullptr, SCALE, 10, g_qh);
    else if (z == 1) gemm_core_b(c_k, c_wk, bk, 1.f, 10, g_kh);
    else if (z == 2) gemm_core_b(c_v, c_wv, bv, 1.f, 10, g_vh);
    else if (blockIdx.y < 16) gemm_core_b(c_p, c_wr, nullptr, 1.f, 11, g_rh);
}

// ---------- output GEMM + residual ----------
__global__ __launch_bounds__(256)
void gemm_out_b(const float* __restrict__ bo, const float* __restrict__ query) {
    int tid = threadIdx.x, l = tid & 31, g = l >> 2, t = l & 3, w = tid >> 5;
    int wm = w & 1, wn = w >> 1;
    int m0 = blockIdx.y * 128, n0 = blockIdx.x * 128;

    float4 c[4][4];
    #pragma unroll
    for (int i = 0; i < 4; i++)
        #pragma unroll
        for (int j = 0; j < 4; j++) c[i][j] = make_float4(0.f, 0.f, 0.f, 0.f);

    auto stage = [&](int ks, int b) {
        bf* As = gsm + (b ? GA1 : GA0);
        bf* Bs = gsm + (b ? GB1 : GB0);
        #pragma unroll
        for (int p = 0; p < 4; p++) {
            int cid = tid + p * 256;
            int row = cid >> 3, cc = cid & 7;
            int rg = m0 + row;
            cpa16(smaddr(As + row * 72 + cc * 8),
                  g_av + (((size_t)(rg >> 10) * Nc + ks) * Sc + (rg & 1023)) * Hc + cc * 8);
        }
        #pragma unroll
        for (int p = 0; p < 4; p++) {
            int cid = tid + p * 256;
            int kk = cid >> 4, cc = cid & 15;
            cpa16(smaddr(Bs + kk * 136 + cc * 8),
                  c_wo + (size_t)(ks * 64 + kk) * Dc + n0 + cc * 8);
        }
        cpcommit();
    };

    stage(0, 0);
    for (int ks = 0; ks < 12; ks++) {
        int b = ks & 1;
        if (ks < 11) { stage(ks + 1, b ^ 1); cpwait1(); }
        else cpwait0();
        __syncthreads();
        gcompute(c, wm, wn, b);
        __syncthreads();
    }
    #pragma unroll
    for (int mi = 0; mi < 4; mi++) {
        #pragma unroll
        for (int nt = 0; nt < 4; nt++) {
            int col = n0 + wn * 32 + nt * 8 + 2 * t;
            float b0f = __ldg(bo + col), b1f = __ldg(bo + col + 1);
            #pragma unroll
            for (int r = 0; r < 2; r++) {
                int row = m0 + wm * 64 + mi * 16 + g + r * 8;
                float2 q = *(const float2*)(query + (size_t)row * Dc + col);
                float v0 = (r ? c[mi][nt].z : c[mi][nt].x) + b0f + q.x;
                float v1 = (r ? c[mi][nt].w : c[mi][nt].y) + b1f + q.y;
                *(float2*)(g_x + (size_t)row * Dc + col) = make_float2(v0, v1);
            }
        }
    }
}

// ---------- fused attention ----------
#define OQ    0
#define OK0   4608
#define OK1   9216
#define OV    13824
#define OP    18432
#define ORS0  23040
#define ORS1  32256
#define OCLS  41472
#define OPW   46080
#define ORW   53248
#define ORR   53312
#define FOFF  53376
#define SMEM_ATTN (53376*2 + (128 + 64 + 128 + 128 + 128)*4)

extern __shared__ bf smb[];
__global__ __launch_bounds__(256)
void attn_kernel(const float* __restrict__ rwb, const float* __restrict__ rrb,
                 const float* __restrict__ rsb, const float* __restrict__ seg) {
    bf* sq   = smb + OQ;
    bf* sv   = smb + OV;
    bf* sp   = smb + OP;
    bf* scls = smb + OCLS;
    bf* rwbs = smb + ORW;
    bf* rrbs = smb + ORR;
    uint*  sttb = (uint*)(smb + FOFF);
    float* samk = (float*)(sttb + 128);
    float* sttd = samk + 64;
    float* mpart = sttd + 128;
    float* lpart = mpart + 128;

    int tid = threadIdx.x, l = tid & 31, g = l >> 2, t = l & 3, w = tid >> 5;
    int mt = w >> 1, nh = w & 1;
    int mtb = mt * 16;
    int i0 = blockIdx.x * 64, n = blockIdx.y, b = blockIdx.z;

    const bf* qbase = g_qh + (((size_t)b*Nc + n)*Sc + i0) * Hc;
    const bf* kbase = g_kh + (((size_t)b*Nc + n)*Sc) * Hc;
    const bf* vbase = g_vh + (((size_t)b*Nc + n)*Sc) * Hc;
    const bf* rbase = g_rh + (size_t)n * Rc * Hc;

    #pragma unroll
    for (int p = 0; p < 2; p++) {
        int cid = tid + p * 256;
        int row = cid >> 3, c16 = cid & 7;
        cpa16(smaddr(sq + row * 72) + c16 * 16, qbase + (size_t)row * Hc + c16 * 8);
        cpa16(smaddr(smb + OK0 + row * 72) + c16 * 16,
              kbase + (size_t)row * Hc + c16 * 8);
    }
    {
        int tb_ = Sc - i0 - 63;
        #pragma unroll
        for (int p = 0; p < 4; p++) {
            int cid = tid + p * 256;
            int row = cid >> 3, c16 = cid & 7;
            int tt2 = tb_ + row;
            int sz = ((unsigned)tt2 < Rc) ? 16 : 0;
            cpa16z(smaddr(smb + ORS0 + row * 72) + c16 * 16,
                   rbase + (size_t)(tt2 & 2047) * Hc + c16 * 8, sz);
        }
    }
    cpcommit();
    if (tid < 64) {
        rwbs[tid] = __float2bfloat16(rwb[n * Hc + tid] * SCALE);
        rrbs[tid] = __float2bfloat16(rrb[n * Hc + tid] * SCALE);
    }

    float4 of[4];
    #pragma unroll
    for (int nt = 0; nt < 4; nt++) of[nt] = make_float4(0.f, 0.f, 0.f, 0.f);
    float m0r = -3.0e38f, m1r = -3.0e38f, l0r = 0.f, l1r = 0.f;

    int vmin = nh * 32 - mtb + 48;
    int u0 = mtb + g, u1 = u0 + 8;
    bf* pwb = smb + OPW + w * (16 * 56);

    for (int t16 = 0; t16 < 16; t16++) {
        int j0 = t16 * 64;
        int p = t16 & 1;
        bf* skp  = smb + (p ? OK1 : OK0);
        bf* srsp = smb + (p ? ORS1 : ORS0);

        __syncthreads();   // (1)
        #pragma unroll
        for (int q_ = 0; q_ < 2; q_++) {
            int cid = tid + q_ * 256;
            int row = cid >> 3, c16 = cid & 7;
            cpa16(smaddr(sv + row * 72) + c16 * 16,
                  vbase + (size_t)(j0 + row) * Hc + c16 * 8);
            cpa16(smaddr(scls + row * 72) + c16 * 16,
                  g_cls + (size_t)(i0 + row) * Sc + j0 + c16 * 8);
        }
        if (tid < 64)
            cpa8(smaddr(sttb) + tid * 8,
                 g_ttb + ((size_t)(b * Sc + i0 + tid) * 32 + (j0 >> 5)));
        if (tid < 16)
            cpa16(smaddr(samk) + tid * 16, g_mk + b * Sc + j0 + tid * 4);
        cpcommit();

        cpwait1();          // A_t
        __syncthreads();    // (3)

        // fused tt computation (once, from staged sq)
        if (t16 == 0 && tid < 128) {
            int u = tid >> 1, sel = tid & 1;
            const float* segp = seg + (sel * Nc + n) * Hc;
            const float* rsbp = rsb + n * Hc;
            float acc = 0.f;
            #pragma unroll
            for (int h = 0; h < 64; h++) {
                float qv = __bfloat162float(sq[u * 72 + h]) + rsbp[h] * SCALE;
                acc += qv * segp[h];
            }
            sttd[2 * u + sel] = acc;
        }

        // prefetch A_{t+1}
        {
            int j0n = j0 + 64;
            if (j0n < Sc) {
                bf* dK = smb + (p ? OK0 : OK1);
                bf* dR = smb + (p ? ORS0 : ORS1);
                #pragma unroll
                for (int q_ = 0; q_ < 2; q_++) {
                    int cid = tid + q_ * 256;
                    int row = cid >> 3, c16 = cid & 7;
                    cpa16(smaddr(dK + row * 72) + c16 * 16,
                          kbase + (size_t)(j0n + row) * Hc + c16 * 8);
                }
                int tb_ = Sc - i0 - 63 + j0n;
                #pragma unroll
                for (int q_ = 0; q_ < 4; q_++) {
                    int cid = tid + q_ * 256;
                    int row = cid >> 3, c16 = cid & 7;
                    int tt2 = tb_ + row;
                    int sz = ((unsigned)tt2 < Rc) ? 16 : 0;
                    cpa16z(smaddr(dR + row * 72) + c16 * 16,
                           rbase + (size_t)(tt2 & 2047) * Hc + c16 * 8, sz);
                }
            }
            cpcommit();
        }

        float4 sc[4], pf[6];
        #pragma unroll
        for (int q_ = 0; q_ < 4; q_++) sc[q_] = make_float4(0.f, 0.f, 0.f, 0.f);
        #pragma unroll
        for (int q_ = 0; q_ < 6; q_++) pf[q_] = make_float4(0.f, 0.f, 0.f, 0.f);
        #pragma unroll
        for (int ks = 0; ks < 4; ks++) {
            int kb = ks * 16;
            uint4 qa = ldsm4(adrA(sq, 72, mtb, kb));
            uint rw0 = *(const uint*)(rwbs + kb + 2 * t);
            uint rw1 = *(const uint*)(rwbs + kb + 2 * t + 8);
            uint rr0 = *(const uint*)(rrbs + kb + 2 * t);
            uint rr1 = *(const uint*)(rrbs + kb + 2 * t + 8);
            uint4 aw, ar;
            aw.x = addb2(qa.x, rw0); aw.y = addb2(qa.y, rw0);
            aw.z = addb2(qa.z, rw1); aw.w = addb2(qa.w, rw1);
            ar.x = addb2(qa.x, rr0); ar.y = addb2(qa.y, rr0);
            ar.z = addb2(qa.z, rr1); ar.w = addb2(qa.w, rr1);
            uint4 bk0 = ldsm4(adrB(skp, 72, nh * 32, kb));
            uint4 bk1 = ldsm4(adrB(skp, 72, nh * 32 + 16, kb));
            mmabf(sc[0], aw, bk0.x, bk0.y); mmabf(sc[1], aw, bk0.z, bk0.w);
            mmabf(sc[2], aw, bk1.x, bk1.y); mmabf(sc[3], aw, bk1.z, bk1.w);
            uint4 br0 = ldsm4(adrB(srsp, 72, vmin, kb));
            uint4 br1 = ldsm4(adrB(srsp, 72, vmin + 16, kb));
            uint4 br2 = ldsm4(adrB(srsp, 72, vmin + 32, kb));
            mmabf(pf[0], ar, br0.x, br0.y); mmabf(pf[1], ar, br0.z, br0.w);
            mmabf(pf[2], ar, br1.x, br1.y); mmabf(pf[3], ar, br1.z, br1.w);
            mmabf(pf[4], ar, br2.x, br2.y); mmabf(pf[5], ar, br2.z, br2.w);
        }
        #pragma unroll
        for (int q_ = 0; q_ < 6; q_++) {
            *(uint*)(pwb + g * 56 + q_ * 8 + 2 * t)       = bfpair(pf[q_].x, pf[q_].y);
            *(uint*)(pwb + (g + 8) * 56 + q_ * 8 + 2 * t) = bfpair(pf[q_].z, pf[q_].w);
        }
        __syncwarp();

        cpwait1();          // B_t
        __syncthreads();    // (6)

        float td0 = sttd[2*u0], ts0 = sttd[2*u0+1];
        float td1 = sttd[2*u1], ts1 = sttd[2*u1+1];
        uint tb0 = sttb[u0 * 2 + nh];
        uint tb1 = sttb[u1 * 2 + nh];
        float mr0 = -3.0e38f, mr1 = -3.0e38f;
        #pragma unroll
        for (int nt = 0; nt < 4; nt++) {
            int jl = nh * 32 + nt * 8 + 2 * t;
            int sh = nt * 8 + 2 * t;
            float mk0 = samk[jl], mk1 = samk[jl + 1];
            uint cu0 = *(const uint*)(scls + u0 * 72 + jl);
            uint cu1 = *(const uint*)(scls + u1 * 72 + jl);
            float2 cl0 = __bfloat1622float2(*(__nv_bfloat162*)&cu0);
            float2 cl1 = __bfloat1622float2(*(__nv_bfloat162*)&cu1);
            int vc0 = nt * 8 + 2 * t - g + 15;
            int vc1 = vc0 - 8;
            float p00 = __bfloat162float(pwb[g * 56 + vc0]);
            float p01 = __bfloat162float(pwb[g * 56 + vc0 + 1]);
            float p10 = __bfloat162float(pwb[(g + 8) * 56 + vc1]);
            float p11 = __bfloat162float(pwb[(g + 8) * 56 + vc1 + 1]);
            float tv00 = ((tb0 >> sh) & 1)       ? ts0 : td0;
            float tv01 = ((tb0 >> (sh + 1)) & 1) ? ts0 : td0;
            float tv10 = ((tb1 >> sh) & 1)       ? ts1 : td1;
            float tv11 = ((tb1 >> (sh + 1)) & 1) ? ts1 : td1;
            sc[nt].x += cl0.x * (p00 + tv00) - mk0;
            sc[nt].y += cl0.y * (p01 + tv01) - mk1;
            sc[nt].z += cl1.x * (p10 + tv10) - mk0;
            sc[nt].w += cl1.y * (p11 + tv11) - mk1;
            mr0 = fmaxf(mr0, fmaxf(sc[nt].x, sc[nt].y));
            mr1 = fmaxf(mr1, fmaxf(sc[nt].z, sc[nt].w));
        }
        mr0 = fmaxf(mr0, __shfl_xor_sync(~0u, mr0, 1));
        mr0 = fmaxf(mr0, __shfl_xor_sync(~0u, mr0, 2));
        mr1 = fmaxf(mr1, __shfl_xor_sync(~0u, mr1, 1));
        mr1 = fmaxf(mr1, __shfl_xor_sync(~0u, mr1, 2));
        float ls0 = 0.f, ls1 = 0.f;
        #pragma unroll
        for (int nt = 0; nt < 4; nt++) {
            sc[nt].x = __expf(sc[nt].x - mr0); sc[nt].y = __expf(sc[nt].y - mr0);
            sc[nt].z = __expf(sc[nt].z - mr1); sc[nt].w = __expf(sc[nt].w - mr1);
            ls0 += sc[nt].x + sc[nt].y; ls1 += sc[nt].z + sc[nt].w;
        }
        ls0 += __shfl_xor_sync(~0u, ls0, 1); ls0 += __shfl_xor_sync(~0u, ls0, 2);
        ls1 += __shfl_xor_sync(~0u, ls1, 1); ls1 += __shfl_xor_sync(~0u, ls1, 2);
        if (t == 0) {
            mpart[nh * 64 + u0] = mr0; mpart[nh * 64 + u1] = mr1;
            lpart[nh * 64 + u0] = ls0; lpart[nh * 64 + u1] = ls1;
        }
        __syncthreads();   // C

        float a0m = mpart[u0], b0m = mpart[64 + u0];
        float a1m = mpart[u1], b1m = mpart[64 + u1];
        float mn0 = fmaxf(m0r, fmaxf(a0m, b0m));
        float mn1 = fmaxf(m1r, fmaxf(a1m, b1m));
        float co0 = __expf(m0r - mn0), co1 = __expf(m1r - mn1);
        l0r = l0r * co0 + lpart[u0] * __expf(a0m - mn0) + lpart[64 + u0] * __expf(b0m - mn0);
        l1r = l1r * co1 + lpart[u1] * __expf(a1m - mn1) + lpart[64 + u1] * __expf(b1m - mn1);
        m0r = mn0; m1r = mn1;
        float f0 = __expf((nh ? b0m : a0m) - mn0);
        float f1 = __expf((nh ? b1m : a1m) - mn1);
        #pragma unroll
        for (int nt = 0; nt < 4; nt++) {
            int jl = nh * 32 + nt * 8 + 2 * t;
            *(uint*)(sp + u0 * 72 + jl) = bfpair(sc[nt].x * f0, sc[nt].y * f0);
            *(uint*)(sp + u1 * 72 + jl) = bfpair(sc[nt].z * f1, sc[nt].w * f1);
        }
        #pragma unroll
        for (int nt = 0; nt < 4; nt++) {
            of[nt].x *= co0; of[nt].y *= co0;
            of[nt].z *= co1; of[nt].w *= co1;
        }
        __syncthreads();   // D

        #pragma unroll
        for (int ks = 0; ks < 4; ks++) {
            int kb = ks * 16;
            uint4 ap = ldsm4(adrA(sp, 72, mtb, kb));
            uint4 v0 = ldsm4t(adrBT(sv, 72, kb, nh * 32));
            uint4 v1 = ldsm4t(adrBT(sv, 72, kb, nh * 32 + 16));
            mmabf(of[0], ap, v0.x, v0.y); mmabf(of[1], ap, v0.z, v0.w);
            mmabf(of[2], ap, v1.x, v1.y); mmabf(of[3], ap, v1.z, v1.w);
        }
    }

    float inv0 = 1.f / l0r, inv1 = 1.f / l1r;
    bf* outb = g_av + (((size_t)b*Nc + n)*Sc + i0) * Hc;
    #pragma unroll
    for (int nt = 0; nt < 4; nt++) {
        int h = nh * 32 + nt * 8 + 2 * t;
        *(uint*)(outb + (size_t)u0 * Hc + h) = bfpair(of[nt].x * inv0, of[nt].y * inv0);
        *(uint*)(outb + (size_t)u1 * Hc + h) = bfpair(of[nt].z * inv1, of[nt].w * inv1);
    }
}

// ---------- LayerNorm ----------
__global__ __launch_bounds__(256)
void ln_kernel(const float* __restrict__ lng, const float* __restrict__ lnb,
               float* __restrict__ out) {
    __shared__ float red[8];
    __shared__ float stat;
    int row = blockIdx.x;
    const float* x = &g_x[(size_t)row * Dc];
    int t = threadIdx.x;
    float v[3];
    float s = 0.f;
    #pragma unroll
    for (int p = 0; p < 3; p++) { v[p] = x[t + p*256]; s += v[p]; }
    #pragma unroll
    for (int off = 16; off; off >>= 1) s += __shfl_xor_sync(~0u, s, off);
    if ((t & 31) == 0) red[t >> 5] = s;
    __syncthreads();
    if (t < 32) {
        float r = (t < 8) ? red[t] : 0.f;
        #pragma unroll
        for (int off = 4; off; off >>= 1) r += __shfl_xor_sync(~0u, r, off);
        if (t == 0) stat = r * (1.f / Dc);
    }
    __syncthreads();
    float mu = stat;
    float s2 = 0.f;
    #pragma unroll
    for (int p = 0; p < 3; p++) { float d = v[p] - mu; s2 += d*d; }
    #pragma unroll
    for (int off = 16; off; off >>= 1) s2 += __shfl_xor_sync(~0u, s2, off);
    if ((t & 31) == 0) red[t >> 5] = s2;
    __syncthreads();
    if (t < 32) {
        float r = (t < 8) ? red[t] : 0.f;
        #pragma unroll
        for (int off = 4; off; off >>= 1) r += __shfl_xor_sync(~0u, r, off);
        if (t == 0) stat = rsqrtf(r * (1.f / Dc) + EPSV);
    }
    __syncthreads();
    float rstd = stat;
    #pragma unroll
    for (int p = 0; p < 3; p++) {
        int i = t + p*256;
        out[(size_t)row*Dc + i] = (v[p] - mu) * rstd * lng[i] + lnb[i];
    }
}

// ---------- launch ----------
extern "C" void kernel_launch(void* const* d_in, const int* in_sizes, int n_in,
                              void* d_out, int out_size) {
    const float* query = (const float*)d_in[0];
    const float* key   = (const float*)d_in[1];
    const float* value = (const float*)d_in[2];
    const float* pose  = (const float*)d_in[3];
    const unsigned char* ttm = (const unsigned char*)d_in[4];
    const float* amask = (const float*)d_in[5];
    const float* clsm  = (const float*)d_in[6];
    const float* Wq    = (const float*)d_in[7];
    const float* Wk    = (const float*)d_in[8];
    const float* bk    = (const float*)d_in[9];
    const float* Wv    = (const float*)d_in[10];
    const float* bv    = (const float*)d_in[11];
    const float* rwb   = (const float*)d_in[12];
    const float* rrb   = (const float*)d_in[13];
    const float* rker  = (const float*)d_in[14];
    const float* rsb   = (const float*)d_in[15];
    const float* seg   = (const float*)d_in[16];
    const float* Wo    = (const float*)d_in[17];
    const float* bo    = (const float*)d_in[18];
    const float* lng   = (const float*)d_in[19];
    const float* lnb   = (const float*)d_in[20];
    float* out = (float*)d_out;

    dim3 blk(256);
    setup<<<Bc*Sc + 4096, blk>>>(ttm, clsm, amask,
                                 query, key, value, pose, Wq, Wk, Wv, rker, Wo);

    cudaFuncSetAttribute(gemm_in, cudaFuncAttributeMaxDynamicSharedMemorySize,
                         GSM_BYTES);
    gemm_in<<<dim3(6, 32, 4), blk, GSM_BYTES>>>(bk, bv);

    cudaFuncSetAttribute(attn_kernel, cudaFuncAttributeMaxDynamicSharedMemorySize,
                         SMEM_ATTN);
    attn_kernel<<<dim3(Sc/64, Nc, Bc), blk, SMEM_ATTN>>>(rwb, rrb, rsb, seg);

    cudaFuncSetAttribute(gemm_out_b, cudaFuncAttributeMaxDynamicSharedMemorySize,
                         GSM_BYTES);
    gemm_out_b<<<dim3(6, 32), blk, GSM_BYTES>>>(bo, query);

    ln_kernel<<<Bc*Sc, blk>>>(lng, lnb, out);
}

// round 13
// speedup vs baseline: 2.4053x; 1.0349x over previous
#include <cuda_runtime.h>
#include <cuda_bf16.h>
#include <math.h>

#define Bc 4
#define Sc 1024
#define Dc 768
#define Nc 12
#define Hc 64
#define Rc 2048
#define SCALE 0.125f
#define INFV 1000000.0f
#define EPSV 1e-9f

typedef unsigned int uint;
typedef __nv_bfloat16 bf;

__device__ __align__(16) bf    g_qh[Bc*Nc*Sc*Hc];
__device__ __align__(16) bf    g_kh[Bc*Nc*Sc*Hc];
__device__ __align__(16) bf    g_vh[Bc*Nc*Sc*Hc];
__device__ __align__(16) bf    g_rh[Nc*Rc*Hc];
__device__ __align__(16) bf    g_av[Bc*Nc*Sc*Hc];
__device__ float g_x [Bc*Sc*Dc];
__device__ __align__(16) bf    g_cls[Sc*Sc];
__device__ __align__(16) uint  g_ttb[Bc*Sc*32];
__device__ __align__(16) float g_mk [Bc*Sc];
// bf16 copies of inputs
__device__ __align__(16) bf c_q [Bc*Sc*Dc];
__device__ __align__(16) bf c_k [Bc*Sc*Dc];
__device__ __align__(16) bf c_v [Bc*Sc*Dc];
__device__ __align__(16) bf c_p [Rc*Dc];
__device__ __align__(16) bf c_wq[Dc*Dc];
__device__ __align__(16) bf c_wk[Dc*Dc];
__device__ __align__(16) bf c_wv[Dc*Dc];
__device__ __align__(16) bf c_wr[Dc*Dc];
__device__ __align__(16) bf c_wo[Dc*Dc];

// ---------- helpers ----------
__device__ __forceinline__ uint smaddr(const void* p) {
    return (uint)__cvta_generic_to_shared(p);
}
__device__ __forceinline__ void cpa16(uint sa, const void* g) {
    asm volatile("cp.async.cg.shared.global [%0], [%1], 16;"
        :: "r"(sa), "l"(__cvta_generic_to_global(g)));
}
__device__ __forceinline__ void cpa16z(uint sa, const void* g, int sz) {
    asm volatile("cp.async.cg.shared.global [%0], [%1], 16, %2;"
        :: "r"(sa), "l"(__cvta_generic_to_global(g)), "r"(sz));
}
__device__ __forceinline__ void cpa8(uint sa, const void* g) {
    asm volatile("cp.async.ca.shared.global [%0], [%1], 8;"
        :: "r"(sa), "l"(__cvta_generic_to_global(g)));
}
__device__ __forceinline__ void cpcommit() {
    asm volatile("cp.async.commit_group;" ::: "memory");
}
__device__ __forceinline__ void cpwait1() {
    asm volatile("cp.async.wait_group 1;" ::: "memory");
}
__device__ __forceinline__ void cpwait0() {
    asm volatile("cp.async.wait_group 0;" ::: "memory");
}
__device__ __forceinline__ uint4 ldsm4(uint a) {
    uint4 r;
    asm volatile("ldmatrix.sync.aligned.m8n8.x4.shared.b16 {%0,%1,%2,%3},[%4];"
        : "=r"(r.x), "=r"(r.y), "=r"(r.z), "=r"(r.w) : "r"(a));
    return r;
}
__device__ __forceinline__ uint4 ldsm4t(uint a) {
    uint4 r;
    asm volatile("ldmatrix.sync.aligned.m8n8.x4.trans.shared.b16 {%0,%1,%2,%3},[%4];"
        : "=r"(r.x), "=r"(r.y), "=r"(r.z), "=r"(r.w) : "r"(a));
    return r;
}
__device__ __forceinline__ uint adrA(const bf* b, int ld, int row0, int kb) {
    int l = threadIdx.x & 31;
    return smaddr(b + (row0 + (l & 15)) * ld + kb + ((l >> 4) << 3));
}
__device__ __forceinline__ uint adrB(const bf* b, int ld, int nb, int kb) {
    int l = threadIdx.x & 31;
    return smaddr(b + (nb + (l & 7) + ((l & 16) >> 1)) * ld + kb + (l & 8));
}
__device__ __forceinline__ uint adrBT(const bf* b, int ld, int kb, int nb) {
    int l = threadIdx.x & 31;
    return smaddr(b + (kb + (l & 7) + (l & 8)) * ld + nb + ((l & 16) >> 1));
}
__device__ __forceinline__ void mmabf(float4& c, uint4 a, uint b0, uint b1) {
    asm volatile(
        "mma.sync.aligned.m16n8k16.row.col.f32.bf16.bf16.f32 "
        "{%0,%1,%2,%3},{%4,%5,%6,%7},{%8,%9},{%0,%1,%2,%3};"
        : "+f"(c.x), "+f"(c.y), "+f"(c.z), "+f"(c.w)
        : "r"(a.x), "r"(a.y), "r"(a.z), "r"(a.w), "r"(b0), "r"(b1));
}
__device__ __forceinline__ uint bfpair(float lo, float hi) {
    uint r; asm("cvt.rn.bf16x2.f32 %0,%1,%2;" : "=r"(r) : "f"(hi), "f"(lo));
    return r;
}
__device__ __forceinline__ uint addb2(uint a, uint b) {
    uint r; asm("add.rn.bf16x2 %0,%1,%2;" : "=r"(r) : "r"(a), "r"(b));
    return r;
}
__device__ __forceinline__ uint2 pack4(float4 v) {
    uint2 r; r.x = bfpair(v.x, v.y); r.y = bfpair(v.z, v.w); return r;
}

// ---------- setup: cb (blocks < 4096) + prep (blocks >= 4096) ----------
__global__ __launch_bounds__(256)
void setup(const unsigned char* __restrict__ ttm,
           const float* __restrict__ clsm,
           const float* __restrict__ amask,
           const float* q, const float* k, const float* v, const float* pose,
           const float* Wq, const float* Wk, const float* Wv,
           const float* rk, const float* Wo) {
    int tid = threadIdx.x;
    if (blockIdx.x < Bc*Sc) {
        int r = blockIdx.x;
        int w = tid >> 5, lane = tid & 31;
        #pragma unroll
        for (int c = 0; c < 4; c++) {
            int j = w * 128 + c * 32 + lane;
            uint m = __ballot_sync(~0u, ttm[(size_t)r * Sc + j] != 0);
            if (lane == 0) g_ttb[r * 32 + w * 4 + c] = m;
        }
        if (r < Sc) {
            int j4 = tid * 4;
            float4 c4 = *(const float4*)(clsm + (size_t)r * Sc + j4);
            *(uint2*)(g_cls + (size_t)r * Sc + j4) = pack4(c4);
        }
        if (r < 16) {
            int idx = r * 256 + tid;
            g_mk[idx] = INFV * (1.f - amask[idx]);
        }
    } else {
        const int NQ4 = Bc*Sc*Dc/4, NP4 = Rc*Dc/4, NW4 = Dc*Dc/4;
        int total = 3*NQ4 + NP4 + 5*NW4;
        int nb = gridDim.x - Bc*Sc;
        for (int i = (blockIdx.x - Bc*Sc) * 256 + tid; i < total; i += nb * 256) {
            const float* s; bf* d; int o = i;
            if (o < NQ4)               { s = q;    d = c_q;  }
            else if ((o -= NQ4) < NQ4) { s = k;    d = c_k;  }
            else if ((o -= NQ4) < NQ4) { s = v;    d = c_v;  }
            else if ((o -= NQ4) < NP4) { s = pose; d = c_p;  }
            else if ((o -= NP4) < NW4) { s = Wq;   d = c_wq; }
            else if ((o -= NW4) < NW4) { s = Wk;   d = c_wk; }
            else if ((o -= NW4) < NW4) { s = Wv;   d = c_wv; }
            else if ((o -= NW4) < NW4) { s = rk;   d = c_wr; }
            else { o -= NW4;             s = Wo;   d = c_wo; }
            float4 vv = *((const float4*)s + o);
            *(uint2*)(d + (size_t)o * 4) = pack4(vv);
        }
    }
}

// ---------- pipelined bf16 GEMMs: 128x128 tile, KC=64, 3-stage ring ----------
#define GST 17920                 // bf per stage: A 9216 + B 8704
#define GOB 9216                  // B offset within stage
#define GSM_BYTES (3*GST*2)       // 107520 bytes

extern __shared__ bf gsm[];

__device__ __forceinline__ void gstage3(const bf* __restrict__ A,
                                        const bf* __restrict__ W,
                                        int m0, int n0, int ks, int s) {
    int tid = threadIdx.x;
    bf* As = gsm + s * GST;
    bf* Bs = gsm + s * GST + GOB;
    #pragma unroll
    for (int p = 0; p < 4; p++) {
        int cid = tid + p * 256;
        int row = cid >> 3, cc = cid & 7;
        cpa16(smaddr(As + row * 72 + cc * 8),
              A + (size_t)(m0 + row) * Dc + ks * 64 + cc * 8);
    }
    #pragma unroll
    for (int p = 0; p < 4; p++) {
        int cid = tid + p * 256;
        int kk = cid >> 4, cc = cid & 15;
        cpa16(smaddr(Bs + kk * 136 + cc * 8),
              W + (size_t)(ks * 64 + kk) * Dc + n0 + cc * 8);
    }
    cpcommit();
}

__device__ __forceinline__ void gcompute(float4 (&c)[4][4], int wm, int wn, int s) {
    bf* As = gsm + s * GST;
    bf* Bs = gsm + s * GST + GOB;
    #pragma unroll
    for (int ks16 = 0; ks16 < 4; ks16++) {
        int kb = ks16 * 16;
        uint4 a0 = ldsm4(adrA(As, 72, wm * 64, kb));
        uint4 a1 = ldsm4(adrA(As, 72, wm * 64 + 16, kb));
        uint4 a2 = ldsm4(adrA(As, 72, wm * 64 + 32, kb));
        uint4 a3 = ldsm4(adrA(As, 72, wm * 64 + 48, kb));
        uint4 b0 = ldsm4t(adrBT(Bs, 136, kb, wn * 32));
        uint4 b1 = ldsm4t(adrBT(Bs, 136, kb, wn * 32 + 16));
        mmabf(c[0][0], a0, b0.x, b0.y); mmabf(c[0][1], a0, b0.z, b0.w);
        mmabf(c[0][2], a0, b1.x, b1.y); mmabf(c[0][3], a0, b1.z, b1.w);
        mmabf(c[1][0], a1, b0.x, b0.y); mmabf(c[1][1], a1, b0.z, b0.w);
        mmabf(c[1][2], a1, b1.x, b1.y); mmabf(c[1][3], a1, b1.z, b1.w);
        mmabf(c[2][0], a2, b0.x, b0.y); mmabf(c[2][1], a2, b0.z, b0.w);
        mmabf(c[2][2], a2, b1.x, b1.y); mmabf(c[2][3], a2, b1.z, b1.w);
        mmabf(c[3][0], a3, b0.x, b0.y); mmabf(c[3][1], a3, b0.z, b0.w);
        mmabf(c[3][2], a3, b1.x, b1.y); mmabf(c[3][3], a3, b1.z, b1.w);
    }
}

__device__ __forceinline__ void gemm_core_b(
    const bf* __restrict__ A, const bf* __restrict__ W,
    const float* __restrict__ bias, float scale, int sshift, bf* __restrict__ out) {
    int tid = threadIdx.x, l = tid & 31, g = l >> 2, t = l & 3, w = tid >> 5;
    int wm = w & 1, wn = w >> 1;
    int m0 = blockIdx.y * 128, n0 = blockIdx.x * 128;
    int Srows = 1 << sshift;

    float4 c[4][4];
    #pragma unroll
    for (int i = 0; i < 4; i++)
        #pragma unroll
        for (int j = 0; j < 4; j++) c[i][j] = make_float4(0.f, 0.f, 0.f, 0.f);

    gstage3(A, W, m0, n0, 0, 0);
    gstage3(A, W, m0, n0, 1, 1);
    int s = 0;
    for (int ks = 0; ks < 12; ks++) {
        if (ks == 11) cpwait0(); else cpwait1();
        __syncthreads();
        if (ks < 10) {
            int sn = s + 2; if (sn >= 3) sn -= 3;
            gstage3(A, W, m0, n0, ks + 2, sn);
        }
        gcompute(c, wm, wn, s);
        if (++s == 3) s = 0;
    }
    #pragma unroll
    for (int mi = 0; mi < 4; mi++) {
        #pragma unroll
        for (int nt = 0; nt < 4; nt++) {
            int col = n0 + wn * 32 + nt * 8 + 2 * t;
            float b0f = bias ? __ldg(bias + col) : 0.f;
            float b1f = bias ? __ldg(bias + col + 1) : 0.f;
            int nn = col >> 6, hh = col & 63;
            #pragma unroll
            for (int r = 0; r < 2; r++) {
                int row = m0 + wm * 64 + mi * 16 + g + r * 8;
                int bb = row >> sshift, ss = row & (Srows - 1);
                float v0 = (r ? c[mi][nt].z : c[mi][nt].x) * scale + b0f;
                float v1 = (r ? c[mi][nt].w : c[mi][nt].y) * scale + b1f;
                *(uint*)(out + (((size_t)bb * Nc + nn) * Srows + ss) * Hc + hh) =
                    bfpair(v0, v1);
            }
        }
    }
}

__global__ __launch_bounds__(256)
void gemm_in(const float* bk, const float* bv) {
    int z = blockIdx.z;
    if (z == 0)      gemm_core_b(c_q, c_wq, nullptr, SCALE, 10, g_qh);
    else if (z == 1) gemm_core_b(c_k, c_wk, bk, 1.f, 10, g_kh);
    else if (z == 2) gemm_core_b(c_v, c_wv, bv, 1.f, 10, g_vh);
    else if (blockIdx.y < 16) gemm_core_b(c_p, c_wr, nullptr, 1.f, 11, g_rh);
}

// ---------- output GEMM + residual (3-stage ring) ----------
__global__ __launch_bounds__(256)
void gemm_out_b(const float* __restrict__ bo, const float* __restrict__ query) {
    int tid = threadIdx.x, l = tid & 31, g = l >> 2, t = l & 3, w = tid >> 5;
    int wm = w & 1, wn = w >> 1;
    int m0 = blockIdx.y * 128, n0 = blockIdx.x * 128;

    float4 c[4][4];
    #pragma unroll
    for (int i = 0; i < 4; i++)
        #pragma unroll
        for (int j = 0; j < 4; j++) c[i][j] = make_float4(0.f, 0.f, 0.f, 0.f);

    auto stage = [&](int ks, int s) {
        bf* As = gsm + s * GST;
        bf* Bs = gsm + s * GST + GOB;
        #pragma unroll
        for (int p = 0; p < 4; p++) {
            int cid = tid + p * 256;
            int row = cid >> 3, cc = cid & 7;
            int rg = m0 + row;
            cpa16(smaddr(As + row * 72 + cc * 8),
                  g_av + (((size_t)(rg >> 10) * Nc + ks) * Sc + (rg & 1023)) * Hc + cc * 8);
        }
        #pragma unroll
        for (int p = 0; p < 4; p++) {
            int cid = tid + p * 256;
            int kk = cid >> 4, cc = cid & 15;
            cpa16(smaddr(Bs + kk * 136 + cc * 8),
                  c_wo + (size_t)(ks * 64 + kk) * Dc + n0 + cc * 8);
        }
        cpcommit();
    };

    stage(0, 0);
    stage(1, 1);
    int s = 0;
    for (int ks = 0; ks < 12; ks++) {
        if (ks == 11) cpwait0(); else cpwait1();
        __syncthreads();
        if (ks < 10) {
            int sn = s + 2; if (sn >= 3) sn -= 3;
            stage(ks + 2, sn);
        }
        gcompute(c, wm, wn, s);
        if (++s == 3) s = 0;
    }
    #pragma unroll
    for (int mi = 0; mi < 4; mi++) {
        #pragma unroll
        for (int nt = 0; nt < 4; nt++) {
            int col = n0 + wn * 32 + nt * 8 + 2 * t;
            float b0f = __ldg(bo + col), b1f = __ldg(bo + col + 1);
            #pragma unroll
            for (int r = 0; r < 2; r++) {
                int row = m0 + wm * 64 + mi * 16 + g + r * 8;
                float2 q = *(const float2*)(query + (size_t)row * Dc + col);
                float v0 = (r ? c[mi][nt].z : c[mi][nt].x) + b0f + q.x;
                float v1 = (r ? c[mi][nt].w : c[mi][nt].y) + b1f + q.y;
                *(float2*)(g_x + (size_t)row * Dc + col) = make_float2(v0, v1);
            }
        }
    }
}

// ---------- fused attention (unchanged from R12) ----------
#define OQ    0
#define OK0   4608
#define OK1   9216
#define OV    13824
#define OP    18432
#define ORS0  23040
#define ORS1  32256
#define OCLS  41472
#define OPW   46080
#define ORW   53248
#define ORR   53312
#define FOFF  53376
#define SMEM_ATTN (53376*2 + (128 + 64 + 128 + 128 + 128)*4)

extern __shared__ bf smb[];
__global__ __launch_bounds__(256)
void attn_kernel(const float* __restrict__ rwb, const float* __restrict__ rrb,
                 const float* __restrict__ rsb, const float* __restrict__ seg) {
    bf* sq   = smb + OQ;
    bf* sv   = smb + OV;
    bf* sp   = smb + OP;
    bf* scls = smb + OCLS;
    bf* rwbs = smb + ORW;
    bf* rrbs = smb + ORR;
    uint*  sttb = (uint*)(smb + FOFF);
    float* samk = (float*)(sttb + 128);
    float* sttd = samk + 64;
    float* mpart = sttd + 128;
    float* lpart = mpart + 128;

    int tid = threadIdx.x, l = tid & 31, g = l >> 2, t = l & 3, w = tid >> 5;
    int mt = w >> 1, nh = w & 1;
    int mtb = mt * 16;
    int i0 = blockIdx.x * 64, n = blockIdx.y, b = blockIdx.z;

    const bf* qbase = g_qh + (((size_t)b*Nc + n)*Sc + i0) * Hc;
    const bf* kbase = g_kh + (((size_t)b*Nc + n)*Sc) * Hc;
    const bf* vbase = g_vh + (((size_t)b*Nc + n)*Sc) * Hc;
    const bf* rbase = g_rh + (size_t)n * Rc * Hc;

    #pragma unroll
    for (int p = 0; p < 2; p++) {
        int cid = tid + p * 256;
        int row = cid >> 3, c16 = cid & 7;
        cpa16(smaddr(sq + row * 72) + c16 * 16, qbase + (size_t)row * Hc + c16 * 8);
        cpa16(smaddr(smb + OK0 + row * 72) + c16 * 16,
              kbase + (size_t)row * Hc + c16 * 8);
    }
    {
        int tb_ = Sc - i0 - 63;
        #pragma unroll
        for (int p = 0; p < 4; p++) {
            int cid = tid + p * 256;
            int row = cid >> 3, c16 = cid & 7;
            int tt2 = tb_ + row;
            int sz = ((unsigned)tt2 < Rc) ? 16 : 0;
            cpa16z(smaddr(smb + ORS0 + row * 72) + c16 * 16,
                   rbase + (size_t)(tt2 & 2047) * Hc + c16 * 8, sz);
        }
    }
    cpcommit();
    if (tid < 64) {
        rwbs[tid] = __float2bfloat16(rwb[n * Hc + tid] * SCALE);
        rrbs[tid] = __float2bfloat16(rrb[n * Hc + tid] * SCALE);
    }

    float4 of[4];
    #pragma unroll
    for (int nt = 0; nt < 4; nt++) of[nt] = make_float4(0.f, 0.f, 0.f, 0.f);
    float m0r = -3.0e38f, m1r = -3.0e38f, l0r = 0.f, l1r = 0.f;

    int vmin = nh * 32 - mtb + 48;
    int u0 = mtb + g, u1 = u0 + 8;
    bf* pwb = smb + OPW + w * (16 * 56);

    for (int t16 = 0; t16 < 16; t16++) {
        int j0 = t16 * 64;
        int p = t16 & 1;
        bf* skp  = smb + (p ? OK1 : OK0);
        bf* srsp = smb + (p ? ORS1 : ORS0);

        __syncthreads();   // (1)
        #pragma unroll
        for (int q_ = 0; q_ < 2; q_++) {
            int cid = tid + q_ * 256;
            int row = cid >> 3, c16 = cid & 7;
            cpa16(smaddr(sv + row * 72) + c16 * 16,
                  vbase + (size_t)(j0 + row) * Hc + c16 * 8);
            cpa16(smaddr(scls + row * 72) + c16 * 16,
                  g_cls + (size_t)(i0 + row) * Sc + j0 + c16 * 8);
        }
        if (tid < 64)
            cpa8(smaddr(sttb) + tid * 8,
                 g_ttb + ((size_t)(b * Sc + i0 + tid) * 32 + (j0 >> 5)));
        if (tid < 16)
            cpa16(smaddr(samk) + tid * 16, g_mk + b * Sc + j0 + tid * 4);
        cpcommit();

        cpwait1();          // A_t
        __syncthreads();    // (3)

        // fused tt computation (once, from staged sq)
        if (t16 == 0 && tid < 128) {
            int u = tid >> 1, sel = tid & 1;
            const float* segp = seg + (sel * Nc + n) * Hc;
            const float* rsbp = rsb + n * Hc;
            float acc = 0.f;
            #pragma unroll
            for (int h = 0; h < 64; h++) {
                float qv = __bfloat162float(sq[u * 72 + h]) + rsbp[h] * SCALE;
                acc += qv * segp[h];
            }
            sttd[2 * u + sel] = acc;
        }

        // prefetch A_{t+1}
        {
            int j0n = j0 + 64;
            if (j0n < Sc) {
                bf* dK = smb + (p ? OK0 : OK1);
                bf* dR = smb + (p ? ORS0 : ORS1);
                #pragma unroll
                for (int q_ = 0; q_ < 2; q_++) {
                    int cid = tid + q_ * 256;
                    int row = cid >> 3, c16 = cid & 7;
                    cpa16(smaddr(dK + row * 72) + c16 * 16,
                          kbase + (size_t)(j0n + row) * Hc + c16 * 8);
                }
                int tb_ = Sc - i0 - 63 + j0n;
                #pragma unroll
                for (int q_ = 0; q_ < 4; q_++) {
                    int cid = tid + q_ * 256;
                    int row = cid >> 3, c16 = cid & 7;
                    int tt2 = tb_ + row;
                    int sz = ((unsigned)tt2 < Rc) ? 16 : 0;
                    cpa16z(smaddr(dR + row * 72) + c16 * 16,
                           rbase + (size_t)(tt2 & 2047) * Hc + c16 * 8, sz);
                }
            }
            cpcommit();
        }

        float4 sc[4], pf[6];
        #pragma unroll
        for (int q_ = 0; q_ < 4; q_++) sc[q_] = make_float4(0.f, 0.f, 0.f, 0.f);
        #pragma unroll
        for (int q_ = 0; q_ < 6; q_++) pf[q_] = make_float4(0.f, 0.f, 0.f, 0.f);
        #pragma unroll
        for (int ks = 0; ks < 4; ks++) {
            int kb = ks * 16;
            uint4 qa = ldsm4(adrA(sq, 72, mtb, kb));
            uint rw0 = *(const uint*)(rwbs + kb + 2 * t);
            uint rw1 = *(const uint*)(rwbs + kb + 2 * t + 8);
            uint rr0 = *(const uint*)(rrbs + kb + 2 * t);
            uint rr1 = *(const uint*)(rrbs + kb + 2 * t + 8);
            uint4 aw, ar;
            aw.x = addb2(qa.x, rw0); aw.y = addb2(qa.y, rw0);
            aw.z = addb2(qa.z, rw1); aw.w = addb2(qa.w, rw1);
            ar.x = addb2(qa.x, rr0); ar.y = addb2(qa.y, rr0);
            ar.z = addb2(qa.z, rr1); ar.w = addb2(qa.w, rr1);
            uint4 bk0 = ldsm4(adrB(skp, 72, nh * 32, kb));
            uint4 bk1 = ldsm4(adrB(skp, 72, nh * 32 + 16, kb));
            mmabf(sc[0], aw, bk0.x, bk0.y); mmabf(sc[1], aw, bk0.z, bk0.w);
            mmabf(sc[2], aw, bk1.x, bk1.y); mmabf(sc[3], aw, bk1.z, bk1.w);
            uint4 br0 = ldsm4(adrB(srsp, 72, vmin, kb));
            uint4 br1 = ldsm4(adrB(srsp, 72, vmin + 16, kb));
            uint4 br2 = ldsm4(adrB(srsp, 72, vmin + 32, kb));
            mmabf(pf[0], ar, br0.x, br0.y); mmabf(pf[1], ar, br0.z, br0.w);
            mmabf(pf[2], ar, br1.x, br1.y); mmabf(pf[3], ar, br1.z, br1.w);
            mmabf(pf[4], ar, br2.x, br2.y); mmabf(pf[5], ar, br2.z, br2.w);
        }
        #pragma unroll
        for (int q_ = 0; q_ < 6; q_++) {
            *(uint*)(pwb + g * 56 + q_ * 8 + 2 * t)       = bfpair(pf[q_].x, pf[q_].y);
            *(uint*)(pwb + (g + 8) * 56 + q_ * 8 + 2 * t) = bfpair(pf[q_].z, pf[q_].w);
        }
        __syncwarp();

        cpwait1();          // B_t
        __syncthreads();    // (6)

        float td0 = sttd[2*u0], ts0 = sttd[2*u0+1];
        float td1 = sttd[2*u1], ts1 = sttd[2*u1+1];
        uint tb0 = sttb[u0 * 2 + nh];
        uint tb1 = sttb[u1 * 2 + nh];
        float mr0 = -3.0e38f, mr1 = -3.0e38f;
        #pragma unroll
        for (int nt = 0; nt < 4; nt++) {
            int jl = nh * 32 + nt * 8 + 2 * t;
            int sh = nt * 8 + 2 * t;
            float mk0 = samk[jl], mk1 = samk[jl + 1];
            uint cu0 = *(const uint*)(scls + u0 * 72 + jl);
            uint cu1 = *(const uint*)(scls + u1 * 72 + jl);
            float2 cl0 = __bfloat1622float2(*(__nv_bfloat162*)&cu0);
            float2 cl1 = __bfloat1622float2(*(__nv_bfloat162*)&cu1);
            int vc0 = nt * 8 + 2 * t - g + 15;
            int vc1 = vc0 - 8;
            float p00 = __bfloat162float(pwb[g * 56 + vc0]);
            float p01 = __bfloat162float(pwb[g * 56 + vc0 + 1]);
            float p10 = __bfloat162float(pwb[(g + 8) * 56 + vc1]);
            float p11 = __bfloat162float(pwb[(g + 8) * 56 + vc1 + 1]);
            float tv00 = ((tb0 >> sh) & 1)       ? ts0 : td0;
            float tv01 = ((tb0 >> (sh + 1)) & 1) ? ts0 : td0;
            float tv10 = ((tb1 >> sh) & 1)       ? ts1 : td1;
            float tv11 = ((tb1 >> (sh + 1)) & 1) ? ts1 : td1;
            sc[nt].x += cl0.x * (p00 + tv00) - mk0;
            sc[nt].y += cl0.y * (p01 + tv01) - mk1;
            sc[nt].z += cl1.x * (p10 + tv10) - mk0;
            sc[nt].w += cl1.y * (p11 + tv11) - mk1;
            mr0 = fmaxf(mr0, fmaxf(sc[nt].x, sc[nt].y));
            mr1 = fmaxf(mr1, fmaxf(sc[nt].z, sc[nt].w));
        }
        mr0 = fmaxf(mr0, __shfl_xor_sync(~0u, mr0, 1));
        mr0 = fmaxf(mr0, __shfl_xor_sync(~0u, mr0, 2));
        mr1 = fmaxf(mr1, __shfl_xor_sync(~0u, mr1, 1));
        mr1 = fmaxf(mr1, __shfl_xor_sync(~0u, mr1, 2));
        float ls0 = 0.f, ls1 = 0.f;
        #pragma unroll
        for (int nt = 0; nt < 4; nt++) {
            sc[nt].x = __expf(sc[nt].x - mr0); sc[nt].y = __expf(sc[nt].y - mr0);
            sc[nt].z = __expf(sc[nt].z - mr1); sc[nt].w = __expf(sc[nt].w - mr1);
            ls0 += sc[nt].x + sc[nt].y; ls1 += sc[nt].z + sc[nt].w;
        }
        ls0 += __shfl_xor_sync(~0u, ls0, 1); ls0 += __shfl_xor_sync(~0u, ls0, 2);
        ls1 += __shfl_xor_sync(~0u, ls1, 1); ls1 += __shfl_xor_sync(~0u, ls1, 2);
        if (t == 0) {
            mpart[nh * 64 + u0] = mr0; mpart[nh * 64 + u1] = mr1;
            lpart[nh * 64 + u0] = ls0; lpart[nh * 64 + u1] = ls1;
        }
        __syncthreads();   // C

        float a0m = mpart[u0], b0m = mpart[64 + u0];
        float a1m = mpart[u1], b1m = mpart[64 + u1];
        float mn0 = fmaxf(m0r, fmaxf(a0m, b0m));
        float mn1 = fmaxf(m1r, fmaxf(a1m, b1m));
        float co0 = __expf(m0r - mn0), co1 = __expf(m1r - mn1);
        l0r = l0r * co0 + lpart[u0] * __expf(a0m - mn0) + lpart[64 + u0] * __expf(b0m - mn0);
        l1r = l1r * co1 + lpart[u1] * __expf(a1m - mn1) + lpart[64 + u1] * __expf(b1m - mn1);
        m0r = mn0; m1r = mn1;
        float f0 = __expf((nh ? b0m : a0m) - mn0);
        float f1 = __expf((nh ? b1m : a1m) - mn1);
        #pragma unroll
        for (int nt = 0; nt < 4; nt++) {
            int jl = nh * 32 + nt * 8 + 2 * t;
            *(uint*)(sp + u0 * 72 + jl) = bfpair(sc[nt].x * f0, sc[nt].y * f0);
            *(uint*)(sp + u1 * 72 + jl) = bfpair(sc[nt].z * f1, sc[nt].w * f1);
        }
        #pragma unroll
        for (int nt = 0; nt < 4; nt++) {
            of[nt].x *= co0; of[nt].y *= co0;
            of[nt].z *= co1; of[nt].w *= co1;
        }
        __syncthreads();   // D

        #pragma unroll
        for (int ks = 0; ks < 4; ks++) {
            int kb = ks * 16;
            uint4 ap = ldsm4(adrA(sp, 72, mtb, kb));
            uint4 v0 = ldsm4t(adrBT(sv, 72, kb, nh * 32));
            uint4 v1 = ldsm4t(adrBT(sv, 72, kb, nh * 32 + 16));
            mmabf(of[0], ap, v0.x, v0.y); mmabf(of[1], ap, v0.z, v0.w);
            mmabf(of[2], ap, v1.x, v1.y); mmabf(of[3], ap, v1.z, v1.w);
        }
    }

    float inv0 = 1.f / l0r, inv1 = 1.f / l1r;
    bf* outb = g_av + (((size_t)b*Nc + n)*Sc + i0) * Hc;
    #pragma unroll
    for (int nt = 0; nt < 4; nt++) {
        int h = nh * 32 + nt * 8 + 2 * t;
        *(uint*)(outb + (size_t)u0 * Hc + h) = bfpair(of[nt].x * inv0, of[nt].y * inv0);
        *(uint*)(outb + (size_t)u1 * Hc + h) = bfpair(of[nt].z * inv1, of[nt].w * inv1);
    }
}

// ---------- LayerNorm ----------
__global__ __launch_bounds__(256)
void ln_kernel(const float* __restrict__ lng, const float* __restrict__ lnb,
               float* __restrict__ out) {
    __shared__ float red[8];
    __shared__ float stat;
    int row = blockIdx.x;
    const float* x = &g_x[(size_t)row * Dc];
    int t = threadIdx.x;
    float v[3];
    float s = 0.f;
    #pragma unroll
    for (int p = 0; p < 3; p++) { v[p] = x[t + p*256]; s += v[p]; }
    #pragma unroll
    for (int off = 16; off; off >>= 1) s += __shfl_xor_sync(~0u, s, off);
    if ((t & 31) == 0) red[t >> 5] = s;
    __syncthreads();
    if (t < 32) {
        float r = (t < 8) ? red[t] : 0.f;
        #pragma unroll
        for (int off = 4; off; off >>= 1) r += __shfl_xor_sync(~0u, r, off);
        if (t == 0) stat = r * (1.f / Dc);
    }
    __syncthreads();
    float mu = stat;
    float s2 = 0.f;
    #pragma unroll
    for (int p = 0; p < 3; p++) { float d = v[p] - mu; s2 += d*d; }
    #pragma unroll
    for (int off = 16; off; off >>= 1) s2 += __shfl_xor_sync(~0u, s2, off);
    if ((t & 31) == 0) red[t >> 5] = s2;
    __syncthreads();
    if (t < 32) {
        float r = (t < 8) ? red[t] : 0.f;
        #pragma unroll
        for (int off = 4; off; off >>= 1) r += __shfl_xor_sync(~0u, r, off);
        if (t == 0) stat = rsqrtf(r * (1.f / Dc) + EPSV);
    }
    __syncthreads();
    float rstd = stat;
    #pragma unroll
    for (int p = 0; p < 3; p++) {
        int i = t + p*256;
        out[(size_t)row*Dc + i] = (v[p] - mu) * rstd * lng[i] + lnb[i];
    }
}

// ---------- launch ----------
extern "C" void kernel_launch(void* const* d_in, const int* in_sizes, int n_in,
                              void* d_out, int out_size) {
    const float* query = (const float*)d_in[0];
    const float* key   = (const float*)d_in[1];
    const float* value = (const float*)d_in[2];
    const float* pose  = (const float*)d_in[3];
    const unsigned char* ttm = (const unsigned char*)d_in[4];
    const float* amask = (const float*)d_in[5];
    const float* clsm  = (const float*)d_in[6];
    const float* Wq    = (const float*)d_in[7];
    const float* Wk    = (const float*)d_in[8];
    const float* bk    = (const float*)d_in[9];
    const float* Wv    = (const float*)d_in[10];
    const float* bv    = (const float*)d_in[11];
    const float* rwb   = (const float*)d_in[12];
    const float* rrb   = (const float*)d_in[13];
    const float* rker  = (const float*)d_in[14];
    const float* rsb   = (const float*)d_in[15];
    const float* seg   = (const float*)d_in[16];
    const float* Wo    = (const float*)d_in[17];
    const float* bo    = (const float*)d_in[18];
    const float* lng   = (const float*)d_in[19];
    const float* lnb   = (const float*)d_in[20];
    float* out = (float*)d_out;

    dim3 blk(256);
    setup<<<Bc*Sc + 4096, blk>>>(ttm, clsm, amask,
                                 query, key, value, pose, Wq, Wk, Wv, rker, Wo);

    cudaFuncSetAttribute(gemm_in, cudaFuncAttributeMaxDynamicSharedMemorySize,
                         GSM_BYTES);
    gemm_in<<<dim3(6, 32, 4), blk, GSM_BYTES>>>(bk, bv);

    cudaFuncSetAttribute(attn_kernel, cudaFuncAttributeMaxDynamicSharedMemorySize,
                         SMEM_ATTN);
    attn_kernel<<<dim3(Sc/64, Nc, Bc), blk, SMEM_ATTN>>>(rwb, rrb, rsb, seg);

    cudaFuncSetAttribute(gemm_out_b, cudaFuncAttributeMaxDynamicSharedMemorySize,
                         GSM_BYTES);
    gemm_out_b<<<dim3(6, 32), blk, GSM_BYTES>>>(bo, query);

    ln_kernel<<<Bc*Sc, blk>>>(lng, lnb, out);
}

// round 15
// speedup vs baseline: 2.7805x; 1.1560x over previous
#include <cuda_runtime.h>
#include <cuda_bf16.h>
#include <math.h>

#define Bc 4
#define Sc 1024
#define Dc 768
#define Nc 12
#define Hc 64
#define Rc 2048
#define SCALE 0.125f
#define INFV 1000000.0f
#define EPSV 1e-9f

typedef unsigned int uint;
typedef __nv_bfloat16 bf;

__device__ __align__(16) bf    g_qh[Bc*Nc*Sc*Hc];
__device__ __align__(16) bf    g_kh[Bc*Nc*Sc*Hc];
__device__ __align__(16) bf    g_vh[Bc*Nc*Sc*Hc];
__device__ __align__(16) bf    g_rh[Nc*Rc*Hc];
__device__ __align__(16) bf    g_av[Bc*Nc*Sc*Hc];
__device__ float g_x [Bc*Sc*Dc];
__device__ __align__(16) bf    g_cls[Sc*Sc];
__device__ __align__(16) uint  g_ttb[Bc*Sc*32];
__device__ __align__(16) float g_mk [Bc*Sc];
__device__ __align__(16) bf c_q [Bc*Sc*Dc];
__device__ __align__(16) bf c_k [Bc*Sc*Dc];
__device__ __align__(16) bf c_v [Bc*Sc*Dc];
__device__ __align__(16) bf c_p [Rc*Dc];
__device__ __align__(16) bf c_wq[Dc*Dc];
__device__ __align__(16) bf c_wk[Dc*Dc];
__device__ __align__(16) bf c_wv[Dc*Dc];
__device__ __align__(16) bf c_wr[Dc*Dc];
__device__ __align__(16) bf c_wo[Dc*Dc];

// ---------- helpers ----------
__device__ __forceinline__ uint smaddr(const void* p) {
    return (uint)__cvta_generic_to_shared(p);
}
__device__ __forceinline__ void cpa16(uint sa, const void* g) {
    asm volatile("cp.async.cg.shared.global [%0], [%1], 16;"
        :: "r"(sa), "l"(__cvta_generic_to_global(g)));
}
__device__ __forceinline__ void cpa16z(uint sa, const void* g, int sz) {
    asm volatile("cp.async.cg.shared.global [%0], [%1], 16, %2;"
        :: "r"(sa), "l"(__cvta_generic_to_global(g)), "r"(sz));
}
__device__ __forceinline__ void cpa8(uint sa, const void* g) {
    asm volatile("cp.async.ca.shared.global [%0], [%1], 8;"
        :: "r"(sa), "l"(__cvta_generic_to_global(g)));
}
__device__ __forceinline__ void cpcommit() {
    asm volatile("cp.async.commit_group;" ::: "memory");
}
__device__ __forceinline__ void cpwait1() {
    asm volatile("cp.async.wait_group 1;" ::: "memory");
}
__device__ __forceinline__ void cpwait0() {
    asm volatile("cp.async.wait_group 0;" ::: "memory");
}
__device__ __forceinline__ uint4 ldsm4(uint a) {
    uint4 r;
    asm volatile("ldmatrix.sync.aligned.m8n8.x4.shared.b16 {%0,%1,%2,%3},[%4];"
        : "=r"(r.x), "=r"(r.y), "=r"(r.z), "=r"(r.w) : "r"(a));
    return r;
}
__device__ __forceinline__ uint4 ldsm4t(uint a) {
    uint4 r;
    asm volatile("ldmatrix.sync.aligned.m8n8.x4.trans.shared.b16 {%0,%1,%2,%3},[%4];"
        : "=r"(r.x), "=r"(r.y), "=r"(r.z), "=r"(r.w) : "r"(a));
    return r;
}
__device__ __forceinline__ uint adrA(const bf* b, int ld, int row0, int kb) {
    int l = threadIdx.x & 31;
    return smaddr(b + (row0 + (l & 15)) * ld + kb + ((l >> 4) << 3));
}
__device__ __forceinline__ uint adrB(const bf* b, int ld, int nb, int kb) {
    int l = threadIdx.x & 31;
    return smaddr(b + (nb + (l & 7) + ((l & 16) >> 1)) * ld + kb + (l & 8));
}
__device__ __forceinline__ uint adrBT(const bf* b, int ld, int kb, int nb) {
    int l = threadIdx.x & 31;
    return smaddr(b + (kb + (l & 7) + (l & 8)) * ld + nb + ((l & 16) >> 1));
}
__device__ __forceinline__ uint adrRing(const bf* b, int t0, int kb) {
    int l = threadIdx.x & 31;
    int slot = (t0 + (l & 7) + ((l & 16) >> 1)) & 255;
    return smaddr(b + slot * 72 + kb + (l & 8));
}
__device__ __forceinline__ void mmabf(float4& c, uint4 a, uint b0, uint b1) {
    asm volatile(
        "mma.sync.aligned.m16n8k16.row.col.f32.bf16.bf16.f32 "
        "{%0,%1,%2,%3},{%4,%5,%6,%7},{%8,%9},{%0,%1,%2,%3};"
        : "+f"(c.x), "+f"(c.y), "+f"(c.z), "+f"(c.w)
        : "r"(a.x), "r"(a.y), "r"(a.z), "r"(a.w), "r"(b0), "r"(b1));
}
__device__ __forceinline__ uint bfpair(float lo, float hi) {
    uint r; asm("cvt.rn.bf16x2.f32 %0,%1,%2;" : "=r"(r) : "f"(hi), "f"(lo));
    return r;
}
__device__ __forceinline__ uint addb2(uint a, uint b) {
    uint r; asm("add.rn.bf16x2 %0,%1,%2;" : "=r"(r) : "r"(a), "r"(b));
    return r;
}
__device__ __forceinline__ uint2 pack4(float4 v) {
    uint2 r; r.x = bfpair(v.x, v.y); r.y = bfpair(v.z, v.w); return r;
}

// ---------- setup (unchanged) ----------
__global__ __launch_bounds__(256)
void setup(const unsigned char* __restrict__ ttm,
           const float* __restrict__ clsm,
           const float* __restrict__ amask,
           const float* q, const float* k, const float* v, const float* pose,
           const float* Wq, const float* Wk, const float* Wv,
           const float* rk, const float* Wo) {
    int tid = threadIdx.x;
    if (blockIdx.x < Bc*Sc) {
        int r = blockIdx.x;
        int w = tid >> 5, lane = tid & 31;
        #pragma unroll
        for (int c = 0; c < 4; c++) {
            int j = w * 128 + c * 32 + lane;
            uint m = __ballot_sync(~0u, ttm[(size_t)r * Sc + j] != 0);
            if (lane == 0) g_ttb[r * 32 + w * 4 + c] = m;
        }
        if (r < Sc) {
            int j4 = tid * 4;
            float4 c4 = *(const float4*)(clsm + (size_t)r * Sc + j4);
            *(uint2*)(g_cls + (size_t)r * Sc + j4) = pack4(c4);
        }
        if (r < 16) {
            int idx = r * 256 + tid;
            g_mk[idx] = INFV * (1.f - amask[idx]);
        }
    } else {
        const int NQ4 = Bc*Sc*Dc/4, NP4 = Rc*Dc/4, NW4 = Dc*Dc/4;
        int total = 3*NQ4 + NP4 + 5*NW4;
        int nb = gridDim.x - Bc*Sc;
        for (int i = (blockIdx.x - Bc*Sc) * 256 + tid; i < total; i += nb * 256) {
            const float* s; bf* d; int o = i;
            if (o < NQ4)               { s = q;    d = c_q;  }
            else if ((o -= NQ4) < NQ4) { s = k;    d = c_k;  }
            else if ((o -= NQ4) < NQ4) { s = v;    d = c_v;  }
            else if ((o -= NQ4) < NP4) { s = pose; d = c_p;  }
            else if ((o -= NP4) < NW4) { s = Wq;   d = c_wq; }
            else if ((o -= NW4) < NW4) { s = Wk;   d = c_wk; }
            else if ((o -= NW4) < NW4) { s = Wv;   d = c_wv; }
            else if ((o -= NW4) < NW4) { s = rk;   d = c_wr; }
            else { o -= NW4;             s = Wo;   d = c_wo; }
            float4 vv = *((const float4*)s + o);
            *(uint2*)(d + (size_t)o * 4) = pack4(vv);
        }
    }
}

// ---------- pipelined bf16 GEMMs (unchanged from R13) ----------
#define GST 17920
#define GOB 9216
#define GSM_BYTES (3*GST*2)

extern __shared__ bf gsm[];

__device__ __forceinline__ void gstage3(const bf* __restrict__ A,
                                        const bf* __restrict__ W,
                                        int m0, int n0, int ks, int s) {
    int tid = threadIdx.x;
    bf* As = gsm + s * GST;
    bf* Bs = gsm + s * GST + GOB;
    #pragma unroll
    for (int p = 0; p < 4; p++) {
        int cid = tid + p * 256;
        int row = cid >> 3, cc = cid & 7;
        cpa16(smaddr(As + row * 72 + cc * 8),
              A + (size_t)(m0 + row) * Dc + ks * 64 + cc * 8);
    }
    #pragma unroll
    for (int p = 0; p < 4; p++) {
        int cid = tid + p * 256;
        int kk = cid >> 4, cc = cid & 15;
        cpa16(smaddr(Bs + kk * 136 + cc * 8),
              W + (size_t)(ks * 64 + kk) * Dc + n0 + cc * 8);
    }
    cpcommit();
}

__device__ __forceinline__ void gcompute(float4 (&c)[4][4], int wm, int wn, int s) {
    bf* As = gsm + s * GST;
    bf* Bs = gsm + s * GST + GOB;
    #pragma unroll
    for (int ks16 = 0; ks16 < 4; ks16++) {
        int kb = ks16 * 16;
        uint4 a0 = ldsm4(adrA(As, 72, wm * 64, kb));
        uint4 a1 = ldsm4(adrA(As, 72, wm * 64 + 16, kb));
        uint4 a2 = ldsm4(adrA(As, 72, wm * 64 + 32, kb));
        uint4 a3 = ldsm4(adrA(As, 72, wm * 64 + 48, kb));
        uint4 b0 = ldsm4t(adrBT(Bs, 136, kb, wn * 32));
        uint4 b1 = ldsm4t(adrBT(Bs, 136, kb, wn * 32 + 16));
        mmabf(c[0][0], a0, b0.x, b0.y); mmabf(c[0][1], a0, b0.z, b0.w);
        mmabf(c[0][2], a0, b1.x, b1.y); mmabf(c[0][3], a0, b1.z, b1.w);
        mmabf(c[1][0], a1, b0.x, b0.y); mmabf(c[1][1], a1, b0.z, b0.w);
        mmabf(c[1][2], a1, b1.x, b1.y); mmabf(c[1][3], a1, b1.z, b1.w);
        mmabf(c[2][0], a2, b0.x, b0.y); mmabf(c[2][1], a2, b0.z, b0.w);
        mmabf(c[2][2], a2, b1.x, b1.y); mmabf(c[2][3], a2, b1.z, b1.w);
        mmabf(c[3][0], a3, b0.x, b0.y); mmabf(c[3][1], a3, b0.z, b0.w);
        mmabf(c[3][2], a3, b1.x, b1.y); mmabf(c[3][3], a3, b1.z, b1.w);
    }
}

__device__ __forceinline__ void gemm_core_b(
    const bf* __restrict__ A, const bf* __restrict__ W,
    const float* __restrict__ bias, float scale, int sshift, bf* __restrict__ out) {
    int tid = threadIdx.x, l = tid & 31, g = l >> 2, t = l & 3, w = tid >> 5;
    int wm = w & 1, wn = w >> 1;
    int m0 = blockIdx.y * 128, n0 = blockIdx.x * 128;
    int Srows = 1 << sshift;

    float4 c[4][4];
    #pragma unroll
    for (int i = 0; i < 4; i++)
        #pragma unroll
        for (int j = 0; j < 4; j++) c[i][j] = make_float4(0.f, 0.f, 0.f, 0.f);

    gstage3(A, W, m0, n0, 0, 0);
    gstage3(A, W, m0, n0, 1, 1);
    int s = 0;
    for (int ks = 0; ks < 12; ks++) {
        if (ks == 11) cpwait0(); else cpwait1();
        __syncthreads();
        if (ks < 10) {
            int sn = s + 2; if (sn >= 3) sn -= 3;
            gstage3(A, W, m0, n0, ks + 2, sn);
        }
        gcompute(c, wm, wn, s);
        if (++s == 3) s = 0;
    }
    #pragma unroll
    for (int mi = 0; mi < 4; mi++) {
        #pragma unroll
        for (int nt = 0; nt < 4; nt++) {
            int col = n0 + wn * 32 + nt * 8 + 2 * t;
            float b0f = bias ? __ldg(bias + col) : 0.f;
            float b1f = bias ? __ldg(bias + col + 1) : 0.f;
            int nn = col >> 6, hh = col & 63;
            #pragma unroll
            for (int r = 0; r < 2; r++) {
                int row = m0 + wm * 64 + mi * 16 + g + r * 8;
                int bb = row >> sshift, ss = row & (Srows - 1);
                float v0 = (r ? c[mi][nt].z : c[mi][nt].x) * scale + b0f;
                float v1 = (r ? c[mi][nt].w : c[mi][nt].y) * scale + b1f;
                *(uint*)(out + (((size_t)bb * Nc + nn) * Srows + ss) * Hc + hh) =
                    bfpair(v0, v1);
            }
        }
    }
}

__global__ __launch_bounds__(256)
void gemm_in(const float* bk, const float* bv) {
    int z = blockIdx.z;
    if (z == 0)      gemm_core_b(c_q, c_wq, nullptr, SCALE, 10, g_qh);
    else if (z == 1) gemm_core_b(c_k, c_wk, bk, 1.f, 10, g_kh);
    else if (z == 2) gemm_core_b(c_v, c_wv, bv, 1.f, 10, g_vh);
    else if (blockIdx.y < 16) gemm_core_b(c_p, c_wr, nullptr, 1.f, 11, g_rh);
}

__global__ __launch_bounds__(256)
void gemm_out_b(const float* __restrict__ bo, const float* __restrict__ query) {
    int tid = threadIdx.x, l = tid & 31, g = l >> 2, t = l & 3, w = tid >> 5;
    int wm = w & 1, wn = w >> 1;
    int m0 = blockIdx.y * 128, n0 = blockIdx.x * 128;

    float4 c[4][4];
    #pragma unroll
    for (int i = 0; i < 4; i++)
        #pragma unroll
        for (int j = 0; j < 4; j++) c[i][j] = make_float4(0.f, 0.f, 0.f, 0.f);

    auto stage = [&](int ks, int s) {
        bf* As = gsm + s * GST;
        bf* Bs = gsm + s * GST + GOB;
        #pragma unroll
        for (int p = 0; p < 4; p++) {
            int cid = tid + p * 256;
            int row = cid >> 3, cc = cid & 7;
            int rg = m0 + row;
            cpa16(smaddr(As + row * 72 + cc * 8),
                  g_av + (((size_t)(rg >> 10) * Nc + ks) * Sc + (rg & 1023)) * Hc + cc * 8);
        }
        #pragma unroll
        for (int p = 0; p < 4; p++) {
            int cid = tid + p * 256;
            int kk = cid >> 4, cc = cid & 15;
            cpa16(smaddr(Bs + kk * 136 + cc * 8),
                  c_wo + (size_t)(ks * 64 + kk) * Dc + n0 + cc * 8);
        }
        cpcommit();
    };

    stage(0, 0);
    stage(1, 1);
    int s = 0;
    for (int ks = 0; ks < 12; ks++) {
        if (ks == 11) cpwait0(); else cpwait1();
        __syncthreads();
        if (ks < 10) {
            int sn = s + 2; if (sn >= 3) sn -= 3;
            stage(ks + 2, sn);
        }
        gcompute(c, wm, wn, s);
        if (++s == 3) s = 0;
    }
    #pragma unroll
    for (int mi = 0; mi < 4; mi++) {
        #pragma unroll
        for (int nt = 0; nt < 4; nt++) {
            int col = n0 + wn * 32 + nt * 8 + 2 * t;
            float b0f = __ldg(bo + col), b1f = __ldg(bo + col + 1);
            #pragma unroll
            for (int r = 0; r < 2; r++) {
                int row = m0 + wm * 64 + mi * 16 + g + r * 8;
                float2 q = *(const float2*)(query + (size_t)row * Dc + col);
                float v0 = (r ? c[mi][nt].z : c[mi][nt].x) + b0f + q.x;
                float v1 = (r ? c[mi][nt].w : c[mi][nt].y) + b1f + q.y;
                *(float2*)(g_x + (size_t)row * Dc + col) = make_float2(v0, v1);
            }
        }
    }
}

// ---------- fused attention v2: warp-owns-rows, i-tile 128, rs ring ----------
// (cls stride 72 bf = 144B, 16B-aligned for cp.async — R14 bug fixed)
#define RINGB 0                  // 256*72 = 18432 bf
#define K0B   18432              // 64*72
#define K1B   23040
#define VB    27648              // 64*72
#define CLSB  32256              // 128*72 = 9216 bf
#define OQT   32256              // transient Q overlay (prologue only; 128*72)
#define PWBB  41472              // 8*16*80 = 10240 bf
#define RWBB  51712
#define RRBB  51776
#define FOFFN 51840
#define SMEM_ATTN2 (51840*2 + 256*4 + 64*4 + 256*4)   // 105984 B

extern __shared__ bf smb[];
__global__ __launch_bounds__(256, 2)
void attn_kernel(const float* __restrict__ rwb, const float* __restrict__ rrb,
                 const float* __restrict__ rsb, const float* __restrict__ seg) {
    bf* ring = smb + RINGB;
    bf* sv   = smb + VB;
    bf* scls = smb + CLSB;
    bf* rwbs = smb + RWBB;
    bf* rrbs = smb + RRBB;
    uint*  sttb = (uint*)(smb + FOFFN);   // 256
    float* samk = (float*)(sttb + 256);   // 64
    float* sttd = samk + 64;              // 256

    int tid = threadIdx.x, l = tid & 31, g = l >> 2, t = l & 3, w = tid >> 5;
    int wrow = w * 16;
    int i0 = blockIdx.x * 128, n = blockIdx.y, b = blockIdx.z;

    const bf* qbase = g_qh + (((size_t)b*Nc + n)*Sc + i0) * Hc;
    const bf* kbase = g_kh + (((size_t)b*Nc + n)*Sc) * Hc;
    const bf* vbase = g_vh + (((size_t)b*Nc + n)*Sc) * Hc;
    const bf* rbase = g_rh + (size_t)n * Rc * Hc;
    int tb0 = Sc - i0 - 127;              // >= 1 always

    // prologue: Q -> overlay (group 0)
    #pragma unroll
    for (int p = 0; p < 4; p++) {
        int cid = tid + p * 256;
        int row = cid >> 3, cc = cid & 7;
        cpa16(smaddr(smb + OQT + row * 72 + cc * 8),
              qbase + (size_t)row * Hc + cc * 8);
    }
    cpcommit();
    // K0 + ring init (192 rows) (group A0)
    #pragma unroll
    for (int p = 0; p < 2; p++) {
        int cid = tid + p * 256;
        int row = cid >> 3, cc = cid & 7;
        cpa16(smaddr(smb + K0B + row * 72 + cc * 8),
              kbase + (size_t)row * Hc + cc * 8);
    }
    #pragma unroll
    for (int p = 0; p < 6; p++) {
        int cid = tid + p * 256;
        int row = cid >> 3, cc = cid & 7;
        int tt2 = tb0 + row;
        cpa16(smaddr(ring + (tt2 & 255) * 72 + cc * 8),
              rbase + (size_t)tt2 * Hc + cc * 8);
    }
    cpcommit();
    if (tid < 64) {
        rwbs[tid] = __float2bfloat16(rwb[n * Hc + tid] * SCALE);
        rrbs[tid] = __float2bfloat16(rrb[n * Hc + tid] * SCALE);
    }
    cpwait1();           // Q resident
    __syncthreads();

    uint4 qa[4];
    #pragma unroll
    for (int ks = 0; ks < 4; ks++)
        qa[ks] = ldsm4(adrA(smb + OQT, 72, wrow, ks * 16));
    {   // tt scalars from staged Q
        int u = tid >> 1, sel = tid & 1;
        const float* segp = seg + (sel * Nc + n) * Hc;
        const float* rsbp = rsb + n * Hc;
        float acc = 0.f;
        #pragma unroll
        for (int h = 0; h < 64; h++) {
            float qv = __bfloat162float(smb[OQT + u * 72 + h]) + rsbp[h] * SCALE;
            acc += qv * segp[h];
        }
        sttd[tid] = acc;
    }
    __syncthreads();     // Q/tt read done; overlay free

    float4 of[8];
    #pragma unroll
    for (int nt = 0; nt < 8; nt++) of[nt] = make_float4(0.f, 0.f, 0.f, 0.f);
    float m0r = -3.0e38f, m1r = -3.0e38f, l0r = 0.f, l1r = 0.f;
    int u0 = wrow + g, u1 = u0 + 8;
    int vminw = 112 - wrow;
    bf* pw = smb + PWBB + w * (16 * 80);

    for (int t16 = 0; t16 < 16; t16++) {
        int j0 = t16 * 64;
        int pp = t16 & 1;
        bf* skp = smb + (pp ? K1B : K0B);
        int tb = tb0 + j0;

        __syncthreads();   // (1) prev PV done; V/cls free
        #pragma unroll
        for (int p = 0; p < 2; p++) {
            int cid = tid + p * 256;
            int row = cid >> 3, cc = cid & 7;
            cpa16(smaddr(sv + row * 72 + cc * 8),
                  vbase + (size_t)(j0 + row) * Hc + cc * 8);
        }
        #pragma unroll
        for (int p = 0; p < 4; p++) {
            int cid = tid + p * 256;
            int row = cid >> 3, cc = cid & 7;
            cpa16(smaddr(scls + row * 72 + cc * 8),
                  g_cls + (size_t)(i0 + row) * Sc + j0 + cc * 8);
        }
        if (tid < 128)
            cpa8(smaddr(sttb + tid * 2),
                 g_ttb + ((size_t)(b * Sc + i0 + tid) * 32 + (j0 >> 5)));
        if (tid < 16)
            cpa16(smaddr(samk + tid * 4), g_mk + b * Sc + j0 + tid * 4);
        cpcommit();

        cpwait1();         // A_t resident
        __syncthreads();   // (2)

        // prefetch A_{t+1}: K + 64 new ring rows
        {
            int j0n = j0 + 64;
            if (j0n < Sc) {
                bf* dK = smb + (pp ? K0B : K1B);
                #pragma unroll
                for (int p = 0; p < 2; p++) {
                    int cid = tid + p * 256;
                    int row = cid >> 3, cc = cid & 7;
                    cpa16(smaddr(dK + row * 72 + cc * 8),
                          kbase + (size_t)(j0n + row) * Hc + cc * 8);
                }
                #pragma unroll
                for (int p = 0; p < 2; p++) {
                    int cid = tid + p * 256;
                    int row = cid >> 3, cc = cid & 7;
                    int tt2 = tb + 192 + row;
                    int sz = (tt2 < Rc) ? 16 : 0;
                    cpa16z(smaddr(ring + (tt2 & 255) * 72 + cc * 8),
                           rbase + (size_t)(tt2 & 2047) * Hc + cc * 8, sz);
                }
            }
            cpcommit();
        }

        // pos mma (band window 80 wide), stash to pw
        float4 pf[10];
        #pragma unroll
        for (int q_ = 0; q_ < 10; q_++) pf[q_] = make_float4(0.f, 0.f, 0.f, 0.f);
        int ta0 = tb + vminw;
        #pragma unroll
        for (int ks = 0; ks < 4; ks++) {
            int kb = ks * 16;
            uint rr0 = *(const uint*)(rrbs + kb + 2 * t);
            uint rr1 = *(const uint*)(rrbs + kb + 2 * t + 8);
            uint4 ar;
            ar.x = addb2(qa[ks].x, rr0); ar.y = addb2(qa[ks].y, rr0);
            ar.z = addb2(qa[ks].z, rr1); ar.w = addb2(qa[ks].w, rr1);
            #pragma unroll
            for (int m = 0; m < 5; m++) {
                uint4 br = ldsm4(adrRing(ring, ta0 + m * 16, kb));
                mmabf(pf[2*m], ar, br.x, br.y);
                mmabf(pf[2*m+1], ar, br.z, br.w);
            }
        }
        #pragma unroll
        for (int m = 0; m < 10; m++) {
            *(uint*)(pw + g * 80 + m * 8 + 2 * t)       = bfpair(pf[m].x, pf[m].y);
            *(uint*)(pw + (g + 8) * 80 + m * 8 + 2 * t) = bfpair(pf[m].z, pf[m].w);
        }
        __syncwarp();

        // content mma
        float4 sc[8];
        #pragma unroll
        for (int q_ = 0; q_ < 8; q_++) sc[q_] = make_float4(0.f, 0.f, 0.f, 0.f);
        #pragma unroll
        for (int ks = 0; ks < 4; ks++) {
            int kb = ks * 16;
            uint rw0 = *(const uint*)(rwbs + kb + 2 * t);
            uint rw1 = *(const uint*)(rwbs + kb + 2 * t + 8);
            uint4 aw;
            aw.x = addb2(qa[ks].x, rw0); aw.y = addb2(qa[ks].y, rw0);
            aw.z = addb2(qa[ks].z, rw1); aw.w = addb2(qa[ks].w, rw1);
            #pragma unroll
            for (int m = 0; m < 4; m++) {
                uint4 bk = ldsm4(adrB(skp, 72, m * 16, kb));
                mmabf(sc[2*m], aw, bk.x, bk.y);
                mmabf(sc[2*m+1], aw, bk.z, bk.w);
            }
        }

        cpwait1();         // B_t resident
        __syncthreads();   // (3)

        // combine + warp-local softmax
        float td0 = sttd[2*u0], ts0 = sttd[2*u0+1];
        float td1 = sttd[2*u1], ts1 = sttd[2*u1+1];
        uint tA0 = sttb[u0*2], tA1 = sttb[u0*2+1];
        uint tB0 = sttb[u1*2], tB1 = sttb[u1*2+1];
        float mr0 = -3.0e38f, mr1 = -3.0e38f;
        #pragma unroll
        for (int nt = 0; nt < 8; nt++) {
            int jl = nt * 8 + 2 * t, sh = jl & 31;
            uint w0 = (nt < 4) ? tA0 : tA1;
            uint w1 = (nt < 4) ? tB0 : tB1;
            float mk0 = samk[jl], mk1 = samk[jl + 1];
            uint cu0 = *(const uint*)(scls + u0 * 72 + jl);
            uint cu1 = *(const uint*)(scls + u1 * 72 + jl);
            float2 cl0 = __bfloat1622float2(*(__nv_bfloat162*)&cu0);
            float2 cl1 = __bfloat1622float2(*(__nv_bfloat162*)&cu1);
            float p00 = __bfloat162float(pw[g * 80 + jl - g + 15]);
            float p01 = __bfloat162float(pw[g * 80 + jl - g + 16]);
            float p10 = __bfloat162float(pw[(g + 8) * 80 + jl - g + 7]);
            float p11 = __bfloat162float(pw[(g + 8) * 80 + jl - g + 8]);
            float tv00 = ((w0 >> sh) & 1)       ? ts0 : td0;
            float tv01 = ((w0 >> (sh + 1)) & 1) ? ts0 : td0;
            float tv10 = ((w1 >> sh) & 1)       ? ts1 : td1;
            float tv11 = ((w1 >> (sh + 1)) & 1) ? ts1 : td1;
            sc[nt].x += cl0.x * (p00 + tv00) - mk0;
            sc[nt].y += cl0.y * (p01 + tv01) - mk1;
            sc[nt].z += cl1.x * (p10 + tv10) - mk0;
            sc[nt].w += cl1.y * (p11 + tv11) - mk1;
            mr0 = fmaxf(mr0, fmaxf(sc[nt].x, sc[nt].y));
            mr1 = fmaxf(mr1, fmaxf(sc[nt].z, sc[nt].w));
        }
        mr0 = fmaxf(mr0, __shfl_xor_sync(~0u, mr0, 1));
        mr0 = fmaxf(mr0, __shfl_xor_sync(~0u, mr0, 2));
        mr1 = fmaxf(mr1, __shfl_xor_sync(~0u, mr1, 1));
        mr1 = fmaxf(mr1, __shfl_xor_sync(~0u, mr1, 2));
        float mn0 = fmaxf(m0r, mr0), mn1 = fmaxf(m1r, mr1);
        float co0 = __expf(m0r - mn0), co1 = __expf(m1r - mn1);
        float ls0 = 0.f, ls1 = 0.f;
        #pragma unroll
        for (int nt = 0; nt < 8; nt++) {
            sc[nt].x = __expf(sc[nt].x - mn0); sc[nt].y = __expf(sc[nt].y - mn0);
            sc[nt].z = __expf(sc[nt].z - mn1); sc[nt].w = __expf(sc[nt].w - mn1);
            ls0 += sc[nt].x + sc[nt].y; ls1 += sc[nt].z + sc[nt].w;
        }
        ls0 += __shfl_xor_sync(~0u, ls0, 1); ls0 += __shfl_xor_sync(~0u, ls0, 2);
        ls1 += __shfl_xor_sync(~0u, ls1, 1); ls1 += __shfl_xor_sync(~0u, ls1, 2);
        l0r = l0r * co0 + ls0; l1r = l1r * co1 + ls1;
        m0r = mn0; m1r = mn1;
        #pragma unroll
        for (int nt = 0; nt < 8; nt++) {
            of[nt].x *= co0; of[nt].y *= co0;
            of[nt].z *= co1; of[nt].w *= co1;
        }

        // PV: P from registers (C-frag -> A-frag), V from smem
        #pragma unroll
        for (int ks = 0; ks < 4; ks++) {
            int kb = ks * 16;
            uint4 pA;
            pA.x = bfpair(sc[2*ks].x, sc[2*ks].y);
            pA.y = bfpair(sc[2*ks].z, sc[2*ks].w);
            pA.z = bfpair(sc[2*ks+1].x, sc[2*ks+1].y);
            pA.w = bfpair(sc[2*ks+1].z, sc[2*ks+1].w);
            #pragma unroll
            for (int m = 0; m < 4; m++) {
                uint4 v_ = ldsm4t(adrBT(sv, 72, kb, m * 16));
                mmabf(of[2*m], pA, v_.x, v_.y);
                mmabf(of[2*m+1], pA, v_.z, v_.w);
            }
        }
    }

    float inv0 = 1.f / l0r, inv1 = 1.f / l1r;
    bf* outb = g_av + (((size_t)b*Nc + n)*Sc + i0) * Hc;
    #pragma unroll
    for (int nt = 0; nt < 8; nt++) {
        int h = nt * 8 + 2 * t;
        *(uint*)(outb + (size_t)u0 * Hc + h) = bfpair(of[nt].x * inv0, of[nt].y * inv0);
        *(uint*)(outb + (size_t)u1 * Hc + h) = bfpair(of[nt].z * inv1, of[nt].w * inv1);
    }
}

// ---------- LayerNorm (unchanged) ----------
__global__ __launch_bounds__(256)
void ln_kernel(const float* __restrict__ lng, const float* __restrict__ lnb,
               float* __restrict__ out) {
    __shared__ float red[8];
    __shared__ float stat;
    int row = blockIdx.x;
    const float* x = &g_x[(size_t)row * Dc];
    int t = threadIdx.x;
    float v[3];
    float s = 0.f;
    #pragma unroll
    for (int p = 0; p < 3; p++) { v[p] = x[t + p*256]; s += v[p]; }
    #pragma unroll
    for (int off = 16; off; off >>= 1) s += __shfl_xor_sync(~0u, s, off);
    if ((t & 31) == 0) red[t >> 5] = s;
    __syncthreads();
    if (t < 32) {
        float r = (t < 8) ? red[t] : 0.f;
        #pragma unroll
        for (int off = 4; off; off >>= 1) r += __shfl_xor_sync(~0u, r, off);
        if (t == 0) stat = r * (1.f / Dc);
    }
    __syncthreads();
    float mu = stat;
    float s2 = 0.f;
    #pragma unroll
    for (int p = 0; p < 3; p++) { float d = v[p] - mu; s2 += d*d; }
    #pragma unroll
    for (int off = 16; off; off >>= 1) s2 += __shfl_xor_sync(~0u, s2, off);
    if ((t & 31) == 0) red[t >> 5] = s2;
    __syncthreads();
    if (t < 32) {
        float r = (t < 8) ? red[t] : 0.f;
        #pragma unroll
        for (int off = 4; off; off >>= 1) r += __shfl_xor_sync(~0u, r, off);
        if (t == 0) stat = rsqrtf(r * (1.f / Dc) + EPSV);
    }
    __syncthreads();
    float rstd = stat;
    #pragma unroll
    for (int p = 0; p < 3; p++) {
        int i = t + p*256;
        out[(size_t)row*Dc + i] = (v[p] - mu) * rstd * lng[i] + lnb[i];
    }
}

// ---------- launch ----------
extern "C" void kernel_launch(void* const* d_in, const int* in_sizes, int n_in,
                              void* d_out, int out_size) {
    const float* query = (const float*)d_in[0];
    const float* key   = (const float*)d_in[1];
    const float* value = (const float*)d_in[2];
    const float* pose  = (const float*)d_in[3];
    const unsigned char* ttm = (const unsigned char*)d_in[4];
    const float* amask = (const float*)d_in[5];
    const float* clsm  = (const float*)d_in[6];
    const float* Wq    = (const float*)d_in[7];
    const float* Wk    = (const float*)d_in[8];
    const float* bk    = (const float*)d_in[9];
    const float* Wv    = (const float*)d_in[10];
    const float* bv    = (const float*)d_in[11];
    const float* rwb   = (const float*)d_in[12];
    const float* rrb   = (const float*)d_in[13];
    const float* rker  = (const float*)d_in[14];
    const float* rsb   = (const float*)d_in[15];
    const float* seg   = (const float*)d_in[16];
    const float* Wo    = (const float*)d_in[17];
    const float* bo    = (const float*)d_in[18];
    const float* lng   = (const float*)d_in[19];
    const float* lnb   = (const float*)d_in[20];
    float* out = (float*)d_out;

    dim3 blk(256);
    setup<<<Bc*Sc + 4096, blk>>>(ttm, clsm, amask,
                                 query, key, value, pose, Wq, Wk, Wv, rker, Wo);

    cudaFuncSetAttribute(gemm_in, cudaFuncAttributeMaxDynamicSharedMemorySize,
                         GSM_BYTES);
    gemm_in<<<dim3(6, 32, 4), blk, GSM_BYTES>>>(bk, bv);

    cudaFuncSetAttribute(attn_kernel, cudaFuncAttributeMaxDynamicSharedMemorySize,
                         SMEM_ATTN2);
    attn_kernel<<<dim3(Sc/128, Nc, Bc), blk, SMEM_ATTN2>>>(rwb, rrb, rsb, seg);

    cudaFuncSetAttribute(gemm_out_b, cudaFuncAttributeMaxDynamicSharedMemorySize,
                         GSM_BYTES);
    gemm_out_b<<<dim3(6, 32), blk, GSM_BYTES>>>(bo, query);

    ln_kernel<<<Bc*Sc, blk>>>(lng, lnb, out);
}